// round 1
// baseline (speedup 1.0000x reference)
#include <cuda_runtime.h>
#include <cstdint>

// Problem constants
#define BATCH 64
#define CDIM  512
#define NTOK  1024   // H*W = 32*32
#define QKV_ROWS 1536

// Scratch (device globals; no allocation allowed in kernel_launch)
__device__ float g_qkv[(size_t)BATCH * QKV_ROWS * NTOK];  // [b][3c][n]  (402 MB)
__device__ float g_att[(size_t)BATCH * NTOK * NTOK];      // [b][n][m]   (268 MB)
__device__ float g_pos[(size_t)CDIM * NTOK];              // [c][n]      (2 MB)

// ---------------------------------------------------------------------------
// pos[c,n] = rel_h[c,h] + rel_w[c,w],  n = h*32 + w
// ---------------------------------------------------------------------------
__global__ void pos_kernel(const float* __restrict__ rel_h,
                           const float* __restrict__ rel_w) {
    int idx = blockIdx.x * blockDim.x + threadIdx.x;
    if (idx >= CDIM * NTOK) return;
    int c = idx >> 10;
    int n = idx & 1023;
    int h = n >> 5;
    int w = n & 31;
    g_pos[idx] = rel_h[c * 32 + h] + rel_w[c * 32 + w];
}

// ---------------------------------------------------------------------------
// GEMM1: qkv[b] = W[1536,512] @ x[b][512,1024]
// A row-major [M,K] (K contiguous)  -> transposed smem store (pad 132)
// B row-major [K,N] (N contiguous)  -> natural smem store
// ---------------------------------------------------------------------------
__global__ __launch_bounds__(256) void gemm_qkv(const float* __restrict__ Wmat,
                                                const float* __restrict__ x) {
    int b = blockIdx.z;
    const float* A = Wmat;                                  // [1536,512]
    const float* B = x + (size_t)b * CDIM * NTOK;           // [512,1024]
    float* C = g_qkv + (size_t)b * QKV_ROWS * NTOK;

    __shared__ float As[16][132];
    __shared__ float Bs[16][128];

    int tid = threadIdx.x;
    int tx = tid & 15, ty = tid >> 4;
    int mBase = blockIdx.y * 128, nBase = blockIdx.x * 128;

    float acc[8][8];
#pragma unroll
    for (int i = 0; i < 8; i++)
#pragma unroll
        for (int j = 0; j < 8; j++) acc[i][j] = 0.f;

    for (int kt = 0; kt < CDIM; kt += 16) {
        // A tile: 128 rows x 16 k (row stride 512), store transposed
#pragma unroll
        for (int it = 0; it < 2; it++) {
            int idx = tid + it * 256;           // 0..511
            int row = idx >> 2;                 // 0..127
            int c4  = (idx & 3) * 4;            // 0,4,8,12
            float4 v = *(const float4*)&A[(size_t)(mBase + row) * CDIM + kt + c4];
            As[c4 + 0][row] = v.x; As[c4 + 1][row] = v.y;
            As[c4 + 2][row] = v.z; As[c4 + 3][row] = v.w;
        }
        // B tile: 16 k-rows x 128 n (contiguous), natural
#pragma unroll
        for (int it = 0; it < 2; it++) {
            int idx = tid + it * 256;
            int kr = idx >> 5;                  // 0..15
            int n4 = (idx & 31) * 4;
            *(float4*)&Bs[kr][n4] =
                *(const float4*)&B[(size_t)(kt + kr) * NTOK + nBase + n4];
        }
        __syncthreads();
#pragma unroll
        for (int k = 0; k < 16; k++) {
            float a[8], bb[8];
            *(float4*)&a[0]  = *(const float4*)&As[k][ty * 8];
            *(float4*)&a[4]  = *(const float4*)&As[k][ty * 8 + 4];
            *(float4*)&bb[0] = *(const float4*)&Bs[k][tx * 8];
            *(float4*)&bb[4] = *(const float4*)&Bs[k][tx * 8 + 4];
#pragma unroll
            for (int i = 0; i < 8; i++)
#pragma unroll
                for (int j = 0; j < 8; j++) acc[i][j] += a[i] * bb[j];
        }
        __syncthreads();
    }
#pragma unroll
    for (int i = 0; i < 8; i++) {
        size_t row = (size_t)(mBase + ty * 8 + i) * NTOK + nBase + tx * 8;
        *(float4*)&C[row]     = *(float4*)&acc[i][0];
        *(float4*)&C[row + 4] = *(float4*)&acc[i][4];
    }
}

// ---------------------------------------------------------------------------
// GEMM2: logits[b][n,m] = sum_{k<512} q[k,n]*kk[k,m] + sum pos[j,n]*q[j,m]
// Stacked operands: Abar[k,n] = (k<512 ? q : pos), Bbar[k,m] = (k<512 ? kk : q)
// Both K-major (contiguous along n/m) -> natural smem stores
// ---------------------------------------------------------------------------
__global__ __launch_bounds__(256) void gemm_logits() {
    int b = blockIdx.z;
    const float* qkv_b = g_qkv + (size_t)b * QKV_ROWS * NTOK;  // q at 0, k at 512 rows
    float* C = g_att + (size_t)b * NTOK * NTOK;

    __shared__ float As[16][128];
    __shared__ float Bs[16][128];

    int tid = threadIdx.x;
    int tx = tid & 15, ty = tid >> 4;
    int nBase = blockIdx.y * 128, mBase = blockIdx.x * 128;

    float acc[8][8];
#pragma unroll
    for (int i = 0; i < 8; i++)
#pragma unroll
        for (int j = 0; j < 8; j++) acc[i][j] = 0.f;

    for (int kt = 0; kt < 1024; kt += 16) {
#pragma unroll
        for (int it = 0; it < 2; it++) {
            int idx = tid + it * 256;
            int kr = idx >> 5;                 // 0..15
            int c4 = (idx & 31) * 4;
            int k = kt + kr;
            const float* aRow = (k < 512) ? (qkv_b + (size_t)k * NTOK)
                                          : (g_pos + (size_t)(k - 512) * NTOK);
            const float* bRow = (k < 512) ? (qkv_b + (size_t)(512 + k) * NTOK)
                                          : (qkv_b + (size_t)(k - 512) * NTOK);
            *(float4*)&As[kr][c4] = *(const float4*)&aRow[nBase + c4];
            *(float4*)&Bs[kr][c4] = *(const float4*)&bRow[mBase + c4];
        }
        __syncthreads();
#pragma unroll
        for (int k = 0; k < 16; k++) {
            float a[8], bb[8];
            *(float4*)&a[0]  = *(const float4*)&As[k][ty * 8];
            *(float4*)&a[4]  = *(const float4*)&As[k][ty * 8 + 4];
            *(float4*)&bb[0] = *(const float4*)&Bs[k][tx * 8];
            *(float4*)&bb[4] = *(const float4*)&Bs[k][tx * 8 + 4];
#pragma unroll
            for (int i = 0; i < 8; i++)
#pragma unroll
                for (int j = 0; j < 8; j++) acc[i][j] += a[i] * bb[j];
        }
        __syncthreads();
    }
#pragma unroll
    for (int i = 0; i < 8; i++) {
        size_t row = (size_t)(nBase + ty * 8 + i) * NTOK + mBase + tx * 8;
        *(float4*)&C[row]     = *(float4*)&acc[i][0];
        *(float4*)&C[row + 4] = *(float4*)&acc[i][4];
    }
}

// ---------------------------------------------------------------------------
// Row softmax over m, in place on g_att. One block (256 thr) per (b,n) row.
// ---------------------------------------------------------------------------
__global__ __launch_bounds__(256) void softmax_kernel() {
    size_t row = blockIdx.x;                 // 0 .. 65535
    float* p = g_att + row * NTOK;
    int tid = threadIdx.x;

    float4 v = *(const float4*)&p[tid * 4];
    float m = fmaxf(fmaxf(v.x, v.y), fmaxf(v.z, v.w));
#pragma unroll
    for (int o = 16; o; o >>= 1) m = fmaxf(m, __shfl_xor_sync(~0u, m, o));

    __shared__ float red[8];
    if ((tid & 31) == 0) red[tid >> 5] = m;
    __syncthreads();
    float bm = red[0];
#pragma unroll
    for (int i = 1; i < 8; i++) bm = fmaxf(bm, red[i]);
    __syncthreads();

    v.x = __expf(v.x - bm); v.y = __expf(v.y - bm);
    v.z = __expf(v.z - bm); v.w = __expf(v.w - bm);
    float s = v.x + v.y + v.z + v.w;
#pragma unroll
    for (int o = 16; o; o >>= 1) s += __shfl_xor_sync(~0u, s, o);
    if ((tid & 31) == 0) red[tid >> 5] = s;
    __syncthreads();
    float bs = 0.f;
#pragma unroll
    for (int i = 0; i < 8; i++) bs += red[i];

    float inv = 1.0f / bs;
    v.x *= inv; v.y *= inv; v.z *= inv; v.w *= inv;
    *(float4*)&p[tid * 4] = v;
}

// ---------------------------------------------------------------------------
// GEMM3: out[b][c,n] = sum_m v[b][c,m] * att[b][n,m]   (A @ B^T)
// A = v row-major [512,1024] (m contiguous) -> transposed store (pad 132)
// B = att row-major [n,m] (m contiguous)    -> transposed store (pad 132)
// ---------------------------------------------------------------------------
__global__ __launch_bounds__(256) void gemm_out(float* __restrict__ out) {
    int b = blockIdx.z;
    const float* A = g_qkv + (size_t)b * QKV_ROWS * NTOK + (size_t)2 * CDIM * NTOK; // v
    const float* B = g_att + (size_t)b * NTOK * NTOK;
    float* C = out + (size_t)b * CDIM * NTOK;

    __shared__ float As[16][132];
    __shared__ float Bs[16][132];

    int tid = threadIdx.x;
    int tx = tid & 15, ty = tid >> 4;
    int cBase = blockIdx.y * 128, nBase = blockIdx.x * 128;

    float acc[8][8];
#pragma unroll
    for (int i = 0; i < 8; i++)
#pragma unroll
        for (int j = 0; j < 8; j++) acc[i][j] = 0.f;

    for (int kt = 0; kt < NTOK; kt += 16) {
        // A tile: 128 c-rows x 16 m, transpose
#pragma unroll
        for (int it = 0; it < 2; it++) {
            int idx = tid + it * 256;
            int row = idx >> 2;
            int c4  = (idx & 3) * 4;
            float4 va = *(const float4*)&A[(size_t)(cBase + row) * NTOK + kt + c4];
            As[c4 + 0][row] = va.x; As[c4 + 1][row] = va.y;
            As[c4 + 2][row] = va.z; As[c4 + 3][row] = va.w;
        }
        // B tile: 128 n-rows x 16 m, transpose -> Bs[m][n]
#pragma unroll
        for (int it = 0; it < 2; it++) {
            int idx = tid + it * 256;
            int row = idx >> 2;
            int m4  = (idx & 3) * 4;
            float4 vb = *(const float4*)&B[(size_t)(nBase + row) * NTOK + kt + m4];
            Bs[m4 + 0][row] = vb.x; Bs[m4 + 1][row] = vb.y;
            Bs[m4 + 2][row] = vb.z; Bs[m4 + 3][row] = vb.w;
        }
        __syncthreads();
#pragma unroll
        for (int k = 0; k < 16; k++) {
            float a[8], bb[8];
            *(float4*)&a[0]  = *(const float4*)&As[k][ty * 8];
            *(float4*)&a[4]  = *(const float4*)&As[k][ty * 8 + 4];
            *(float4*)&bb[0] = *(const float4*)&Bs[k][tx * 8];
            *(float4*)&bb[4] = *(const float4*)&Bs[k][tx * 8 + 4];
#pragma unroll
            for (int i = 0; i < 8; i++)
#pragma unroll
                for (int j = 0; j < 8; j++) acc[i][j] += a[i] * bb[j];
        }
        __syncthreads();
    }
#pragma unroll
    for (int i = 0; i < 8; i++) {
        size_t row = (size_t)(cBase + ty * 8 + i) * NTOK + nBase + tx * 8;
        *(float4*)&C[row]     = *(float4*)&acc[i][0];
        *(float4*)&C[row + 4] = *(float4*)&acc[i][4];
    }
}

// ---------------------------------------------------------------------------
extern "C" void kernel_launch(void* const* d_in, const int* in_sizes, int n_in,
                              void* d_out, int out_size) {
    const float* x     = (const float*)d_in[0];  // [64,512,32,32]
    const float* Wmat  = (const float*)d_in[1];  // [1536,512]
    const float* rel_h = (const float*)d_in[2];  // [1,512,32,1]
    const float* rel_w = (const float*)d_in[3];  // [1,512,1,32]
    float* out = (float*)d_out;                  // [64,512,32,32]

    // pos bias
    pos_kernel<<<(CDIM * NTOK + 255) / 256, 256>>>(rel_h, rel_w);

    // qkv = W @ x  (per batch)
    {
        dim3 grid(NTOK / 128, QKV_ROWS / 128, BATCH);
        gemm_qkv<<<grid, 256>>>(Wmat, x);
    }
    // logits = [q;pos]^T [k;q]
    {
        dim3 grid(NTOK / 128, NTOK / 128, BATCH);
        gemm_logits<<<grid, 256>>>();
    }
    // softmax rows
    softmax_kernel<<<BATCH * NTOK, 256>>>();

    // out = v @ att^T
    {
        dim3 grid(NTOK / 128, CDIM / 128, BATCH);
        gemm_out<<<grid, 256>>>(out);
    }
}

// round 3
// speedup vs baseline: 2.4267x; 2.4267x over previous
#include <cuda_runtime.h>
#include <cuda_bf16.h>
#include <cstdint>

#define BATCH 64
#define CDIM  512
#define NTOK  1024

typedef __nv_bfloat16 bf;

// ---------------- scratch (device globals) ----------------------------------
__device__ bf g_xTh[(size_t)BATCH * NTOK * CDIM];   // [b][n][c] hi
__device__ bf g_xTm[(size_t)BATCH * NTOK * CDIM];   // mid
__device__ bf g_Wh [(size_t)1536 * 512];
__device__ bf g_Wm [(size_t)1536 * 512];
__device__ bf g_posh[(size_t)NTOK * CDIM];          // [n][c]
__device__ bf g_posm[(size_t)NTOK * CDIM];
__device__ bf g_qkh[(size_t)BATCH * NTOK * NTOK];   // [b][n][o]  o<512:qT, o>=512:kT
__device__ bf g_qkm[(size_t)BATCH * NTOK * NTOK];
__device__ bf g_vh [(size_t)BATCH * CDIM * NTOK];   // [b][c][n]
__device__ bf g_vm [(size_t)BATCH * CDIM * NTOK];
__device__ float g_logit[(size_t)BATCH * NTOK * NTOK];
__device__ bf g_atth[(size_t)BATCH * NTOK * NTOK];  // [b][n][m]
__device__ bf g_attm[(size_t)BATCH * NTOK * NTOK];

// ---------------- PTX helpers ----------------------------------------------
__device__ __forceinline__ uint32_t smem_u32(const void* p) {
    uint32_t a;
    asm("{ .reg .u64 t; cvta.to.shared.u64 t, %1; cvt.u32.u64 %0, t; }" : "=r"(a) : "l"(p));
    return a;
}
__device__ __forceinline__ void cpa16(uint32_t dst, const void* src) {
    asm volatile("cp.async.cg.shared.global [%0], [%1], 16;" :: "r"(dst), "l"(src));
}
__device__ __forceinline__ void cp_commit() {
    asm volatile("cp.async.commit_group;");
}
__device__ __forceinline__ void ldsm4(uint32_t r[4], uint32_t addr) {
    asm volatile("ldmatrix.sync.aligned.m8n8.x4.shared.b16 {%0,%1,%2,%3}, [%4];"
                 : "=r"(r[0]), "=r"(r[1]), "=r"(r[2]), "=r"(r[3]) : "r"(addr));
}
__device__ __forceinline__ void mma16816(float c[4], const uint32_t a[4], const uint32_t b[2]) {
    asm volatile("mma.sync.aligned.m16n8k16.row.col.f32.bf16.bf16.f32 "
                 "{%0,%1,%2,%3}, {%4,%5,%6,%7}, {%8,%9}, {%0,%1,%2,%3};"
                 : "+f"(c[0]), "+f"(c[1]), "+f"(c[2]), "+f"(c[3])
                 : "r"(a[0]), "r"(a[1]), "r"(a[2]), "r"(a[3]), "r"(b[0]), "r"(b[1]));
}

// smem tile layout: rows padded to 40 bf16 (80B) -> conflict-free ldmatrix
#define T_BYTES 10240           // 128 rows * 80B
#define OFF_AH 0
#define OFF_AM 10240
#define OFF_BH 20480
#define OFF_BM 30720
#define STAGE_BYTES 40960
#define SMEM_BYTES (2 * STAGE_BYTES)

__device__ __forceinline__ void split_store(bf* __restrict__ ph, bf* __restrict__ pm,
                                            size_t off, float v0, float v1) {
    bf h0 = __float2bfloat16(v0), h1 = __float2bfloat16(v1);
    bf m0 = __float2bfloat16(v0 - __bfloat162float(h0));
    bf m1 = __float2bfloat16(v1 - __bfloat162float(h1));
    __nv_bfloat162 hh; hh.x = h0; hh.y = h1;
    __nv_bfloat162 mm; mm.x = m0; mm.y = m1;
    *reinterpret_cast<__nv_bfloat162*>(ph + off) = hh;
    *reinterpret_cast<__nv_bfloat162*>(pm + off) = mm;
}

// ---------------- unified bf16x3 GEMM ---------------------------------------
// D tile 128x128, K-chunk 32, 256 threads, warps 2(m) x 4(n), double-buffered.
// MODE 0: qkT[b][n][o]  = xT[n][:] . W[o][:]          K=512
// MODE 1: v[b][c][n]    = W[1024+c][:] . xT[n][:]      K=512
// MODE 2: logit[b][n][m]= qT.kT + posT.qT (stacked K)  K=1024
// MODE 3: out[b][c][n]  = v[c][:] . att[n][:]          K=1024
template <int MODE>
__global__ __launch_bounds__(256, 2) void mma_gemm(float* __restrict__ outp) {
    extern __shared__ __align__(128) char smem[];
    const uint32_t sbase = smem_u32(smem);
    const int tid = threadIdx.x;
    const int wid = tid >> 5, lane = tid & 31;
    const int b = blockIdx.z;
    const int nBase = blockIdx.x * 128;   // output cols (B rows)
    const int mBase = blockIdx.y * 128;   // output rows (A rows)
    const int wm = (wid >> 2) * 64, wn = (wid & 3) * 32;

    constexpr int KDIM = (MODE < 2) ? 512 : 1024;
    constexpr int NIT = KDIM / 32;

    const size_t bQK = (size_t)b << 20;        // b * 1024*1024
    const size_t bXT = (size_t)b << 19;        // b * 512*1024

    float acc[4][4][4];
#pragma unroll
    for (int i = 0; i < 4; i++)
#pragma unroll
        for (int j = 0; j < 4; j++)
#pragma unroll
            for (int k = 0; k < 4; k++) acc[i][j][k] = 0.f;

    // per-thread cp.async coords (2 chunks per tile)
    const int row0 = tid >> 2, c16 = tid & 3;          // chunk 0
    const int row1 = (tid + 256) >> 2;                 // chunk 1 (same c16)

    auto issue_stage = [&](int stage, int kt) {
        const bf *pah, *pam, *pbh, *pbm;
        int lda, ldb;
        if (MODE == 0) {
            pah = g_xTh + bXT + (size_t)mBase * 512 + kt; pam = g_xTm + bXT + (size_t)mBase * 512 + kt; lda = 512;
            pbh = g_Wh + (size_t)nBase * 512 + kt;        pbm = g_Wm + (size_t)nBase * 512 + kt;        ldb = 512;
        } else if (MODE == 1) {
            pah = g_Wh + (size_t)(1024 + mBase) * 512 + kt; pam = g_Wm + (size_t)(1024 + mBase) * 512 + kt; lda = 512;
            pbh = g_xTh + bXT + (size_t)nBase * 512 + kt;   pbm = g_xTm + bXT + (size_t)nBase * 512 + kt;   ldb = 512;
        } else if (MODE == 2) {
            if (kt < 512) {
                pah = g_qkh + bQK + (size_t)mBase * 1024 + kt; pam = g_qkm + bQK + (size_t)mBase * 1024 + kt; lda = 1024;
                pbh = g_qkh + bQK + (size_t)nBase * 1024 + 512 + kt; pbm = g_qkm + bQK + (size_t)nBase * 1024 + 512 + kt;
            } else {
                pah = g_posh + (size_t)mBase * 512 + (kt - 512); pam = g_posm + (size_t)mBase * 512 + (kt - 512); lda = 512;
                pbh = g_qkh + bQK + (size_t)nBase * 1024 + (kt - 512); pbm = g_qkm + bQK + (size_t)nBase * 1024 + (kt - 512);
            }
            ldb = 1024;
        } else {
            pah = g_vh + bXT + (size_t)mBase * 1024 + kt; pam = g_vm + bXT + (size_t)mBase * 1024 + kt; lda = 1024;
            pbh = g_atth + bQK + (size_t)nBase * 1024 + kt; pbm = g_attm + bQK + (size_t)nBase * 1024 + kt; ldb = 1024;
        }
        const uint32_t sb = sbase + stage * STAGE_BYTES;
        const uint32_t d0 = row0 * 80 + c16 * 16;
        const uint32_t d1 = row1 * 80 + c16 * 16;
        const int s0a = row0 * lda + c16 * 8, s1a = row1 * lda + c16 * 8;
        const int s0b = row0 * ldb + c16 * 8, s1b = row1 * ldb + c16 * 8;
        cpa16(sb + OFF_AH + d0, pah + s0a); cpa16(sb + OFF_AH + d1, pah + s1a);
        cpa16(sb + OFF_AM + d0, pam + s0a); cpa16(sb + OFF_AM + d1, pam + s1a);
        cpa16(sb + OFF_BH + d0, pbh + s0b); cpa16(sb + OFF_BH + d1, pbh + s1b);
        cpa16(sb + OFF_BM + d0, pbm + s0b); cpa16(sb + OFF_BM + d1, pbm + s1b);
        cp_commit();
    };

    auto compute = [&](int stage) {
        const uint32_t base = sbase + stage * STAGE_BYTES;
#pragma unroll
        for (int ks = 0; ks < 32; ks += 16) {
            uint32_t bh[4][2], bm[4][2];
            const int sel = lane >> 3;            // 0..3
#pragma unroll
            for (int pr = 0; pr < 2; pr++) {
                const int nt = 2 * pr + (sel >> 1);
                const int kb = sel & 1;
                const uint32_t ra = base + OFF_BH + (uint32_t)(wn + nt * 8 + (lane & 7)) * 80 + (ks + kb * 8) * 2;
                uint32_t r[4];
                ldsm4(r, ra);
                bh[2 * pr][0] = r[0]; bh[2 * pr][1] = r[1];
                bh[2 * pr + 1][0] = r[2]; bh[2 * pr + 1][1] = r[3];
                ldsm4(r, ra + (OFF_BM - OFF_BH));
                bm[2 * pr][0] = r[0]; bm[2 * pr][1] = r[1];
                bm[2 * pr + 1][0] = r[2]; bm[2 * pr + 1][1] = r[3];
            }
#pragma unroll
            for (int mt = 0; mt < 4; mt++) {
                const uint32_t aa = base + OFF_AH + (uint32_t)(wm + mt * 16 + (sel & 1) * 8 + (lane & 7)) * 80 + (ks + (sel >> 1) * 8) * 2;
                uint32_t ah[4], am[4];
                ldsm4(ah, aa);
                ldsm4(am, aa + (OFF_AM - OFF_AH));
#pragma unroll
                for (int nt = 0; nt < 4; nt++) {
                    mma16816(acc[mt][nt], ah, bh[nt]);
                    mma16816(acc[mt][nt], ah, bm[nt]);
                    mma16816(acc[mt][nt], am, bh[nt]);
                }
            }
        }
    };

    issue_stage(0, 0);
    for (int it = 0; it < NIT; it++) {
        if (it + 1 < NIT) {
            issue_stage((it + 1) & 1, (it + 1) * 32);
            asm volatile("cp.async.wait_group 1;");
        } else {
            asm volatile("cp.async.wait_group 0;");
        }
        __syncthreads();
        compute(it & 1);
        __syncthreads();
    }

    // ---------------- epilogue ----------------
    bf *oh = nullptr, *om = nullptr;
    float* of = nullptr;
    if (MODE == 0)      { oh = g_qkh + bQK; om = g_qkm + bQK; }
    else if (MODE == 1) { oh = g_vh + bXT;  om = g_vm + bXT; }
    else if (MODE == 2) { of = g_logit + bQK; }
    else                { of = outp + bXT; }

    const int lr = lane >> 2, lc = 2 * (lane & 3);
#pragma unroll
    for (int mt = 0; mt < 4; mt++) {
#pragma unroll
        for (int nt = 0; nt < 4; nt++) {
            const int r0 = mBase + wm + mt * 16 + lr;
            const int c0 = nBase + wn + nt * 8 + lc;
            if (MODE < 2) {
                split_store(oh, om, (size_t)r0 * 1024 + c0, acc[mt][nt][0], acc[mt][nt][1]);
                split_store(oh, om, (size_t)(r0 + 8) * 1024 + c0, acc[mt][nt][2], acc[mt][nt][3]);
            } else {
                float2 v0; v0.x = acc[mt][nt][0]; v0.y = acc[mt][nt][1];
                float2 v1; v1.x = acc[mt][nt][2]; v1.y = acc[mt][nt][3];
                *reinterpret_cast<float2*>(of + (size_t)r0 * 1024 + c0) = v0;
                *reinterpret_cast<float2*>(of + (size_t)(r0 + 8) * 1024 + c0) = v1;
            }
        }
    }
}

// ---------------- prep kernels ----------------------------------------------
__global__ void prep_w(const float* __restrict__ W) {
    int idx = blockIdx.x * blockDim.x + threadIdx.x;
    if (idx >= 1536 * 512) return;
    float v = W[idx];
    bf h = __float2bfloat16(v);
    g_Wh[idx] = h;
    g_Wm[idx] = __float2bfloat16(v - __bfloat162float(h));
}

__global__ void prep_pos(const float* __restrict__ rel_h, const float* __restrict__ rel_w) {
    int idx = blockIdx.x * blockDim.x + threadIdx.x;   // over [n][c]
    if (idx >= NTOK * CDIM) return;
    int c = idx & 511, n = idx >> 9;
    int h = n >> 5, w = n & 31;
    float v = rel_h[c * 32 + h] + rel_w[c * 32 + w];
    bf hb = __float2bfloat16(v);
    g_posh[idx] = hb;
    g_posm[idx] = __float2bfloat16(v - __bfloat162float(hb));
}

__global__ void transpose_kernel(const float* __restrict__ x) {
    __shared__ float t[32][33];
    int b = blockIdx.z;
    int n0 = blockIdx.x * 32, c0 = blockIdx.y * 32;
    const float* src = x + (size_t)b * CDIM * NTOK;
    size_t dbase = (size_t)b * NTOK * CDIM;
    int tx = threadIdx.x, ty = threadIdx.y;
#pragma unroll
    for (int j = 0; j < 32; j += 8)
        t[ty + j][tx] = src[(size_t)(c0 + ty + j) * NTOK + n0 + tx];
    __syncthreads();
#pragma unroll
    for (int j = 0; j < 32; j += 8) {
        float v = t[tx][ty + j];
        size_t off = dbase + (size_t)(n0 + ty + j) * CDIM + c0 + tx;
        bf h = __float2bfloat16(v);
        g_xTh[off] = h;
        g_xTm[off] = __float2bfloat16(v - __bfloat162float(h));
    }
}

__global__ __launch_bounds__(256) void softmax_kernel() {
    size_t row = blockIdx.x;
    const float* p = g_logit + row * NTOK;
    int tid = threadIdx.x;

    float4 v = *(const float4*)&p[tid * 4];
    float m = fmaxf(fmaxf(v.x, v.y), fmaxf(v.z, v.w));
#pragma unroll
    for (int o = 16; o; o >>= 1) m = fmaxf(m, __shfl_xor_sync(~0u, m, o));
    __shared__ float red[8];
    if ((tid & 31) == 0) red[tid >> 5] = m;
    __syncthreads();
    float bm = red[0];
#pragma unroll
    for (int i = 1; i < 8; i++) bm = fmaxf(bm, red[i]);
    __syncthreads();

    v.x = __expf(v.x - bm); v.y = __expf(v.y - bm);
    v.z = __expf(v.z - bm); v.w = __expf(v.w - bm);
    float s = v.x + v.y + v.z + v.w;
#pragma unroll
    for (int o = 16; o; o >>= 1) s += __shfl_xor_sync(~0u, s, o);
    if ((tid & 31) == 0) red[tid >> 5] = s;
    __syncthreads();
    float bs = 0.f;
#pragma unroll
    for (int i = 0; i < 8; i++) bs += red[i];
    float inv = 1.0f / bs;
    v.x *= inv; v.y *= inv; v.z *= inv; v.w *= inv;

    size_t off = row * NTOK + tid * 4;
    split_store(g_atth, g_attm, off, v.x, v.y);
    split_store(g_atth, g_attm, off + 2, v.z, v.w);
}

// ---------------------------------------------------------------------------
extern "C" void kernel_launch(void* const* d_in, const int* in_sizes, int n_in,
                              void* d_out, int out_size) {
    const float* x     = (const float*)d_in[0];
    const float* Wmat  = (const float*)d_in[1];
    const float* rel_h = (const float*)d_in[2];
    const float* rel_w = (const float*)d_in[3];
    float* out = (float*)d_out;

    static bool attr_set = false;
    if (!attr_set) {
        cudaFuncSetAttribute(mma_gemm<0>, cudaFuncAttributeMaxDynamicSharedMemorySize, SMEM_BYTES);
        cudaFuncSetAttribute(mma_gemm<1>, cudaFuncAttributeMaxDynamicSharedMemorySize, SMEM_BYTES);
        cudaFuncSetAttribute(mma_gemm<2>, cudaFuncAttributeMaxDynamicSharedMemorySize, SMEM_BYTES);
        cudaFuncSetAttribute(mma_gemm<3>, cudaFuncAttributeMaxDynamicSharedMemorySize, SMEM_BYTES);
        attr_set = true;
    }

    prep_w<<<(1536 * 512 + 255) / 256, 256>>>(Wmat);
    prep_pos<<<(NTOK * CDIM + 255) / 256, 256>>>(rel_h, rel_w);
    transpose_kernel<<<dim3(32, 16, 64), dim3(32, 8)>>>(x);

    mma_gemm<0><<<dim3(8, 8, 64), 256, SMEM_BYTES>>>(nullptr);   // qkT (hi/mid)
    mma_gemm<1><<<dim3(8, 4, 64), 256, SMEM_BYTES>>>(nullptr);   // v   (hi/mid)
    mma_gemm<2><<<dim3(8, 8, 64), 256, SMEM_BYTES>>>(nullptr);   // logits fp32
    softmax_kernel<<<BATCH * NTOK, 256>>>();                     // att (hi/mid)
    mma_gemm<3><<<dim3(8, 4, 64), 256, SMEM_BYTES>>>(out);       // out fp32
}

// round 4
// speedup vs baseline: 2.8589x; 1.1781x over previous
#include <cuda_runtime.h>
#include <cuda_bf16.h>
#include <cstdint>

#define BATCH 64
#define CDIM  512
#define NTOK  1024

typedef __nv_bfloat16 bf;

// ---------------- scratch (device globals) ----------------------------------
__device__ bf g_xTh[(size_t)BATCH * NTOK * CDIM];   // [b][n][c] hi
__device__ bf g_xTm[(size_t)BATCH * NTOK * CDIM];   // mid
__device__ bf g_Wh [(size_t)1536 * 512];
__device__ bf g_Wm [(size_t)1536 * 512];
__device__ bf g_posh[(size_t)NTOK * CDIM];          // [n][c]
__device__ bf g_posm[(size_t)NTOK * CDIM];
__device__ bf g_qkh[(size_t)BATCH * NTOK * NTOK];   // [b][n][o]  o<512:qT, o>=512:kT
__device__ bf g_qkm[(size_t)BATCH * NTOK * NTOK];
__device__ bf g_vh [(size_t)BATCH * CDIM * NTOK];   // [b][c][n]
__device__ bf g_vm [(size_t)BATCH * CDIM * NTOK];
__device__ float g_logit[(size_t)BATCH * NTOK * NTOK];
__device__ bf g_atth[(size_t)BATCH * NTOK * NTOK];  // [b][n][m]
__device__ bf g_attm[(size_t)BATCH * NTOK * NTOK];

// ---------------- PTX helpers ----------------------------------------------
__device__ __forceinline__ uint32_t smem_u32(const void* p) {
    uint32_t a;
    asm("{ .reg .u64 t; cvta.to.shared.u64 t, %1; cvt.u32.u64 %0, t; }" : "=r"(a) : "l"(p));
    return a;
}
__device__ __forceinline__ void cpa16(uint32_t dst, const void* src) {
    asm volatile("cp.async.cg.shared.global [%0], [%1], 16;" :: "r"(dst), "l"(src));
}
__device__ __forceinline__ void ldsm4(uint32_t r[4], uint32_t addr) {
    asm volatile("ldmatrix.sync.aligned.m8n8.x4.shared.b16 {%0,%1,%2,%3}, [%4];"
                 : "=r"(r[0]), "=r"(r[1]), "=r"(r[2]), "=r"(r[3]) : "r"(addr));
}
__device__ __forceinline__ void mma16816(float c[4], const uint32_t a[4], const uint32_t b[2]) {
    asm volatile("mma.sync.aligned.m16n8k16.row.col.f32.bf16.bf16.f32 "
                 "{%0,%1,%2,%3}, {%4,%5,%6,%7}, {%8,%9}, {%0,%1,%2,%3};"
                 : "+f"(c[0]), "+f"(c[1]), "+f"(c[2]), "+f"(c[3])
                 : "r"(a[0]), "r"(a[1]), "r"(a[2]), "r"(a[3]), "r"(b[0]), "r"(b[1]));
}

// Swizzled 64B-row tile: 128 rows x 4 chunks of 16B. Conflict-free for
// cp.async 16B stores and ldmatrix 8-row reads.
__device__ __forceinline__ uint32_t sw_off(int row, int chunk) {
    return (uint32_t)(row * 64 + ((chunk ^ ((row >> 1) & 3)) << 4));
}

#define T_BYTES 8192            // 128 rows * 64B
#define OFF_AH 0
#define OFF_AM 8192
#define OFF_BH 16384
#define OFF_BM 24576
#define STAGE_BYTES 32768
#define NSTAGE 3
#define SMEM_BYTES (NSTAGE * STAGE_BYTES)

__device__ __forceinline__ void split_store(bf* __restrict__ ph, bf* __restrict__ pm,
                                            size_t off, float v0, float v1) {
    bf h0 = __float2bfloat16(v0), h1 = __float2bfloat16(v1);
    bf m0 = __float2bfloat16(v0 - __bfloat162float(h0));
    bf m1 = __float2bfloat16(v1 - __bfloat162float(h1));
    __nv_bfloat162 hh; hh.x = h0; hh.y = h1;
    __nv_bfloat162 mm; mm.x = m0; mm.y = m1;
    *reinterpret_cast<__nv_bfloat162*>(ph + off) = hh;
    *reinterpret_cast<__nv_bfloat162*>(pm + off) = mm;
}

// ---------------- unified bf16x3 GEMM ---------------------------------------
// D tile 128x128, K-chunk 32, 256 threads, warps 2(m) x 4(n), 3-stage pipeline.
template <int MODE>
__global__ __launch_bounds__(256, 2) void mma_gemm(float* __restrict__ outp) {
    extern __shared__ __align__(128) char smem[];
    const uint32_t sbase = smem_u32(smem);
    const int tid = threadIdx.x;
    const int wid = tid >> 5, lane = tid & 31;
    const int b = blockIdx.z;
    const int nBase = blockIdx.x * 128;
    const int mBase = blockIdx.y * 128;
    const int wm = (wid >> 2) * 64, wn = (wid & 3) * 32;

    constexpr int KDIM = (MODE < 2) ? 512 : 1024;
    constexpr int NIT = KDIM / 32;

    const size_t bQK = (size_t)b << 20;
    const size_t bXT = (size_t)b << 19;

    float acc[4][4][4];
#pragma unroll
    for (int i = 0; i < 4; i++)
#pragma unroll
        for (int j = 0; j < 4; j++)
#pragma unroll
            for (int k = 0; k < 4; k++) acc[i][j][k] = 0.f;

    auto issue_stage = [&](int stage, int kt) {
        const bf *pah, *pam, *pbh, *pbm;
        int lda, ldb;
        if (MODE == 0) {
            pah = g_xTh + bXT + (size_t)mBase * 512 + kt; pam = g_xTm + bXT + (size_t)mBase * 512 + kt; lda = 512;
            pbh = g_Wh + (size_t)nBase * 512 + kt;        pbm = g_Wm + (size_t)nBase * 512 + kt;        ldb = 512;
        } else if (MODE == 1) {
            pah = g_Wh + (size_t)(1024 + mBase) * 512 + kt; pam = g_Wm + (size_t)(1024 + mBase) * 512 + kt; lda = 512;
            pbh = g_xTh + bXT + (size_t)nBase * 512 + kt;   pbm = g_xTm + bXT + (size_t)nBase * 512 + kt;   ldb = 512;
        } else if (MODE == 2) {
            if (kt < 512) {
                pah = g_qkh + bQK + (size_t)mBase * 1024 + kt; pam = g_qkm + bQK + (size_t)mBase * 1024 + kt; lda = 1024;
                pbh = g_qkh + bQK + (size_t)nBase * 1024 + 512 + kt; pbm = g_qkm + bQK + (size_t)nBase * 1024 + 512 + kt;
            } else {
                pah = g_posh + (size_t)mBase * 512 + (kt - 512); pam = g_posm + (size_t)mBase * 512 + (kt - 512); lda = 512;
                pbh = g_qkh + bQK + (size_t)nBase * 1024 + (kt - 512); pbm = g_qkm + bQK + (size_t)nBase * 1024 + (kt - 512);
            }
            ldb = 1024;
        } else {
            pah = g_vh + bXT + (size_t)mBase * 1024 + kt; pam = g_vm + bXT + (size_t)mBase * 1024 + kt; lda = 1024;
            pbh = g_atth + bQK + (size_t)nBase * 1024 + kt; pbm = g_attm + bQK + (size_t)nBase * 1024 + kt; ldb = 1024;
        }
        const uint32_t sb = sbase + stage * STAGE_BYTES;
#pragma unroll
        for (int j = 0; j < 2; j++) {
            const int idx = tid + j * 256;          // 0..511
            const int row = idx >> 2, ch = idx & 3;
            const uint32_t d = sw_off(row, ch);
            const int sa = row * lda + ch * 8;
            const int sb_ = row * ldb + ch * 8;
            cpa16(sb + OFF_AH + d, pah + sa);
            cpa16(sb + OFF_AM + d, pam + sa);
            cpa16(sb + OFF_BH + d, pbh + sb_);
            cpa16(sb + OFF_BM + d, pbm + sb_);
        }
        asm volatile("cp.async.commit_group;");
    };

    auto compute = [&](int stage) {
        const uint32_t base = sbase + stage * STAGE_BYTES;
        const int sel = lane >> 3;            // 0..3
#pragma unroll
        for (int ks = 0; ks < 32; ks += 16) {
            uint32_t bhf[4][2], bmf[4][2];
#pragma unroll
            for (int pr = 0; pr < 2; pr++) {
                const int nt = 2 * pr + (sel >> 1);
                const int kb = sel & 1;
                const uint32_t ra = base + OFF_BH +
                    sw_off(wn + nt * 8 + (lane & 7), ks / 8 + kb);
                uint32_t r[4];
                ldsm4(r, ra);
                bhf[2 * pr][0] = r[0]; bhf[2 * pr][1] = r[1];
                bhf[2 * pr + 1][0] = r[2]; bhf[2 * pr + 1][1] = r[3];
                ldsm4(r, ra + (OFF_BM - OFF_BH));
                bmf[2 * pr][0] = r[0]; bmf[2 * pr][1] = r[1];
                bmf[2 * pr + 1][0] = r[2]; bmf[2 * pr + 1][1] = r[3];
            }
#pragma unroll
            for (int mt = 0; mt < 4; mt++) {
                const uint32_t aa = base + OFF_AH +
                    sw_off(wm + mt * 16 + (sel & 1) * 8 + (lane & 7), ks / 8 + (sel >> 1));
                uint32_t ah[4], am[4];
                ldsm4(ah, aa);
                ldsm4(am, aa + (OFF_AM - OFF_AH));
#pragma unroll
                for (int nt = 0; nt < 4; nt++) mma16816(acc[mt][nt], ah, bhf[nt]);
#pragma unroll
                for (int nt = 0; nt < 4; nt++) mma16816(acc[mt][nt], ah, bmf[nt]);
#pragma unroll
                for (int nt = 0; nt < 4; nt++) mma16816(acc[mt][nt], am, bhf[nt]);
            }
        }
    };

    issue_stage(0, 0);
    issue_stage(1, 32);
    for (int it = 0; it < NIT; it++) {
        if (it + 2 < NIT) {
            asm volatile("cp.async.wait_group 1;");
        } else {
            asm volatile("cp.async.wait_group 0;");
        }
        __syncthreads();
        if (it + 2 < NIT) issue_stage((it + 2) % NSTAGE, (it + 2) * 32);
        compute(it % NSTAGE);
    }

    // ---------------- epilogue ----------------
    bf *oh = nullptr, *om = nullptr;
    float* of = nullptr;
    if (MODE == 0)      { oh = g_qkh + bQK; om = g_qkm + bQK; }
    else if (MODE == 1) { oh = g_vh + bXT;  om = g_vm + bXT; }
    else if (MODE == 2) { of = g_logit + bQK; }
    else                { of = outp + bXT; }

    const int lr = lane >> 2, lc = 2 * (lane & 3);
#pragma unroll
    for (int mt = 0; mt < 4; mt++) {
#pragma unroll
        for (int nt = 0; nt < 4; nt++) {
            const int r0 = mBase + wm + mt * 16 + lr;
            const int c0 = nBase + wn + nt * 8 + lc;
            if (MODE < 2) {
                split_store(oh, om, (size_t)r0 * 1024 + c0, acc[mt][nt][0], acc[mt][nt][1]);
                split_store(oh, om, (size_t)(r0 + 8) * 1024 + c0, acc[mt][nt][2], acc[mt][nt][3]);
            } else {
                float2 v0; v0.x = acc[mt][nt][0]; v0.y = acc[mt][nt][1];
                float2 v1; v1.x = acc[mt][nt][2]; v1.y = acc[mt][nt][3];
                *reinterpret_cast<float2*>(of + (size_t)r0 * 1024 + c0) = v0;
                *reinterpret_cast<float2*>(of + (size_t)(r0 + 8) * 1024 + c0) = v1;
            }
        }
    }
}

// ---------------- prep kernels ----------------------------------------------
__global__ void prep_w(const float* __restrict__ W) {
    int idx = blockIdx.x * blockDim.x + threadIdx.x;
    if (idx >= 1536 * 512) return;
    float v = W[idx];
    bf h = __float2bfloat16(v);
    g_Wh[idx] = h;
    g_Wm[idx] = __float2bfloat16(v - __bfloat162float(h));
}

__global__ void prep_pos(const float* __restrict__ rel_h, const float* __restrict__ rel_w) {
    int idx = blockIdx.x * blockDim.x + threadIdx.x;
    if (idx >= NTOK * CDIM) return;
    int c = idx & 511, n = idx >> 9;
    int h = n >> 5, w = n & 31;
    float v = rel_h[c * 32 + h] + rel_w[c * 32 + w];
    bf hb = __float2bfloat16(v);
    g_posh[idx] = hb;
    g_posm[idx] = __float2bfloat16(v - __bfloat162float(hb));
}

__global__ void transpose_kernel(const float* __restrict__ x) {
    __shared__ float t[32][33];
    int b = blockIdx.z;
    int n0 = blockIdx.x * 32, c0 = blockIdx.y * 32;
    const float* src = x + (size_t)b * CDIM * NTOK;
    size_t dbase = (size_t)b * NTOK * CDIM;
    int tx = threadIdx.x, ty = threadIdx.y;
#pragma unroll
    for (int j = 0; j < 32; j += 8)
        t[ty + j][tx] = src[(size_t)(c0 + ty + j) * NTOK + n0 + tx];
    __syncthreads();
#pragma unroll
    for (int j = 0; j < 32; j += 8) {
        float v = t[tx][ty + j];
        size_t off = dbase + (size_t)(n0 + ty + j) * CDIM + c0 + tx;
        bf h = __float2bfloat16(v);
        g_xTh[off] = h;
        g_xTm[off] = __float2bfloat16(v - __bfloat162float(h));
    }
}

__global__ __launch_bounds__(256) void softmax_kernel() {
    size_t row = blockIdx.x;
    const float* p = g_logit + row * NTOK;
    int tid = threadIdx.x;

    float4 v = *(const float4*)&p[tid * 4];
    float m = fmaxf(fmaxf(v.x, v.y), fmaxf(v.z, v.w));
#pragma unroll
    for (int o = 16; o; o >>= 1) m = fmaxf(m, __shfl_xor_sync(~0u, m, o));
    __shared__ float red[8];
    if ((tid & 31) == 0) red[tid >> 5] = m;
    __syncthreads();
    float bm = red[0];
#pragma unroll
    for (int i = 1; i < 8; i++) bm = fmaxf(bm, red[i]);
    __syncthreads();

    v.x = __expf(v.x - bm); v.y = __expf(v.y - bm);
    v.z = __expf(v.z - bm); v.w = __expf(v.w - bm);
    float s = v.x + v.y + v.z + v.w;
#pragma unroll
    for (int o = 16; o; o >>= 1) s += __shfl_xor_sync(~0u, s, o);
    if ((tid & 31) == 0) red[tid >> 5] = s;
    __syncthreads();
    float bs = 0.f;
#pragma unroll
    for (int i = 0; i < 8; i++) bs += red[i];
    float inv = 1.0f / bs;
    v.x *= inv; v.y *= inv; v.z *= inv; v.w *= inv;

    size_t off = row * NTOK + tid * 4;
    split_store(g_atth, g_attm, off, v.x, v.y);
    split_store(g_atth, g_attm, off + 2, v.z, v.w);
}

// ---------------------------------------------------------------------------
extern "C" void kernel_launch(void* const* d_in, const int* in_sizes, int n_in,
                              void* d_out, int out_size) {
    const float* x     = (const float*)d_in[0];
    const float* Wmat  = (const float*)d_in[1];
    const float* rel_h = (const float*)d_in[2];
    const float* rel_w = (const float*)d_in[3];
    float* out = (float*)d_out;

    static bool attr_set = false;
    if (!attr_set) {
        cudaFuncSetAttribute(mma_gemm<0>, cudaFuncAttributeMaxDynamicSharedMemorySize, SMEM_BYTES);
        cudaFuncSetAttribute(mma_gemm<1>, cudaFuncAttributeMaxDynamicSharedMemorySize, SMEM_BYTES);
        cudaFuncSetAttribute(mma_gemm<2>, cudaFuncAttributeMaxDynamicSharedMemorySize, SMEM_BYTES);
        cudaFuncSetAttribute(mma_gemm<3>, cudaFuncAttributeMaxDynamicSharedMemorySize, SMEM_BYTES);
        attr_set = true;
    }

    prep_w<<<(1536 * 512 + 255) / 256, 256>>>(Wmat);
    prep_pos<<<(NTOK * CDIM + 255) / 256, 256>>>(rel_h, rel_w);
    transpose_kernel<<<dim3(32, 16, 64), dim3(32, 8)>>>(x);

    mma_gemm<0><<<dim3(8, 8, 64), 256, SMEM_BYTES>>>(nullptr);   // qkT (hi/mid)
    mma_gemm<1><<<dim3(8, 4, 64), 256, SMEM_BYTES>>>(nullptr);   // v   (hi/mid)
    mma_gemm<2><<<dim3(8, 8, 64), 256, SMEM_BYTES>>>(nullptr);   // logits fp32
    softmax_kernel<<<BATCH * NTOK, 256>>>();                     // att (hi/mid)
    mma_gemm<3><<<dim3(8, 4, 64), 256, SMEM_BYTES>>>(out);       // out fp32
}

// round 5
// speedup vs baseline: 3.7825x; 1.3231x over previous
#include <cuda_runtime.h>
#include <cuda_bf16.h>
#include <cuda_fp16.h>
#include <cstdint>

#define BATCH 64
#define CDIM  512
#define NTOK  1024

typedef __nv_bfloat16 bf;

// ---------------- scratch (device globals) ----------------------------------
__device__ bf g_xTh[(size_t)BATCH * NTOK * CDIM];   // [b][n][c] hi
__device__ bf g_xTm[(size_t)BATCH * NTOK * CDIM];   // mid
__device__ bf g_Wh [(size_t)1536 * 512];
__device__ bf g_Wm [(size_t)1536 * 512];
__device__ bf g_rhwh[(size_t)64 * 512];             // [r][c] r<32: rel_h^T, r>=32: rel_w^T
__device__ bf g_rhwm[(size_t)64 * 512];
__device__ bf g_qkh[(size_t)BATCH * NTOK * NTOK];   // [b][n][o]  o<512:qT, o>=512:kT
__device__ bf g_qkm[(size_t)BATCH * NTOK * NTOK];
__device__ __half g_vh16[(size_t)BATCH * CDIM * NTOK];  // [b][c][n] fp16 hi
__device__ __half g_vl16[(size_t)BATCH * CDIM * NTOK];  // fp16 lo
__device__ float  g_logit[(size_t)BATCH * NTOK * NTOK];
__device__ __half g_att16[(size_t)BATCH * NTOK * NTOK]; // [b][n][m]
__device__ float  g_P[(size_t)BATCH * 64 * NTOK];       // [b][r][m]

// ---------------- PTX helpers ----------------------------------------------
__device__ __forceinline__ uint32_t smem_u32(const void* p) {
    uint32_t a;
    asm("{ .reg .u64 t; cvta.to.shared.u64 t, %1; cvt.u32.u64 %0, t; }" : "=r"(a) : "l"(p));
    return a;
}
__device__ __forceinline__ void cpa16(uint32_t dst, const void* src) {
    asm volatile("cp.async.cg.shared.global [%0], [%1], 16;" :: "r"(dst), "l"(src));
}
__device__ __forceinline__ void ldsm4(uint32_t r[4], uint32_t addr) {
    asm volatile("ldmatrix.sync.aligned.m8n8.x4.shared.b16 {%0,%1,%2,%3}, [%4];"
                 : "=r"(r[0]), "=r"(r[1]), "=r"(r[2]), "=r"(r[3]) : "r"(addr));
}
__device__ __forceinline__ void mma16816(float c[4], const uint32_t a[4], const uint32_t b[2]) {
    asm volatile("mma.sync.aligned.m16n8k16.row.col.f32.bf16.bf16.f32 "
                 "{%0,%1,%2,%3}, {%4,%5,%6,%7}, {%8,%9}, {%0,%1,%2,%3};"
                 : "+f"(c[0]), "+f"(c[1]), "+f"(c[2]), "+f"(c[3])
                 : "r"(a[0]), "r"(a[1]), "r"(a[2]), "r"(a[3]), "r"(b[0]), "r"(b[1]));
}
__device__ __forceinline__ void mma16816h(float c[4], const uint32_t a[4], const uint32_t b[2]) {
    asm volatile("mma.sync.aligned.m16n8k16.row.col.f32.f16.f16.f32 "
                 "{%0,%1,%2,%3}, {%4,%5,%6,%7}, {%8,%9}, {%0,%1,%2,%3};"
                 : "+f"(c[0]), "+f"(c[1]), "+f"(c[2]), "+f"(c[3])
                 : "r"(a[0]), "r"(a[1]), "r"(a[2]), "r"(a[3]), "r"(b[0]), "r"(b[1]));
}

// Swizzled 64B-row tile: row*64B, chunk xor'd by (row>>1)&3.
__device__ __forceinline__ uint32_t sw_off(int row, int chunk) {
    return (uint32_t)(row * 64 + ((chunk ^ ((row >> 1) & 3)) << 4));
}

__device__ __forceinline__ void split_store(bf* __restrict__ ph, bf* __restrict__ pm,
                                            size_t off, float v0, float v1) {
    bf h0 = __float2bfloat16(v0), h1 = __float2bfloat16(v1);
    bf m0 = __float2bfloat16(v0 - __bfloat162float(h0));
    bf m1 = __float2bfloat16(v1 - __bfloat162float(h1));
    __nv_bfloat162 hh; hh.x = h0; hh.y = h1;
    __nv_bfloat162 mm; mm.x = m0; mm.y = m1;
    *reinterpret_cast<__nv_bfloat162*>(ph + off) = hh;
    *reinterpret_cast<__nv_bfloat162*>(pm + off) = mm;
}
__device__ __forceinline__ void split_store_f16(__half* __restrict__ ph, __half* __restrict__ pl,
                                                size_t off, float v0, float v1) {
    __half h0 = __float2half_rn(v0), h1 = __float2half_rn(v1);
    __half l0 = __float2half_rn(v0 - __half2float(h0));
    __half l1 = __float2half_rn(v1 - __half2float(h1));
    __half2 hh; hh.x = h0; hh.y = h1;
    __half2 ll; ll.x = l0; ll.y = l1;
    *reinterpret_cast<__half2*>(ph + off) = hh;
    *reinterpret_cast<__half2*>(pl + off) = ll;
}

// ================= main 3-term bf16 GEMM (MODE 0,1,2; 128x128 tile, K=512) ==
#define OFF_AH 0
#define OFF_AM 8192
#define OFF_BH 16384
#define OFF_BM 24576
#define STAGE_BYTES 32768
#define NSTAGE 3
#define SMEM_MAIN (NSTAGE * STAGE_BYTES)

template <int MODE>
__global__ __launch_bounds__(256, 2) void mma_gemm(float* __restrict__ outp) {
    extern __shared__ __align__(128) char smem[];
    const uint32_t sbase = smem_u32(smem);
    const int tid = threadIdx.x;
    const int wid = tid >> 5, lane = tid & 31;
    const int b = blockIdx.z;
    const int nBase = blockIdx.x * 128;
    const int mBase = blockIdx.y * 128;
    const int wm = (wid >> 2) * 64, wn = (wid & 3) * 32;

    constexpr int NIT = 16;   // K = 512
    const size_t bQK = (size_t)b << 20;
    const size_t bXT = (size_t)b << 19;

    float acc[4][4][4];
#pragma unroll
    for (int i = 0; i < 4; i++)
#pragma unroll
        for (int j = 0; j < 4; j++)
#pragma unroll
            for (int k = 0; k < 4; k++) acc[i][j][k] = 0.f;

    auto issue_stage = [&](int stage, int kt) {
        const bf *pah, *pam, *pbh, *pbm;
        int lda, ldb;
        if (MODE == 0) {
            pah = g_xTh + bXT + (size_t)mBase * 512 + kt; pam = g_xTm + bXT + (size_t)mBase * 512 + kt; lda = 512;
            pbh = g_Wh + (size_t)nBase * 512 + kt;        pbm = g_Wm + (size_t)nBase * 512 + kt;        ldb = 512;
        } else if (MODE == 1) {
            pah = g_Wh + (size_t)(1024 + mBase) * 512 + kt; pam = g_Wm + (size_t)(1024 + mBase) * 512 + kt; lda = 512;
            pbh = g_xTh + bXT + (size_t)nBase * 512 + kt;   pbm = g_xTm + bXT + (size_t)nBase * 512 + kt;   ldb = 512;
        } else {
            pah = g_qkh + bQK + (size_t)mBase * 1024 + kt; pam = g_qkm + bQK + (size_t)mBase * 1024 + kt; lda = 1024;
            pbh = g_qkh + bQK + (size_t)nBase * 1024 + 512 + kt; pbm = g_qkm + bQK + (size_t)nBase * 1024 + 512 + kt; ldb = 1024;
        }
        const uint32_t sb = sbase + stage * STAGE_BYTES;
#pragma unroll
        for (int j = 0; j < 2; j++) {
            const int idx = tid + j * 256;
            const int row = idx >> 2, ch = idx & 3;
            const uint32_t d = sw_off(row, ch);
            const int sa = row * lda + ch * 8;
            const int sb_ = row * ldb + ch * 8;
            cpa16(sb + OFF_AH + d, pah + sa);
            cpa16(sb + OFF_AM + d, pam + sa);
            cpa16(sb + OFF_BH + d, pbh + sb_);
            cpa16(sb + OFF_BM + d, pbm + sb_);
        }
        asm volatile("cp.async.commit_group;");
    };

    auto compute = [&](int stage) {
        const uint32_t base = sbase + stage * STAGE_BYTES;
        const int sel = lane >> 3;
        uint32_t bhf[2][4][2];
#pragma unroll
        for (int k8 = 0; k8 < 2; k8++)
#pragma unroll
            for (int pr = 0; pr < 2; pr++) {
                const int nt = 2 * pr + (sel >> 1);
                const int kb = sel & 1;
                uint32_t r[4];
                ldsm4(r, base + OFF_BH + sw_off(wn + nt * 8 + (lane & 7), k8 * 2 + kb));
                bhf[k8][2 * pr][0] = r[0]; bhf[k8][2 * pr][1] = r[1];
                bhf[k8][2 * pr + 1][0] = r[2]; bhf[k8][2 * pr + 1][1] = r[3];
            }
#pragma unroll
        for (int k8 = 0; k8 < 2; k8++) {
            uint32_t bmf[4][2];
#pragma unroll
            for (int pr = 0; pr < 2; pr++) {
                const int nt = 2 * pr + (sel >> 1);
                const int kb = sel & 1;
                uint32_t r[4];
                ldsm4(r, base + OFF_BM + sw_off(wn + nt * 8 + (lane & 7), k8 * 2 + kb));
                bmf[2 * pr][0] = r[0]; bmf[2 * pr][1] = r[1];
                bmf[2 * pr + 1][0] = r[2]; bmf[2 * pr + 1][1] = r[3];
            }
#pragma unroll
            for (int mt = 0; mt < 4; mt++) {
                const uint32_t aa = base + OFF_AH +
                    sw_off(wm + mt * 16 + (sel & 1) * 8 + (lane & 7), k8 * 2 + (sel >> 1));
                uint32_t ah[4], am[4];
                ldsm4(ah, aa);
                ldsm4(am, aa + (OFF_AM - OFF_AH));
#pragma unroll
                for (int nt = 0; nt < 4; nt++) mma16816(acc[mt][nt], ah, bhf[k8][nt]);
#pragma unroll
                for (int nt = 0; nt < 4; nt++) mma16816(acc[mt][nt], ah, bmf[nt]);
#pragma unroll
                for (int nt = 0; nt < 4; nt++) mma16816(acc[mt][nt], am, bhf[k8][nt]);
            }
        }
    };

    issue_stage(0, 0);
    issue_stage(1, 32);
    for (int it = 0; it < NIT; it++) {
        if (it + 2 < NIT) asm volatile("cp.async.wait_group 1;");
        else              asm volatile("cp.async.wait_group 0;");
        __syncthreads();
        if (it + 2 < NIT) issue_stage((it + 2) % NSTAGE, (it + 2) * 32);
        compute(it % NSTAGE);
    }

    const int lr = lane >> 2, lc = 2 * (lane & 3);
#pragma unroll
    for (int mt = 0; mt < 4; mt++) {
#pragma unroll
        for (int nt = 0; nt < 4; nt++) {
            const int r0 = mBase + wm + mt * 16 + lr;
            const int c0 = nBase + wn + nt * 8 + lc;
            if (MODE == 0) {
                split_store(g_qkh + bQK, g_qkm + bQK, (size_t)r0 * 1024 + c0, acc[mt][nt][0], acc[mt][nt][1]);
                split_store(g_qkh + bQK, g_qkm + bQK, (size_t)(r0 + 8) * 1024 + c0, acc[mt][nt][2], acc[mt][nt][3]);
            } else if (MODE == 1) {
                split_store_f16(g_vh16 + bXT, g_vl16 + bXT, (size_t)r0 * 1024 + c0, acc[mt][nt][0], acc[mt][nt][1]);
                split_store_f16(g_vh16 + bXT, g_vl16 + bXT, (size_t)(r0 + 8) * 1024 + c0, acc[mt][nt][2], acc[mt][nt][3]);
            } else {
                float2 v0; v0.x = acc[mt][nt][0]; v0.y = acc[mt][nt][1];
                float2 v1; v1.x = acc[mt][nt][2]; v1.y = acc[mt][nt][3];
                *reinterpret_cast<float2*>(g_logit + bQK + (size_t)r0 * 1024 + c0) = v0;
                *reinterpret_cast<float2*>(g_logit + bQK + (size_t)(r0 + 8) * 1024 + c0) = v1;
            }
        }
    }
}

// ================= P GEMM: P[b][r][m] = RHW[r][:] . q[m][:]  (64x128 tile) ==
#define P_AH 0
#define P_AM 4096
#define P_BH 8192
#define P_BM 16384
#define P_STAGE 24576
#define SMEM_P (NSTAGE * P_STAGE)

__global__ __launch_bounds__(256, 2) void p_gemm() {
    extern __shared__ __align__(128) char smem[];
    const uint32_t sbase = smem_u32(smem);
    const int tid = threadIdx.x;
    const int wid = tid >> 5, lane = tid & 31;
    const int b = blockIdx.z;
    const int nBase = blockIdx.x * 128;
    const int wm = (wid >> 2) * 32, wn = (wid & 3) * 32;
    const size_t bQK = (size_t)b << 20;

    float acc[2][4][4];
#pragma unroll
    for (int i = 0; i < 2; i++)
#pragma unroll
        for (int j = 0; j < 4; j++)
#pragma unroll
            for (int k = 0; k < 4; k++) acc[i][j][k] = 0.f;

    auto issue_stage = [&](int stage, int kt) {
        const uint32_t sb = sbase + stage * P_STAGE;
        // A: 64 rows x 4 chunks, one AH + one AM per thread
        {
            const int row = tid >> 2, ch = tid & 3;
            const uint32_t d = sw_off(row, ch);
            const int s = row * 512 + kt + ch * 8;
            cpa16(sb + P_AH + d, g_rhwh + s);
            cpa16(sb + P_AM + d, g_rhwm + s);
        }
        // B: q rows (nBase..nBase+127), 128x4 chunks, two per thread
#pragma unroll
        for (int j = 0; j < 2; j++) {
            const int idx = tid + j * 256;
            const int row = idx >> 2, ch = idx & 3;
            const uint32_t d = sw_off(row, ch);
            const size_t s = bQK + (size_t)(nBase + row) * 1024 + kt + ch * 8;
            cpa16(sb + P_BH + d, g_qkh + s);
            cpa16(sb + P_BM + d, g_qkm + s);
        }
        asm volatile("cp.async.commit_group;");
    };

    auto compute = [&](int stage) {
        const uint32_t base = sbase + stage * P_STAGE;
        const int sel = lane >> 3;
#pragma unroll
        for (int k8 = 0; k8 < 2; k8++) {
            uint32_t bhf[4][2], bmf[4][2];
#pragma unroll
            for (int pr = 0; pr < 2; pr++) {
                const int nt = 2 * pr + (sel >> 1);
                const int kb = sel & 1;
                const uint32_t ra = base + P_BH + sw_off(wn + nt * 8 + (lane & 7), k8 * 2 + kb);
                uint32_t r[4];
                ldsm4(r, ra);
                bhf[2 * pr][0] = r[0]; bhf[2 * pr][1] = r[1];
                bhf[2 * pr + 1][0] = r[2]; bhf[2 * pr + 1][1] = r[3];
                ldsm4(r, ra + (P_BM - P_BH));
                bmf[2 * pr][0] = r[0]; bmf[2 * pr][1] = r[1];
                bmf[2 * pr + 1][0] = r[2]; bmf[2 * pr + 1][1] = r[3];
            }
#pragma unroll
            for (int mt = 0; mt < 2; mt++) {
                const uint32_t aa = base + P_AH +
                    sw_off(wm + mt * 16 + (sel & 1) * 8 + (lane & 7), k8 * 2 + (sel >> 1));
                uint32_t ah[4], am[4];
                ldsm4(ah, aa);
                ldsm4(am, aa + (P_AM - P_AH));
#pragma unroll
                for (int nt = 0; nt < 4; nt++) mma16816(acc[mt][nt], ah, bhf[nt]);
#pragma unroll
                for (int nt = 0; nt < 4; nt++) mma16816(acc[mt][nt], ah, bmf[nt]);
#pragma unroll
                for (int nt = 0; nt < 4; nt++) mma16816(acc[mt][nt], am, bhf[nt]);
            }
        }
    };

    issue_stage(0, 0);
    issue_stage(1, 32);
    for (int it = 0; it < 16; it++) {
        if (it + 2 < 16) asm volatile("cp.async.wait_group 1;");
        else             asm volatile("cp.async.wait_group 0;");
        __syncthreads();
        if (it + 2 < 16) issue_stage((it + 2) % NSTAGE, (it + 2) * 32);
        compute(it % NSTAGE);
    }

    const int lr = lane >> 2, lc = 2 * (lane & 3);
    float* P = g_P + (size_t)b * 64 * 1024;
#pragma unroll
    for (int mt = 0; mt < 2; mt++) {
#pragma unroll
        for (int nt = 0; nt < 4; nt++) {
            const int r0 = wm + mt * 16 + lr;
            const int c0 = nBase + wn + nt * 8 + lc;
            float2 v0; v0.x = acc[mt][nt][0]; v0.y = acc[mt][nt][1];
            float2 v1; v1.x = acc[mt][nt][2]; v1.y = acc[mt][nt][3];
            *reinterpret_cast<float2*>(P + (size_t)r0 * 1024 + c0) = v0;
            *reinterpret_cast<float2*>(P + (size_t)(r0 + 8) * 1024 + c0) = v1;
        }
    }
}

// ================= out GEMM: fp16 2-term (128x128 tile, K=1024) =============
#define O_AH 0
#define O_AL 8192
#define O_B  16384
#define O_STAGE 24576
#define SMEM_O (NSTAGE * O_STAGE)

__global__ __launch_bounds__(256, 2) void out_gemm(float* __restrict__ outp) {
    extern __shared__ __align__(128) char smem[];
    const uint32_t sbase = smem_u32(smem);
    const int tid = threadIdx.x;
    const int wid = tid >> 5, lane = tid & 31;
    const int b = blockIdx.z;
    const int nBase = blockIdx.x * 128;   // output cols n
    const int mBase = blockIdx.y * 128;   // output rows c
    const int wm = (wid >> 2) * 64, wn = (wid & 3) * 32;
    const size_t bQK = (size_t)b << 20;
    const size_t bXT = (size_t)b << 19;

    float acc[4][4][4];
#pragma unroll
    for (int i = 0; i < 4; i++)
#pragma unroll
        for (int j = 0; j < 4; j++)
#pragma unroll
            for (int k = 0; k < 4; k++) acc[i][j][k] = 0.f;

    auto issue_stage = [&](int stage, int kt) {
        const uint32_t sb = sbase + stage * O_STAGE;
        const __half* pah = g_vh16 + bXT + (size_t)mBase * 1024 + kt;
        const __half* pal = g_vl16 + bXT + (size_t)mBase * 1024 + kt;
        const __half* pb  = g_att16 + bQK + (size_t)nBase * 1024 + kt;
#pragma unroll
        for (int j = 0; j < 2; j++) {
            const int idx = tid + j * 256;
            const int row = idx >> 2, ch = idx & 3;
            const uint32_t d = sw_off(row, ch);
            const int s = row * 1024 + ch * 8;
            cpa16(sb + O_AH + d, pah + s);
            cpa16(sb + O_AL + d, pal + s);
            cpa16(sb + O_B  + d, pb  + s);
        }
        asm volatile("cp.async.commit_group;");
    };

    auto compute = [&](int stage) {
        const uint32_t base = sbase + stage * O_STAGE;
        const int sel = lane >> 3;
        uint32_t bff[2][4][2];
#pragma unroll
        for (int k8 = 0; k8 < 2; k8++)
#pragma unroll
            for (int pr = 0; pr < 2; pr++) {
                const int nt = 2 * pr + (sel >> 1);
                const int kb = sel & 1;
                uint32_t r[4];
                ldsm4(r, base + O_B + sw_off(wn + nt * 8 + (lane & 7), k8 * 2 + kb));
                bff[k8][2 * pr][0] = r[0]; bff[k8][2 * pr][1] = r[1];
                bff[k8][2 * pr + 1][0] = r[2]; bff[k8][2 * pr + 1][1] = r[3];
            }
#pragma unroll
        for (int k8 = 0; k8 < 2; k8++) {
#pragma unroll
            for (int mt = 0; mt < 4; mt++) {
                const uint32_t aa = base + O_AH +
                    sw_off(wm + mt * 16 + (sel & 1) * 8 + (lane & 7), k8 * 2 + (sel >> 1));
                uint32_t ah[4], al[4];
                ldsm4(ah, aa);
                ldsm4(al, aa + (O_AL - O_AH));
#pragma unroll
                for (int nt = 0; nt < 4; nt++) mma16816h(acc[mt][nt], ah, bff[k8][nt]);
#pragma unroll
                for (int nt = 0; nt < 4; nt++) mma16816h(acc[mt][nt], al, bff[k8][nt]);
            }
        }
    };

    issue_stage(0, 0);
    issue_stage(1, 32);
    for (int it = 0; it < 32; it++) {
        if (it + 2 < 32) asm volatile("cp.async.wait_group 1;");
        else             asm volatile("cp.async.wait_group 0;");
        __syncthreads();
        if (it + 2 < 32) issue_stage((it + 2) % NSTAGE, (it + 2) * 32);
        compute(it % NSTAGE);
    }

    const int lr = lane >> 2, lc = 2 * (lane & 3);
    float* of = outp + bXT;
#pragma unroll
    for (int mt = 0; mt < 4; mt++) {
#pragma unroll
        for (int nt = 0; nt < 4; nt++) {
            const int r0 = mBase + wm + mt * 16 + lr;
            const int c0 = nBase + wn + nt * 8 + lc;
            float2 v0; v0.x = acc[mt][nt][0]; v0.y = acc[mt][nt][1];
            float2 v1; v1.x = acc[mt][nt][2]; v1.y = acc[mt][nt][3];
            *reinterpret_cast<float2*>(of + (size_t)r0 * 1024 + c0) = v0;
            *reinterpret_cast<float2*>(of + (size_t)(r0 + 8) * 1024 + c0) = v1;
        }
    }
}

// ---------------- prep kernels ----------------------------------------------
__global__ void prep_w(const float* __restrict__ W) {
    int idx = blockIdx.x * blockDim.x + threadIdx.x;
    if (idx >= 1536 * 512) return;
    float v = W[idx];
    bf h = __float2bfloat16(v);
    g_Wh[idx] = h;
    g_Wm[idx] = __float2bfloat16(v - __bfloat162float(h));
}

__global__ void prep_rhw(const float* __restrict__ rel_h, const float* __restrict__ rel_w) {
    int idx = blockIdx.x * blockDim.x + threadIdx.x;   // over 64*512
    if (idx >= 64 * 512) return;
    int r = idx >> 9, c = idx & 511;
    float v = (r < 32) ? rel_h[c * 32 + r] : rel_w[c * 32 + (r - 32)];
    bf h = __float2bfloat16(v);
    g_rhwh[idx] = h;
    g_rhwm[idx] = __float2bfloat16(v - __bfloat162float(h));
}

__global__ void transpose_kernel(const float* __restrict__ x) {
    __shared__ float t[32][33];
    int b = blockIdx.z;
    int n0 = blockIdx.x * 32, c0 = blockIdx.y * 32;
    const float* src = x + (size_t)b * CDIM * NTOK;
    size_t dbase = (size_t)b * NTOK * CDIM;
    int tx = threadIdx.x, ty = threadIdx.y;
#pragma unroll
    for (int j = 0; j < 32; j += 8)
        t[ty + j][tx] = src[(size_t)(c0 + ty + j) * NTOK + n0 + tx];
    __syncthreads();
#pragma unroll
    for (int j = 0; j < 32; j += 8) {
        float v = t[tx][ty + j];
        size_t off = dbase + (size_t)(n0 + ty + j) * CDIM + c0 + tx;
        bf h = __float2bfloat16(v);
        g_xTh[off] = h;
        g_xTm[off] = __float2bfloat16(v - __bfloat162float(h));
    }
}

// softmax over m with fused pos-bias; writes fp16 att
__global__ __launch_bounds__(256) void softmax_bias() {
    size_t row = blockIdx.x;                 // (b,n)
    int b = (int)(row >> 10);
    int n = (int)(row & 1023);
    int h = n >> 5, w = n & 31;
    const float* p  = g_logit + row * NTOK;
    const float* ph = g_P + ((size_t)b * 64 + h) * 1024;
    const float* pw = g_P + ((size_t)b * 64 + 32 + w) * 1024;
    int tid = threadIdx.x;

    float4 v = *(const float4*)&p[tid * 4];
    float4 bh = *(const float4*)&ph[tid * 4];
    float4 bw = *(const float4*)&pw[tid * 4];
    v.x += bh.x + bw.x; v.y += bh.y + bw.y;
    v.z += bh.z + bw.z; v.w += bh.w + bw.w;

    float m = fmaxf(fmaxf(v.x, v.y), fmaxf(v.z, v.w));
#pragma unroll
    for (int o = 16; o; o >>= 1) m = fmaxf(m, __shfl_xor_sync(~0u, m, o));
    __shared__ float red[8];
    if ((tid & 31) == 0) red[tid >> 5] = m;
    __syncthreads();
    float bm = red[0];
#pragma unroll
    for (int i = 1; i < 8; i++) bm = fmaxf(bm, red[i]);
    __syncthreads();

    v.x = __expf(v.x - bm); v.y = __expf(v.y - bm);
    v.z = __expf(v.z - bm); v.w = __expf(v.w - bm);
    float s = v.x + v.y + v.z + v.w;
#pragma unroll
    for (int o = 16; o; o >>= 1) s += __shfl_xor_sync(~0u, s, o);
    if ((tid & 31) == 0) red[tid >> 5] = s;
    __syncthreads();
    float bs = 0.f;
#pragma unroll
    for (int i = 0; i < 8; i++) bs += red[i];
    float inv = 1.0f / bs;

    __half2 a0; a0.x = __float2half_rn(v.x * inv); a0.y = __float2half_rn(v.y * inv);
    __half2 a1; a1.x = __float2half_rn(v.z * inv); a1.y = __float2half_rn(v.w * inv);
    size_t off = row * NTOK + tid * 4;
    *reinterpret_cast<__half2*>(g_att16 + off) = a0;
    *reinterpret_cast<__half2*>(g_att16 + off + 2) = a1;
}

// ---------------------------------------------------------------------------
extern "C" void kernel_launch(void* const* d_in, const int* in_sizes, int n_in,
                              void* d_out, int out_size) {
    const float* x     = (const float*)d_in[0];
    const float* Wmat  = (const float*)d_in[1];
    const float* rel_h = (const float*)d_in[2];
    const float* rel_w = (const float*)d_in[3];
    float* out = (float*)d_out;

    cudaFuncSetAttribute(mma_gemm<0>, cudaFuncAttributeMaxDynamicSharedMemorySize, SMEM_MAIN);
    cudaFuncSetAttribute(mma_gemm<1>, cudaFuncAttributeMaxDynamicSharedMemorySize, SMEM_MAIN);
    cudaFuncSetAttribute(mma_gemm<2>, cudaFuncAttributeMaxDynamicSharedMemorySize, SMEM_MAIN);
    cudaFuncSetAttribute(p_gemm,      cudaFuncAttributeMaxDynamicSharedMemorySize, SMEM_P);
    cudaFuncSetAttribute(out_gemm,    cudaFuncAttributeMaxDynamicSharedMemorySize, SMEM_O);

    prep_w<<<(1536 * 512 + 255) / 256, 256>>>(Wmat);
    prep_rhw<<<(64 * 512 + 255) / 256, 256>>>(rel_h, rel_w);
    transpose_kernel<<<dim3(32, 16, 64), dim3(32, 8)>>>(x);

    mma_gemm<0><<<dim3(8, 8, 64), 256, SMEM_MAIN>>>(nullptr);   // qkT (bf16 hi/mid)
    mma_gemm<1><<<dim3(8, 4, 64), 256, SMEM_MAIN>>>(nullptr);   // v (fp16 hi/lo)
    mma_gemm<2><<<dim3(8, 8, 64), 256, SMEM_MAIN>>>(nullptr);   // logits = q.k (fp32)
    p_gemm<<<dim3(8, 1, 64), 256, SMEM_P>>>();                  // P = [rh;rw]^T q
    softmax_bias<<<BATCH * NTOK, 256>>>();                      // att fp16
    out_gemm<<<dim3(8, 4, 64), 256, SMEM_O>>>(out);             // out fp32
}

// round 6
// speedup vs baseline: 4.3867x; 1.1598x over previous
#include <cuda_runtime.h>
#include <cuda_bf16.h>
#include <cuda_fp16.h>
#include <cstdint>

#define BATCH 64
#define CDIM  512
#define NTOK  1024

typedef __nv_bfloat16 bf;

// ---------------- scratch (device globals) ----------------------------------
__device__ float g_WT [(size_t)512 * 1536];            // [c][o] = W[o][c]
__device__ float g_rhw[(size_t)64 * 512];              // [r][o] fp32
__device__ bf g_Mh[(size_t)512 * 512];                 // M = Wq^T Wk, bf16 hi
__device__ bf g_Mm[(size_t)512 * 512];
__device__ bf g_Gh[(size_t)64 * 512];                  // G = RHW * Wq
__device__ bf g_Gm[(size_t)64 * 512];
__device__ bf g_xTh[(size_t)BATCH * NTOK * CDIM];      // [b][n][c]
__device__ bf g_xTm[(size_t)BATCH * NTOK * CDIM];
__device__ __half g_xT16[(size_t)BATCH * NTOK * CDIM];
__device__ __half g_W16h[(size_t)512 * 512];           // Wv fp16 hi  [cv][c]
__device__ __half g_W16l[(size_t)512 * 512];
__device__ bf g_Th[(size_t)BATCH * NTOK * 512];        // T^T [b][m][c1]
__device__ bf g_Tm[(size_t)BATCH * NTOK * 512];
__device__ float  g_logit[(size_t)BATCH * NTOK * NTOK];
__device__ float  g_P[(size_t)BATCH * 64 * NTOK];
__device__ __half g_vh16[(size_t)BATCH * CDIM * NTOK]; // [b][c][n]
__device__ __half g_vl16[(size_t)BATCH * CDIM * NTOK];
__device__ __half g_att16[(size_t)BATCH * NTOK * NTOK];

// ---------------- PTX helpers ----------------------------------------------
__device__ __forceinline__ uint32_t smem_u32(const void* p) {
    uint32_t a;
    asm("{ .reg .u64 t; cvta.to.shared.u64 t, %1; cvt.u32.u64 %0, t; }" : "=r"(a) : "l"(p));
    return a;
}
__device__ __forceinline__ void cpa16(uint32_t dst, const void* src) {
    asm volatile("cp.async.cg.shared.global [%0], [%1], 16;" :: "r"(dst), "l"(src));
}
__device__ __forceinline__ void ldsm4(uint32_t r[4], uint32_t addr) {
    asm volatile("ldmatrix.sync.aligned.m8n8.x4.shared.b16 {%0,%1,%2,%3}, [%4];"
                 : "=r"(r[0]), "=r"(r[1]), "=r"(r[2]), "=r"(r[3]) : "r"(addr));
}
__device__ __forceinline__ void mma16816(float c[4], const uint32_t a[4], const uint32_t b[2]) {
    asm volatile("mma.sync.aligned.m16n8k16.row.col.f32.bf16.bf16.f32 "
                 "{%0,%1,%2,%3}, {%4,%5,%6,%7}, {%8,%9}, {%0,%1,%2,%3};"
                 : "+f"(c[0]), "+f"(c[1]), "+f"(c[2]), "+f"(c[3])
                 : "r"(a[0]), "r"(a[1]), "r"(a[2]), "r"(a[3]), "r"(b[0]), "r"(b[1]));
}
__device__ __forceinline__ void mma16816h(float c[4], const uint32_t a[4], const uint32_t b[2]) {
    asm volatile("mma.sync.aligned.m16n8k16.row.col.f32.f16.f16.f32 "
                 "{%0,%1,%2,%3}, {%4,%5,%6,%7}, {%8,%9}, {%0,%1,%2,%3};"
                 : "+f"(c[0]), "+f"(c[1]), "+f"(c[2]), "+f"(c[3])
                 : "r"(a[0]), "r"(a[1]), "r"(a[2]), "r"(a[3]), "r"(b[0]), "r"(b[1]));
}
__device__ __forceinline__ uint32_t sw_off(int row, int chunk) {
    return (uint32_t)(row * 64 + ((chunk ^ ((row >> 1) & 3)) << 4));
}
__device__ __forceinline__ void split_store(bf* __restrict__ ph, bf* __restrict__ pm,
                                            size_t off, float v0, float v1) {
    bf h0 = __float2bfloat16(v0), h1 = __float2bfloat16(v1);
    bf m0 = __float2bfloat16(v0 - __bfloat162float(h0));
    bf m1 = __float2bfloat16(v1 - __bfloat162float(h1));
    __nv_bfloat162 hh; hh.x = h0; hh.y = h1;
    __nv_bfloat162 mm; mm.x = m0; mm.y = m1;
    *reinterpret_cast<__nv_bfloat162*>(ph + off) = hh;
    *reinterpret_cast<__nv_bfloat162*>(pm + off) = mm;
}
__device__ __forceinline__ void split_store_f16(__half* __restrict__ ph, __half* __restrict__ pl,
                                                size_t off, float v0, float v1) {
    __half h0 = __float2half_rn(v0), h1 = __float2half_rn(v1);
    __half l0 = __float2half_rn(v0 - __half2float(h0));
    __half l1 = __float2half_rn(v1 - __half2float(h1));
    __half2 hh; hh.x = h0; hh.y = h1;
    __half2 ll; ll.x = l0; ll.y = l1;
    *reinterpret_cast<__half2*>(ph + off) = hh;
    *reinterpret_cast<__half2*>(pl + off) = ll;
}

// ================= 3-term bf16 GEMM (128x128 tile, K=512) ===================
// MODE 0: T^T[b][m][c1] = sum_c2 xT[m][c2] * M[c1][c2]
// MODE 1: logit[b][n][m] = sum_c1 xT[n][c1] * T^T[m][c1]
#define OFF_AH 0
#define OFF_AM 8192
#define OFF_BH 16384
#define OFF_BM 24576
#define STAGE_BYTES 32768
#define NSTAGE 3
#define SMEM_MAIN (NSTAGE * STAGE_BYTES)

template <int MODE>
__global__ __launch_bounds__(256, 2) void gemm3() {
    extern __shared__ __align__(128) char smem[];
    const uint32_t sbase = smem_u32(smem);
    const int tid = threadIdx.x;
    const int wid = tid >> 5, lane = tid & 31;
    const int b = blockIdx.z;
    const int nBase = blockIdx.x * 128;
    const int mBase = blockIdx.y * 128;
    const int wm = (wid >> 2) * 64, wn = (wid & 3) * 32;

    constexpr int NIT = 16;
    const size_t bXT = (size_t)b << 19;     // b*1024*512 (xT and T batch stride)
    const size_t bQK = (size_t)b << 20;

    float acc[4][4][4];
#pragma unroll
    for (int i = 0; i < 4; i++)
#pragma unroll
        for (int j = 0; j < 4; j++)
#pragma unroll
            for (int k = 0; k < 4; k++) acc[i][j][k] = 0.f;

    auto issue_stage = [&](int stage, int kt) {
        const bf *pah, *pam, *pbh, *pbm;
        pah = g_xTh + bXT + (size_t)mBase * 512 + kt;
        pam = g_xTm + bXT + (size_t)mBase * 512 + kt;
        if (MODE == 0) {
            pbh = g_Mh + (size_t)nBase * 512 + kt;
            pbm = g_Mm + (size_t)nBase * 512 + kt;
        } else {
            pbh = g_Th + bXT + (size_t)nBase * 512 + kt;
            pbm = g_Tm + bXT + (size_t)nBase * 512 + kt;
        }
        const uint32_t sb = sbase + stage * STAGE_BYTES;
#pragma unroll
        for (int j = 0; j < 2; j++) {
            const int idx = tid + j * 256;
            const int row = idx >> 2, ch = idx & 3;
            const uint32_t d = sw_off(row, ch);
            const int s = row * 512 + ch * 8;
            cpa16(sb + OFF_AH + d, pah + s);
            cpa16(sb + OFF_AM + d, pam + s);
            cpa16(sb + OFF_BH + d, pbh + s);
            cpa16(sb + OFF_BM + d, pbm + s);
        }
        asm volatile("cp.async.commit_group;");
    };

    auto compute = [&](int stage) {
        const uint32_t base = sbase + stage * STAGE_BYTES;
        const int sel = lane >> 3;
        uint32_t bhf[2][4][2];
#pragma unroll
        for (int k8 = 0; k8 < 2; k8++)
#pragma unroll
            for (int pr = 0; pr < 2; pr++) {
                const int nt = 2 * pr + (sel >> 1);
                const int kb = sel & 1;
                uint32_t r[4];
                ldsm4(r, base + OFF_BH + sw_off(wn + nt * 8 + (lane & 7), k8 * 2 + kb));
                bhf[k8][2 * pr][0] = r[0]; bhf[k8][2 * pr][1] = r[1];
                bhf[k8][2 * pr + 1][0] = r[2]; bhf[k8][2 * pr + 1][1] = r[3];
            }
#pragma unroll
        for (int k8 = 0; k8 < 2; k8++) {
            uint32_t bmf[4][2];
#pragma unroll
            for (int pr = 0; pr < 2; pr++) {
                const int nt = 2 * pr + (sel >> 1);
                const int kb = sel & 1;
                uint32_t r[4];
                ldsm4(r, base + OFF_BM + sw_off(wn + nt * 8 + (lane & 7), k8 * 2 + kb));
                bmf[2 * pr][0] = r[0]; bmf[2 * pr][1] = r[1];
                bmf[2 * pr + 1][0] = r[2]; bmf[2 * pr + 1][1] = r[3];
            }
#pragma unroll
            for (int mt = 0; mt < 4; mt++) {
                const uint32_t aa = base + OFF_AH +
                    sw_off(wm + mt * 16 + (sel & 1) * 8 + (lane & 7), k8 * 2 + (sel >> 1));
                uint32_t ah[4], am[4];
                ldsm4(ah, aa);
                ldsm4(am, aa + (OFF_AM - OFF_AH));
#pragma unroll
                for (int nt = 0; nt < 4; nt++) mma16816(acc[mt][nt], ah, bhf[k8][nt]);
#pragma unroll
                for (int nt = 0; nt < 4; nt++) mma16816(acc[mt][nt], ah, bmf[nt]);
#pragma unroll
                for (int nt = 0; nt < 4; nt++) mma16816(acc[mt][nt], am, bhf[k8][nt]);
            }
        }
    };

    issue_stage(0, 0);
    issue_stage(1, 32);
    for (int it = 0; it < NIT; it++) {
        if (it + 2 < NIT) asm volatile("cp.async.wait_group 1;");
        else              asm volatile("cp.async.wait_group 0;");
        __syncthreads();
        if (it + 2 < NIT) issue_stage((it + 2) % NSTAGE, (it + 2) * 32);
        compute(it % NSTAGE);
    }

    const int lr = lane >> 2, lc = 2 * (lane & 3);
#pragma unroll
    for (int mt = 0; mt < 4; mt++) {
#pragma unroll
        for (int nt = 0; nt < 4; nt++) {
            const int r0 = mBase + wm + mt * 16 + lr;
            const int c0 = nBase + wn + nt * 8 + lc;
            if (MODE == 0) {
                split_store(g_Th + bXT, g_Tm + bXT, (size_t)r0 * 512 + c0, acc[mt][nt][0], acc[mt][nt][1]);
                split_store(g_Th + bXT, g_Tm + bXT, (size_t)(r0 + 8) * 512 + c0, acc[mt][nt][2], acc[mt][nt][3]);
            } else {
                float2 v0; v0.x = acc[mt][nt][0]; v0.y = acc[mt][nt][1];
                float2 v1; v1.x = acc[mt][nt][2]; v1.y = acc[mt][nt][3];
                *reinterpret_cast<float2*>(g_logit + bQK + (size_t)r0 * 1024 + c0) = v0;
                *reinterpret_cast<float2*>(g_logit + bQK + (size_t)(r0 + 8) * 1024 + c0) = v1;
            }
        }
    }
}

// ================= P GEMM: P[b][r][m] = G[r][:] . xT[m][:]  (64x128 tile) ===
#define P_AH 0
#define P_AM 4096
#define P_BH 8192
#define P_BM 16384
#define P_STAGE 24576
#define SMEM_P (NSTAGE * P_STAGE)

__global__ __launch_bounds__(256, 2) void p_gemm() {
    extern __shared__ __align__(128) char smem[];
    const uint32_t sbase = smem_u32(smem);
    const int tid = threadIdx.x;
    const int wid = tid >> 5, lane = tid & 31;
    const int b = blockIdx.z;
    const int nBase = blockIdx.x * 128;
    const int wm = (wid >> 2) * 32, wn = (wid & 3) * 32;
    const size_t bXT = (size_t)b << 19;

    float acc[2][4][4];
#pragma unroll
    for (int i = 0; i < 2; i++)
#pragma unroll
        for (int j = 0; j < 4; j++)
#pragma unroll
            for (int k = 0; k < 4; k++) acc[i][j][k] = 0.f;

    auto issue_stage = [&](int stage, int kt) {
        const uint32_t sb = sbase + stage * P_STAGE;
        {
            const int row = tid >> 2, ch = tid & 3;
            const uint32_t d = sw_off(row, ch);
            const int s = row * 512 + kt + ch * 8;
            cpa16(sb + P_AH + d, g_Gh + s);
            cpa16(sb + P_AM + d, g_Gm + s);
        }
#pragma unroll
        for (int j = 0; j < 2; j++) {
            const int idx = tid + j * 256;
            const int row = idx >> 2, ch = idx & 3;
            const uint32_t d = sw_off(row, ch);
            const size_t s = bXT + (size_t)(nBase + row) * 512 + kt + ch * 8;
            cpa16(sb + P_BH + d, g_xTh + s);
            cpa16(sb + P_BM + d, g_xTm + s);
        }
        asm volatile("cp.async.commit_group;");
    };

    auto compute = [&](int stage) {
        const uint32_t base = sbase + stage * P_STAGE;
        const int sel = lane >> 3;
#pragma unroll
        for (int k8 = 0; k8 < 2; k8++) {
            uint32_t bhf[4][2], bmf[4][2];
#pragma unroll
            for (int pr = 0; pr < 2; pr++) {
                const int nt = 2 * pr + (sel >> 1);
                const int kb = sel & 1;
                const uint32_t ra = base + P_BH + sw_off(wn + nt * 8 + (lane & 7), k8 * 2 + kb);
                uint32_t r[4];
                ldsm4(r, ra);
                bhf[2 * pr][0] = r[0]; bhf[2 * pr][1] = r[1];
                bhf[2 * pr + 1][0] = r[2]; bhf[2 * pr + 1][1] = r[3];
                ldsm4(r, ra + (P_BM - P_BH));
                bmf[2 * pr][0] = r[0]; bmf[2 * pr][1] = r[1];
                bmf[2 * pr + 1][0] = r[2]; bmf[2 * pr + 1][1] = r[3];
            }
#pragma unroll
            for (int mt = 0; mt < 2; mt++) {
                const uint32_t aa = base + P_AH +
                    sw_off(wm + mt * 16 + (sel & 1) * 8 + (lane & 7), k8 * 2 + (sel >> 1));
                uint32_t ah[4], am[4];
                ldsm4(ah, aa);
                ldsm4(am, aa + (P_AM - P_AH));
#pragma unroll
                for (int nt = 0; nt < 4; nt++) mma16816(acc[mt][nt], ah, bhf[nt]);
#pragma unroll
                for (int nt = 0; nt < 4; nt++) mma16816(acc[mt][nt], ah, bmf[nt]);
#pragma unroll
                for (int nt = 0; nt < 4; nt++) mma16816(acc[mt][nt], am, bhf[nt]);
            }
        }
    };

    issue_stage(0, 0);
    issue_stage(1, 32);
    for (int it = 0; it < 16; it++) {
        if (it + 2 < 16) asm volatile("cp.async.wait_group 1;");
        else             asm volatile("cp.async.wait_group 0;");
        __syncthreads();
        if (it + 2 < 16) issue_stage((it + 2) % NSTAGE, (it + 2) * 32);
        compute(it % NSTAGE);
    }

    const int lr = lane >> 2, lc = 2 * (lane & 3);
    float* P = g_P + (size_t)b * 64 * 1024;
#pragma unroll
    for (int mt = 0; mt < 2; mt++) {
#pragma unroll
        for (int nt = 0; nt < 4; nt++) {
            const int r0 = wm + mt * 16 + lr;
            const int c0 = nBase + wn + nt * 8 + lc;
            float2 v0; v0.x = acc[mt][nt][0]; v0.y = acc[mt][nt][1];
            float2 v1; v1.x = acc[mt][nt][2]; v1.y = acc[mt][nt][3];
            *reinterpret_cast<float2*>(P + (size_t)r0 * 1024 + c0) = v0;
            *reinterpret_cast<float2*>(P + (size_t)(r0 + 8) * 1024 + c0) = v1;
        }
    }
}

// ======= fp16 2-term GEMM: A(hi/lo) x B  (128x128 tile) =====================
// MODE 0: v[b][c][n]  = (W16h+W16l)[c][:] . xT16[n][:]      K=512
// MODE 1: out[b][c][n]= (vh+vl)[c][:] . att16[n][:]          K=1024
#define O_AH 0
#define O_AL 8192
#define O_B  16384
#define O_STAGE 24576
#define SMEM_O (NSTAGE * O_STAGE)

template <int MODE>
__global__ __launch_bounds__(256, 2) void a2b1(float* __restrict__ outp) {
    extern __shared__ __align__(128) char smem[];
    const uint32_t sbase = smem_u32(smem);
    const int tid = threadIdx.x;
    const int wid = tid >> 5, lane = tid & 31;
    const int b = blockIdx.z;
    const int nBase = blockIdx.x * 128;
    const int mBase = blockIdx.y * 128;
    const int wm = (wid >> 2) * 64, wn = (wid & 3) * 32;
    const size_t bQK = (size_t)b << 20;
    const size_t bXT = (size_t)b << 19;

    constexpr int NIT = (MODE == 0) ? 16 : 32;
    constexpr int LD  = (MODE == 0) ? 512 : 1024;

    float acc[4][4][4];
#pragma unroll
    for (int i = 0; i < 4; i++)
#pragma unroll
        for (int j = 0; j < 4; j++)
#pragma unroll
            for (int k = 0; k < 4; k++) acc[i][j][k] = 0.f;

    auto issue_stage = [&](int stage, int kt) {
        const __half *pah, *pal, *pb;
        if (MODE == 0) {
            pah = g_W16h + (size_t)mBase * 512 + kt;
            pal = g_W16l + (size_t)mBase * 512 + kt;
            pb  = g_xT16 + bXT + (size_t)nBase * 512 + kt;
        } else {
            pah = g_vh16 + bXT + (size_t)mBase * 1024 + kt;
            pal = g_vl16 + bXT + (size_t)mBase * 1024 + kt;
            pb  = g_att16 + bQK + (size_t)nBase * 1024 + kt;
        }
        const uint32_t sb = sbase + stage * O_STAGE;
#pragma unroll
        for (int j = 0; j < 2; j++) {
            const int idx = tid + j * 256;
            const int row = idx >> 2, ch = idx & 3;
            const uint32_t d = sw_off(row, ch);
            const int s = row * LD + ch * 8;
            cpa16(sb + O_AH + d, pah + s);
            cpa16(sb + O_AL + d, pal + s);
            cpa16(sb + O_B  + d, pb  + s);
        }
        asm volatile("cp.async.commit_group;");
    };

    auto compute = [&](int stage) {
        const uint32_t base = sbase + stage * O_STAGE;
        const int sel = lane >> 3;
        uint32_t bff[2][4][2];
#pragma unroll
        for (int k8 = 0; k8 < 2; k8++)
#pragma unroll
            for (int pr = 0; pr < 2; pr++) {
                const int nt = 2 * pr + (sel >> 1);
                const int kb = sel & 1;
                uint32_t r[4];
                ldsm4(r, base + O_B + sw_off(wn + nt * 8 + (lane & 7), k8 * 2 + kb));
                bff[k8][2 * pr][0] = r[0]; bff[k8][2 * pr][1] = r[1];
                bff[k8][2 * pr + 1][0] = r[2]; bff[k8][2 * pr + 1][1] = r[3];
            }
#pragma unroll
        for (int k8 = 0; k8 < 2; k8++) {
#pragma unroll
            for (int mt = 0; mt < 4; mt++) {
                const uint32_t aa = base + O_AH +
                    sw_off(wm + mt * 16 + (sel & 1) * 8 + (lane & 7), k8 * 2 + (sel >> 1));
                uint32_t ah[4], al[4];
                ldsm4(ah, aa);
                ldsm4(al, aa + (O_AL - O_AH));
#pragma unroll
                for (int nt = 0; nt < 4; nt++) mma16816h(acc[mt][nt], ah, bff[k8][nt]);
#pragma unroll
                for (int nt = 0; nt < 4; nt++) mma16816h(acc[mt][nt], al, bff[k8][nt]);
            }
        }
    };

    issue_stage(0, 0);
    issue_stage(1, 32);
    for (int it = 0; it < NIT; it++) {
        if (it + 2 < NIT) asm volatile("cp.async.wait_group 1;");
        else              asm volatile("cp.async.wait_group 0;");
        __syncthreads();
        if (it + 2 < NIT) issue_stage((it + 2) % NSTAGE, (it + 2) * 32);
        compute(it % NSTAGE);
    }

    const int lr = lane >> 2, lc = 2 * (lane & 3);
#pragma unroll
    for (int mt = 0; mt < 4; mt++) {
#pragma unroll
        for (int nt = 0; nt < 4; nt++) {
            const int r0 = mBase + wm + mt * 16 + lr;
            const int c0 = nBase + wn + nt * 8 + lc;
            if (MODE == 0) {
                split_store_f16(g_vh16 + bXT, g_vl16 + bXT, (size_t)r0 * 1024 + c0, acc[mt][nt][0], acc[mt][nt][1]);
                split_store_f16(g_vh16 + bXT, g_vl16 + bXT, (size_t)(r0 + 8) * 1024 + c0, acc[mt][nt][2], acc[mt][nt][3]);
            } else {
                float* of = outp + bXT;
                float2 v0; v0.x = acc[mt][nt][0]; v0.y = acc[mt][nt][1];
                float2 v1; v1.x = acc[mt][nt][2]; v1.y = acc[mt][nt][3];
                *reinterpret_cast<float2*>(of + (size_t)r0 * 1024 + c0) = v0;
                *reinterpret_cast<float2*>(of + (size_t)(r0 + 8) * 1024 + c0) = v1;
            }
        }
    }
}

// ---------------- small fp32 GEMM for M and G precompute --------------------
// C[row][col] = sum_k A[row][k] * B[col][k], K=512; split-stored as bf16.
template <int IS_G>
__global__ __launch_bounds__(256) void sgemm_split() {
    const float* A = IS_G ? g_rhw : g_WT;
    const int lda = IS_G ? 512 : 1536;
    const float* B = IS_G ? g_WT : (g_WT + 512);
    const int ldb = 1536;
    bf* Ch = IS_G ? g_Gh : g_Mh;
    bf* Cm = IS_G ? g_Gm : g_Mm;

    __shared__ float As[16][72];
    __shared__ float Bs[16][72];
    const int tid = threadIdx.x;
    const int tx = tid & 15, ty = tid >> 4;
    const int rBase = blockIdx.y * 64, cBase = blockIdx.x * 64;

    float acc[4][4];
#pragma unroll
    for (int i = 0; i < 4; i++)
#pragma unroll
        for (int j = 0; j < 4; j++) acc[i][j] = 0.f;

    for (int kt = 0; kt < 512; kt += 16) {
        const int row = tid >> 2, q = (tid & 3) * 4;
        float4 va = *(const float4*)&A[(size_t)(rBase + row) * lda + kt + q];
        As[q + 0][row] = va.x; As[q + 1][row] = va.y;
        As[q + 2][row] = va.z; As[q + 3][row] = va.w;
        float4 vb = *(const float4*)&B[(size_t)(cBase + row) * ldb + kt + q];
        Bs[q + 0][row] = vb.x; Bs[q + 1][row] = vb.y;
        Bs[q + 2][row] = vb.z; Bs[q + 3][row] = vb.w;
        __syncthreads();
#pragma unroll
        for (int k = 0; k < 16; k++) {
            float a[4], bb[4];
            *(float4*)&a[0]  = *(const float4*)&As[k][ty * 4];
            *(float4*)&bb[0] = *(const float4*)&Bs[k][tx * 4];
#pragma unroll
            for (int i = 0; i < 4; i++)
#pragma unroll
                for (int j = 0; j < 4; j++) acc[i][j] += a[i] * bb[j];
        }
        __syncthreads();
    }
#pragma unroll
    for (int i = 0; i < 4; i++) {
        const int row = rBase + ty * 4 + i;
        const int col = cBase + tx * 4;
        split_store(Ch, Cm, (size_t)row * 512 + col, acc[i][0], acc[i][1]);
        split_store(Ch, Cm, (size_t)row * 512 + col + 2, acc[i][2], acc[i][3]);
    }
}

// ---------------- prep kernels ----------------------------------------------
__global__ void transpose_w(const float* __restrict__ W) {
    __shared__ float t[32][33];
    int o0 = blockIdx.x * 32, c0 = blockIdx.y * 32;
    int tx = threadIdx.x, ty = threadIdx.y;
#pragma unroll
    for (int j = 0; j < 32; j += 8)
        t[ty + j][tx] = W[(size_t)(o0 + ty + j) * 512 + c0 + tx];
    __syncthreads();
#pragma unroll
    for (int j = 0; j < 32; j += 8)
        g_WT[(size_t)(c0 + ty + j) * 1536 + o0 + tx] = t[tx][ty + j];
}

__global__ void prep_rhw(const float* __restrict__ rel_h, const float* __restrict__ rel_w) {
    int idx = blockIdx.x * blockDim.x + threadIdx.x;
    if (idx >= 64 * 512) return;
    int r = idx >> 9, c = idx & 511;
    g_rhw[idx] = (r < 32) ? rel_h[c * 32 + r] : rel_w[c * 32 + (r - 32)];
}

__global__ void prep_w16(const float* __restrict__ W) {
    int idx = blockIdx.x * blockDim.x + threadIdx.x;
    if (idx >= 512 * 512) return;
    int cv = idx >> 9, c = idx & 511;
    float v = W[(size_t)(1024 + cv) * 512 + c];
    __half h = __float2half_rn(v);
    g_W16h[idx] = h;
    g_W16l[idx] = __float2half_rn(v - __half2float(h));
}

__global__ void transpose_x(const float* __restrict__ x) {
    __shared__ float t[32][33];
    int b = blockIdx.z;
    int n0 = blockIdx.x * 32, c0 = blockIdx.y * 32;
    const float* src = x + (size_t)b * CDIM * NTOK;
    size_t dbase = (size_t)b * NTOK * CDIM;
    int tx = threadIdx.x, ty = threadIdx.y;
#pragma unroll
    for (int j = 0; j < 32; j += 8)
        t[ty + j][tx] = src[(size_t)(c0 + ty + j) * NTOK + n0 + tx];
    __syncthreads();
#pragma unroll
    for (int j = 0; j < 32; j += 8) {
        float v = t[tx][ty + j];
        size_t off = dbase + (size_t)(n0 + ty + j) * CDIM + c0 + tx;
        bf h = __float2bfloat16(v);
        g_xTh[off] = h;
        g_xTm[off] = __float2bfloat16(v - __bfloat162float(h));
        g_xT16[off] = __float2half_rn(v);
    }
}

// softmax over m with fused pos-bias; writes fp16 att
__global__ __launch_bounds__(256) void softmax_bias() {
    size_t row = blockIdx.x;
    int b = (int)(row >> 10);
    int n = (int)(row & 1023);
    int h = n >> 5, w = n & 31;
    const float* p  = g_logit + row * NTOK;
    const float* ph = g_P + ((size_t)b * 64 + h) * 1024;
    const float* pw = g_P + ((size_t)b * 64 + 32 + w) * 1024;
    int tid = threadIdx.x;

    float4 v = *(const float4*)&p[tid * 4];
    float4 bh = *(const float4*)&ph[tid * 4];
    float4 bw = *(const float4*)&pw[tid * 4];
    v.x += bh.x + bw.x; v.y += bh.y + bw.y;
    v.z += bh.z + bw.z; v.w += bh.w + bw.w;

    float m = fmaxf(fmaxf(v.x, v.y), fmaxf(v.z, v.w));
#pragma unroll
    for (int o = 16; o; o >>= 1) m = fmaxf(m, __shfl_xor_sync(~0u, m, o));
    __shared__ float red[8];
    if ((tid & 31) == 0) red[tid >> 5] = m;
    __syncthreads();
    float bm = red[0];
#pragma unroll
    for (int i = 1; i < 8; i++) bm = fmaxf(bm, red[i]);
    __syncthreads();

    v.x = __expf(v.x - bm); v.y = __expf(v.y - bm);
    v.z = __expf(v.z - bm); v.w = __expf(v.w - bm);
    float s = v.x + v.y + v.z + v.w;
#pragma unroll
    for (int o = 16; o; o >>= 1) s += __shfl_xor_sync(~0u, s, o);
    if ((tid & 31) == 0) red[tid >> 5] = s;
    __syncthreads();
    float bs = 0.f;
#pragma unroll
    for (int i = 0; i < 8; i++) bs += red[i];
    float inv = 1.0f / bs;

    __half2 a0; a0.x = __float2half_rn(v.x * inv); a0.y = __float2half_rn(v.y * inv);
    __half2 a1; a1.x = __float2half_rn(v.z * inv); a1.y = __float2half_rn(v.w * inv);
    size_t off = row * NTOK + tid * 4;
    *reinterpret_cast<__half2*>(g_att16 + off) = a0;
    *reinterpret_cast<__half2*>(g_att16 + off + 2) = a1;
}

// ---------------------------------------------------------------------------
extern "C" void kernel_launch(void* const* d_in, const int* in_sizes, int n_in,
                              void* d_out, int out_size) {
    const float* x     = (const float*)d_in[0];
    const float* Wmat  = (const float*)d_in[1];
    const float* rel_h = (const float*)d_in[2];
    const float* rel_w = (const float*)d_in[3];
    float* out = (float*)d_out;

    cudaFuncSetAttribute(gemm3<0>, cudaFuncAttributeMaxDynamicSharedMemorySize, SMEM_MAIN);
    cudaFuncSetAttribute(gemm3<1>, cudaFuncAttributeMaxDynamicSharedMemorySize, SMEM_MAIN);
    cudaFuncSetAttribute(p_gemm,   cudaFuncAttributeMaxDynamicSharedMemorySize, SMEM_P);
    cudaFuncSetAttribute(a2b1<0>,  cudaFuncAttributeMaxDynamicSharedMemorySize, SMEM_O);
    cudaFuncSetAttribute(a2b1<1>,  cudaFuncAttributeMaxDynamicSharedMemorySize, SMEM_O);

    transpose_w<<<dim3(48, 16), dim3(32, 8)>>>(Wmat);
    prep_rhw<<<(64 * 512 + 255) / 256, 256>>>(rel_h, rel_w);
    prep_w16<<<(512 * 512 + 255) / 256, 256>>>(Wmat);
    transpose_x<<<dim3(32, 16, 64), dim3(32, 8)>>>(x);

    sgemm_split<0><<<dim3(8, 8), 256>>>();     // M = Wq^T Wk
    sgemm_split<1><<<dim3(8, 1), 256>>>();     // G = RHW * Wq

    gemm3<0><<<dim3(4, 8, 64), 256, SMEM_MAIN>>>();   // T^T = xT . M
    gemm3<1><<<dim3(8, 8, 64), 256, SMEM_MAIN>>>();   // logits = xT . T^T
    p_gemm<<<dim3(8, 1, 64), 256, SMEM_P>>>();        // P = G . xT
    a2b1<0><<<dim3(8, 4, 64), 256, SMEM_O>>>(nullptr); // v = W16 . xT16
    softmax_bias<<<BATCH * NTOK, 256>>>();             // att fp16
    a2b1<1><<<dim3(8, 4, 64), 256, SMEM_O>>>(out);     // out = v . att
}

// round 7
// speedup vs baseline: 4.8609x; 1.1081x over previous
#include <cuda_runtime.h>
#include <cuda_bf16.h>
#include <cuda_fp16.h>
#include <cstdint>

#define BATCH 64
#define CDIM  512
#define NTOK  1024

typedef __nv_bfloat16 bf;

// ---------------- scratch (device globals) ----------------------------------
__device__ float g_WT [(size_t)512 * 1536];            // [c][o] = W[o][c]
__device__ float g_rhw[(size_t)64 * 512];              // [r][c] fp32
__device__ bf g_Mh[(size_t)512 * 512];                 // M = Wq^T Wk, bf16 hi
__device__ bf g_Mm[(size_t)512 * 512];
__device__ bf g_Gh[(size_t)64 * 512];                  // G = RHW * Wq
__device__ bf g_Gm[(size_t)64 * 512];
__device__ bf g_xTh[(size_t)BATCH * NTOK * CDIM];      // [b][n][c]
__device__ bf g_xTm[(size_t)BATCH * NTOK * CDIM];
__device__ __half g_xT16[(size_t)BATCH * NTOK * CDIM];
__device__ __half g_W16h[(size_t)512 * 512];           // Wv fp16 hi  [cv][c]
__device__ __half g_W16l[(size_t)512 * 512];
__device__ bf g_Th[(size_t)BATCH * NTOK * 512];        // T^T [b][m][c1]
__device__ bf g_Tm[(size_t)BATCH * NTOK * 512];
__device__ float  g_logit[(size_t)BATCH * NTOK * NTOK];
__device__ float  g_P[(size_t)BATCH * 64 * NTOK];
__device__ __half g_v16[(size_t)BATCH * CDIM * NTOK];  // [b][c][n] fp16 (single)
__device__ __half g_att16[(size_t)BATCH * NTOK * NTOK];

// ---------------- PTX helpers ----------------------------------------------
__device__ __forceinline__ uint32_t smem_u32(const void* p) {
    uint32_t a;
    asm("{ .reg .u64 t; cvta.to.shared.u64 t, %1; cvt.u32.u64 %0, t; }" : "=r"(a) : "l"(p));
    return a;
}
__device__ __forceinline__ void cpa16(uint32_t dst, const void* src) {
    asm volatile("cp.async.cg.shared.global [%0], [%1], 16;" :: "r"(dst), "l"(src));
}
__device__ __forceinline__ void ldsm4(uint32_t r[4], uint32_t addr) {
    asm volatile("ldmatrix.sync.aligned.m8n8.x4.shared.b16 {%0,%1,%2,%3}, [%4];"
                 : "=r"(r[0]), "=r"(r[1]), "=r"(r[2]), "=r"(r[3]) : "r"(addr));
}
__device__ __forceinline__ void mma16816(float c[4], const uint32_t a[4], const uint32_t b[2]) {
    asm volatile("mma.sync.aligned.m16n8k16.row.col.f32.bf16.bf16.f32 "
                 "{%0,%1,%2,%3}, {%4,%5,%6,%7}, {%8,%9}, {%0,%1,%2,%3};"
                 : "+f"(c[0]), "+f"(c[1]), "+f"(c[2]), "+f"(c[3])
                 : "r"(a[0]), "r"(a[1]), "r"(a[2]), "r"(a[3]), "r"(b[0]), "r"(b[1]));
}
__device__ __forceinline__ void mma16816h(float c[4], const uint32_t a[4], const uint32_t b[2]) {
    asm volatile("mma.sync.aligned.m16n8k16.row.col.f32.f16.f16.f32 "
                 "{%0,%1,%2,%3}, {%4,%5,%6,%7}, {%8,%9}, {%0,%1,%2,%3};"
                 : "+f"(c[0]), "+f"(c[1]), "+f"(c[2]), "+f"(c[3])
                 : "r"(a[0]), "r"(a[1]), "r"(a[2]), "r"(a[3]), "r"(b[0]), "r"(b[1]));
}
__device__ __forceinline__ uint32_t sw_off(int row, int chunk) {
    return (uint32_t)(row * 64 + ((chunk ^ ((row >> 1) & 3)) << 4));
}
__device__ __forceinline__ void split_store(bf* __restrict__ ph, bf* __restrict__ pm,
                                            size_t off, float v0, float v1) {
    bf h0 = __float2bfloat16(v0), h1 = __float2bfloat16(v1);
    bf m0 = __float2bfloat16(v0 - __bfloat162float(h0));
    bf m1 = __float2bfloat16(v1 - __bfloat162float(h1));
    __nv_bfloat162 hh; hh.x = h0; hh.y = h1;
    __nv_bfloat162 mm; mm.x = m0; mm.y = m1;
    *reinterpret_cast<__nv_bfloat162*>(ph + off) = hh;
    *reinterpret_cast<__nv_bfloat162*>(pm + off) = mm;
}

// ================= 3-term bf16 GEMM (128x128 tile, K=512) ===================
// MODE 0: T^T[b][m][c1] = sum_c2 xT[m][c2] * M[c1][c2]
// MODE 1: logit[b][n][m] = sum_c1 xT[n][c1] * T^T[m][c1]
#define OFF_AH 0
#define OFF_AM 8192
#define OFF_BH 16384
#define OFF_BM 24576
#define STAGE_BYTES 32768
#define NSTAGE 3
#define SMEM_MAIN (NSTAGE * STAGE_BYTES)

template <int MODE>
__global__ __launch_bounds__(256, 2) void gemm3() {
    extern __shared__ __align__(128) char smem[];
    const uint32_t sbase = smem_u32(smem);
    const int tid = threadIdx.x;
    const int wid = tid >> 5, lane = tid & 31;
    const int b = blockIdx.z;
    const int nBase = blockIdx.x * 128;
    const int mBase = blockIdx.y * 128;
    const int wm = (wid >> 2) * 64, wn = (wid & 3) * 32;

    constexpr int NIT = 16;
    const size_t bXT = (size_t)b << 19;
    const size_t bQK = (size_t)b << 20;

    float acc[4][4][4];
#pragma unroll
    for (int i = 0; i < 4; i++)
#pragma unroll
        for (int j = 0; j < 4; j++)
#pragma unroll
            for (int k = 0; k < 4; k++) acc[i][j][k] = 0.f;

    auto issue_stage = [&](int stage, int kt) {
        const bf *pah, *pam, *pbh, *pbm;
        pah = g_xTh + bXT + (size_t)mBase * 512 + kt;
        pam = g_xTm + bXT + (size_t)mBase * 512 + kt;
        if (MODE == 0) {
            pbh = g_Mh + (size_t)nBase * 512 + kt;
            pbm = g_Mm + (size_t)nBase * 512 + kt;
        } else {
            pbh = g_Th + bXT + (size_t)nBase * 512 + kt;
            pbm = g_Tm + bXT + (size_t)nBase * 512 + kt;
        }
        const uint32_t sb = sbase + stage * STAGE_BYTES;
#pragma unroll
        for (int j = 0; j < 2; j++) {
            const int idx = tid + j * 256;
            const int row = idx >> 2, ch = idx & 3;
            const uint32_t d = sw_off(row, ch);
            const int s = row * 512 + ch * 8;
            cpa16(sb + OFF_AH + d, pah + s);
            cpa16(sb + OFF_AM + d, pam + s);
            cpa16(sb + OFF_BH + d, pbh + s);
            cpa16(sb + OFF_BM + d, pbm + s);
        }
        asm volatile("cp.async.commit_group;");
    };

    auto compute = [&](int stage) {
        const uint32_t base = sbase + stage * STAGE_BYTES;
        const int sel = lane >> 3;
        uint32_t bhf[2][4][2];
#pragma unroll
        for (int k8 = 0; k8 < 2; k8++)
#pragma unroll
            for (int pr = 0; pr < 2; pr++) {
                const int nt = 2 * pr + (sel >> 1);
                const int kb = sel & 1;
                uint32_t r[4];
                ldsm4(r, base + OFF_BH + sw_off(wn + nt * 8 + (lane & 7), k8 * 2 + kb));
                bhf[k8][2 * pr][0] = r[0]; bhf[k8][2 * pr][1] = r[1];
                bhf[k8][2 * pr + 1][0] = r[2]; bhf[k8][2 * pr + 1][1] = r[3];
            }
#pragma unroll
        for (int k8 = 0; k8 < 2; k8++) {
            uint32_t bmf[4][2];
#pragma unroll
            for (int pr = 0; pr < 2; pr++) {
                const int nt = 2 * pr + (sel >> 1);
                const int kb = sel & 1;
                uint32_t r[4];
                ldsm4(r, base + OFF_BM + sw_off(wn + nt * 8 + (lane & 7), k8 * 2 + kb));
                bmf[2 * pr][0] = r[0]; bmf[2 * pr][1] = r[1];
                bmf[2 * pr + 1][0] = r[2]; bmf[2 * pr + 1][1] = r[3];
            }
#pragma unroll
            for (int mt = 0; mt < 4; mt++) {
                const uint32_t aa = base + OFF_AH +
                    sw_off(wm + mt * 16 + (sel & 1) * 8 + (lane & 7), k8 * 2 + (sel >> 1));
                uint32_t ah[4], am[4];
                ldsm4(ah, aa);
                ldsm4(am, aa + (OFF_AM - OFF_AH));
#pragma unroll
                for (int nt = 0; nt < 4; nt++) mma16816(acc[mt][nt], ah, bhf[k8][nt]);
#pragma unroll
                for (int nt = 0; nt < 4; nt++) mma16816(acc[mt][nt], ah, bmf[nt]);
#pragma unroll
                for (int nt = 0; nt < 4; nt++) mma16816(acc[mt][nt], am, bhf[k8][nt]);
            }
        }
    };

    issue_stage(0, 0);
    issue_stage(1, 32);
    for (int it = 0; it < NIT; it++) {
        if (it + 2 < NIT) asm volatile("cp.async.wait_group 1;");
        else              asm volatile("cp.async.wait_group 0;");
        __syncthreads();
        if (it + 2 < NIT) issue_stage((it + 2) % NSTAGE, (it + 2) * 32);
        compute(it % NSTAGE);
    }

    const int lr = lane >> 2, lc = 2 * (lane & 3);
#pragma unroll
    for (int mt = 0; mt < 4; mt++) {
#pragma unroll
        for (int nt = 0; nt < 4; nt++) {
            const int r0 = mBase + wm + mt * 16 + lr;
            const int c0 = nBase + wn + nt * 8 + lc;
            if (MODE == 0) {
                split_store(g_Th + bXT, g_Tm + bXT, (size_t)r0 * 512 + c0, acc[mt][nt][0], acc[mt][nt][1]);
                split_store(g_Th + bXT, g_Tm + bXT, (size_t)(r0 + 8) * 512 + c0, acc[mt][nt][2], acc[mt][nt][3]);
            } else {
                float2 v0; v0.x = acc[mt][nt][0]; v0.y = acc[mt][nt][1];
                float2 v1; v1.x = acc[mt][nt][2]; v1.y = acc[mt][nt][3];
                *reinterpret_cast<float2*>(g_logit + bQK + (size_t)r0 * 1024 + c0) = v0;
                *reinterpret_cast<float2*>(g_logit + bQK + (size_t)(r0 + 8) * 1024 + c0) = v1;
            }
        }
    }
}

// ================= P GEMM: P[b][r][m] = G[r][:] . xT[m][:]  (64x128 tile) ===
#define P_AH 0
#define P_AM 4096
#define P_BH 8192
#define P_BM 16384
#define P_STAGE 24576
#define SMEM_P (NSTAGE * P_STAGE)

__global__ __launch_bounds__(256, 2) void p_gemm() {
    extern __shared__ __align__(128) char smem[];
    const uint32_t sbase = smem_u32(smem);
    const int tid = threadIdx.x;
    const int wid = tid >> 5, lane = tid & 31;
    const int b = blockIdx.z;
    const int nBase = blockIdx.x * 128;
    const int wm = (wid >> 2) * 32, wn = (wid & 3) * 32;
    const size_t bXT = (size_t)b << 19;

    float acc[2][4][4];
#pragma unroll
    for (int i = 0; i < 2; i++)
#pragma unroll
        for (int j = 0; j < 4; j++)
#pragma unroll
            for (int k = 0; k < 4; k++) acc[i][j][k] = 0.f;

    auto issue_stage = [&](int stage, int kt) {
        const uint32_t sb = sbase + stage * P_STAGE;
        {
            const int row = tid >> 2, ch = tid & 3;
            const uint32_t d = sw_off(row, ch);
            const int s = row * 512 + kt + ch * 8;
            cpa16(sb + P_AH + d, g_Gh + s);
            cpa16(sb + P_AM + d, g_Gm + s);
        }
#pragma unroll
        for (int j = 0; j < 2; j++) {
            const int idx = tid + j * 256;
            const int row = idx >> 2, ch = idx & 3;
            const uint32_t d = sw_off(row, ch);
            const size_t s = bXT + (size_t)(nBase + row) * 512 + kt + ch * 8;
            cpa16(sb + P_BH + d, g_xTh + s);
            cpa16(sb + P_BM + d, g_xTm + s);
        }
        asm volatile("cp.async.commit_group;");
    };

    auto compute = [&](int stage) {
        const uint32_t base = sbase + stage * P_STAGE;
        const int sel = lane >> 3;
#pragma unroll
        for (int k8 = 0; k8 < 2; k8++) {
            uint32_t bhf[4][2], bmf[4][2];
#pragma unroll
            for (int pr = 0; pr < 2; pr++) {
                const int nt = 2 * pr + (sel >> 1);
                const int kb = sel & 1;
                const uint32_t ra = base + P_BH + sw_off(wn + nt * 8 + (lane & 7), k8 * 2 + kb);
                uint32_t r[4];
                ldsm4(r, ra);
                bhf[2 * pr][0] = r[0]; bhf[2 * pr][1] = r[1];
                bhf[2 * pr + 1][0] = r[2]; bhf[2 * pr + 1][1] = r[3];
                ldsm4(r, ra + (P_BM - P_BH));
                bmf[2 * pr][0] = r[0]; bmf[2 * pr][1] = r[1];
                bmf[2 * pr + 1][0] = r[2]; bmf[2 * pr + 1][1] = r[3];
            }
#pragma unroll
            for (int mt = 0; mt < 2; mt++) {
                const uint32_t aa = base + P_AH +
                    sw_off(wm + mt * 16 + (sel & 1) * 8 + (lane & 7), k8 * 2 + (sel >> 1));
                uint32_t ah[4], am[4];
                ldsm4(ah, aa);
                ldsm4(am, aa + (P_AM - P_AH));
#pragma unroll
                for (int nt = 0; nt < 4; nt++) mma16816(acc[mt][nt], ah, bhf[nt]);
#pragma unroll
                for (int nt = 0; nt < 4; nt++) mma16816(acc[mt][nt], ah, bmf[nt]);
#pragma unroll
                for (int nt = 0; nt < 4; nt++) mma16816(acc[mt][nt], am, bhf[nt]);
            }
        }
    };

    issue_stage(0, 0);
    issue_stage(1, 32);
    for (int it = 0; it < 16; it++) {
        if (it + 2 < 16) asm volatile("cp.async.wait_group 1;");
        else             asm volatile("cp.async.wait_group 0;");
        __syncthreads();
        if (it + 2 < 16) issue_stage((it + 2) % NSTAGE, (it + 2) * 32);
        compute(it % NSTAGE);
    }

    const int lr = lane >> 2, lc = 2 * (lane & 3);
    float* P = g_P + (size_t)b * 64 * 1024;
#pragma unroll
    for (int mt = 0; mt < 2; mt++) {
#pragma unroll
        for (int nt = 0; nt < 4; nt++) {
            const int r0 = wm + mt * 16 + lr;
            const int c0 = nBase + wn + nt * 8 + lc;
            float2 v0; v0.x = acc[mt][nt][0]; v0.y = acc[mt][nt][1];
            float2 v1; v1.x = acc[mt][nt][2]; v1.y = acc[mt][nt][3];
            *reinterpret_cast<float2*>(P + (size_t)r0 * 1024 + c0) = v0;
            *reinterpret_cast<float2*>(P + (size_t)(r0 + 8) * 1024 + c0) = v1;
        }
    }
}

// ======= v GEMM: fp16 2-term compute, fp16 single store (128x128, K=512) ====
#define V_AH 0
#define V_AL 8192
#define V_B  16384
#define V_STAGE 24576
#define SMEM_V (NSTAGE * V_STAGE)

__global__ __launch_bounds__(256, 2) void v_gemm() {
    extern __shared__ __align__(128) char smem[];
    const uint32_t sbase = smem_u32(smem);
    const int tid = threadIdx.x;
    const int wid = tid >> 5, lane = tid & 31;
    const int b = blockIdx.z;
    const int nBase = blockIdx.x * 128;
    const int mBase = blockIdx.y * 128;
    const int wm = (wid >> 2) * 64, wn = (wid & 3) * 32;
    const size_t bXT = (size_t)b << 19;

    float acc[4][4][4];
#pragma unroll
    for (int i = 0; i < 4; i++)
#pragma unroll
        for (int j = 0; j < 4; j++)
#pragma unroll
            for (int k = 0; k < 4; k++) acc[i][j][k] = 0.f;

    auto issue_stage = [&](int stage, int kt) {
        const __half* pah = g_W16h + (size_t)mBase * 512 + kt;
        const __half* pal = g_W16l + (size_t)mBase * 512 + kt;
        const __half* pb  = g_xT16 + bXT + (size_t)nBase * 512 + kt;
        const uint32_t sb = sbase + stage * V_STAGE;
#pragma unroll
        for (int j = 0; j < 2; j++) {
            const int idx = tid + j * 256;
            const int row = idx >> 2, ch = idx & 3;
            const uint32_t d = sw_off(row, ch);
            const int s = row * 512 + ch * 8;
            cpa16(sb + V_AH + d, pah + s);
            cpa16(sb + V_AL + d, pal + s);
            cpa16(sb + V_B  + d, pb  + s);
        }
        asm volatile("cp.async.commit_group;");
    };

    auto compute = [&](int stage) {
        const uint32_t base = sbase + stage * V_STAGE;
        const int sel = lane >> 3;
        uint32_t bff[2][4][2];
#pragma unroll
        for (int k8 = 0; k8 < 2; k8++)
#pragma unroll
            for (int pr = 0; pr < 2; pr++) {
                const int nt = 2 * pr + (sel >> 1);
                const int kb = sel & 1;
                uint32_t r[4];
                ldsm4(r, base + V_B + sw_off(wn + nt * 8 + (lane & 7), k8 * 2 + kb));
                bff[k8][2 * pr][0] = r[0]; bff[k8][2 * pr][1] = r[1];
                bff[k8][2 * pr + 1][0] = r[2]; bff[k8][2 * pr + 1][1] = r[3];
            }
#pragma unroll
        for (int k8 = 0; k8 < 2; k8++) {
#pragma unroll
            for (int mt = 0; mt < 4; mt++) {
                const uint32_t aa = base + V_AH +
                    sw_off(wm + mt * 16 + (sel & 1) * 8 + (lane & 7), k8 * 2 + (sel >> 1));
                uint32_t ah[4], al[4];
                ldsm4(ah, aa);
                ldsm4(al, aa + (V_AL - V_AH));
#pragma unroll
                for (int nt = 0; nt < 4; nt++) mma16816h(acc[mt][nt], ah, bff[k8][nt]);
#pragma unroll
                for (int nt = 0; nt < 4; nt++) mma16816h(acc[mt][nt], al, bff[k8][nt]);
            }
        }
    };

    issue_stage(0, 0);
    issue_stage(1, 32);
    for (int it = 0; it < 16; it++) {
        if (it + 2 < 16) asm volatile("cp.async.wait_group 1;");
        else             asm volatile("cp.async.wait_group 0;");
        __syncthreads();
        if (it + 2 < 16) issue_stage((it + 2) % NSTAGE, (it + 2) * 32);
        compute(it % NSTAGE);
    }

    const int lr = lane >> 2, lc = 2 * (lane & 3);
    __half* ov = g_v16 + bXT;
#pragma unroll
    for (int mt = 0; mt < 4; mt++) {
#pragma unroll
        for (int nt = 0; nt < 4; nt++) {
            const int r0 = mBase + wm + mt * 16 + lr;
            const int c0 = nBase + wn + nt * 8 + lc;
            __half2 h0; h0.x = __float2half_rn(acc[mt][nt][0]); h0.y = __float2half_rn(acc[mt][nt][1]);
            __half2 h1; h1.x = __float2half_rn(acc[mt][nt][2]); h1.y = __float2half_rn(acc[mt][nt][3]);
            *reinterpret_cast<__half2*>(ov + (size_t)r0 * 1024 + c0) = h0;
            *reinterpret_cast<__half2*>(ov + (size_t)(r0 + 8) * 1024 + c0) = h1;
        }
    }
}

// ======= out GEMM: fp16 single-term (128x128 tile, K=1024) ==================
#define U_A  0
#define U_B  8192
#define U_STAGE 16384
#define SMEM_U (NSTAGE * U_STAGE)

__global__ __launch_bounds__(256, 2) void out_gemm(float* __restrict__ outp) {
    extern __shared__ __align__(128) char smem[];
    const uint32_t sbase = smem_u32(smem);
    const int tid = threadIdx.x;
    const int wid = tid >> 5, lane = tid & 31;
    const int b = blockIdx.z;
    const int nBase = blockIdx.x * 128;
    const int mBase = blockIdx.y * 128;
    const int wm = (wid >> 2) * 64, wn = (wid & 3) * 32;
    const size_t bQK = (size_t)b << 20;
    const size_t bXT = (size_t)b << 19;

    float acc[4][4][4];
#pragma unroll
    for (int i = 0; i < 4; i++)
#pragma unroll
        for (int j = 0; j < 4; j++)
#pragma unroll
            for (int k = 0; k < 4; k++) acc[i][j][k] = 0.f;

    auto issue_stage = [&](int stage, int kt) {
        const __half* pa = g_v16 + bXT + (size_t)mBase * 1024 + kt;
        const __half* pb = g_att16 + bQK + (size_t)nBase * 1024 + kt;
        const uint32_t sb = sbase + stage * U_STAGE;
#pragma unroll
        for (int j = 0; j < 2; j++) {
            const int idx = tid + j * 256;
            const int row = idx >> 2, ch = idx & 3;
            const uint32_t d = sw_off(row, ch);
            const int s = row * 1024 + ch * 8;
            cpa16(sb + U_A + d, pa + s);
            cpa16(sb + U_B + d, pb + s);
        }
        asm volatile("cp.async.commit_group;");
    };

    auto compute = [&](int stage) {
        const uint32_t base = sbase + stage * U_STAGE;
        const int sel = lane >> 3;
        uint32_t bff[2][4][2];
#pragma unroll
        for (int k8 = 0; k8 < 2; k8++)
#pragma unroll
            for (int pr = 0; pr < 2; pr++) {
                const int nt = 2 * pr + (sel >> 1);
                const int kb = sel & 1;
                uint32_t r[4];
                ldsm4(r, base + U_B + sw_off(wn + nt * 8 + (lane & 7), k8 * 2 + kb));
                bff[k8][2 * pr][0] = r[0]; bff[k8][2 * pr][1] = r[1];
                bff[k8][2 * pr + 1][0] = r[2]; bff[k8][2 * pr + 1][1] = r[3];
            }
#pragma unroll
        for (int k8 = 0; k8 < 2; k8++) {
#pragma unroll
            for (int mt = 0; mt < 4; mt++) {
                const uint32_t aa = base + U_A +
                    sw_off(wm + mt * 16 + (sel & 1) * 8 + (lane & 7), k8 * 2 + (sel >> 1));
                uint32_t ah[4];
                ldsm4(ah, aa);
#pragma unroll
                for (int nt = 0; nt < 4; nt++) mma16816h(acc[mt][nt], ah, bff[k8][nt]);
            }
        }
    };

    issue_stage(0, 0);
    issue_stage(1, 32);
    for (int it = 0; it < 32; it++) {
        if (it + 2 < 32) asm volatile("cp.async.wait_group 1;");
        else             asm volatile("cp.async.wait_group 0;");
        __syncthreads();
        if (it + 2 < 32) issue_stage((it + 2) % NSTAGE, (it + 2) * 32);
        compute(it % NSTAGE);
    }

    const int lr = lane >> 2, lc = 2 * (lane & 3);
    float* of = outp + bXT;
#pragma unroll
    for (int mt = 0; mt < 4; mt++) {
#pragma unroll
        for (int nt = 0; nt < 4; nt++) {
            const int r0 = mBase + wm + mt * 16 + lr;
            const int c0 = nBase + wn + nt * 8 + lc;
            float2 v0; v0.x = acc[mt][nt][0]; v0.y = acc[mt][nt][1];
            float2 v1; v1.x = acc[mt][nt][2]; v1.y = acc[mt][nt][3];
            *reinterpret_cast<float2*>(of + (size_t)r0 * 1024 + c0) = v0;
            *reinterpret_cast<float2*>(of + (size_t)(r0 + 8) * 1024 + c0) = v1;
        }
    }
}

// ---------------- small fp32 GEMM for M and G precompute --------------------
template <int IS_G>
__global__ __launch_bounds__(256) void sgemm_split() {
    const float* A = IS_G ? g_rhw : g_WT;
    const int lda = IS_G ? 512 : 1536;
    const float* B = IS_G ? g_WT : (g_WT + 512);
    const int ldb = 1536;
    bf* Ch = IS_G ? g_Gh : g_Mh;
    bf* Cm = IS_G ? g_Gm : g_Mm;

    __shared__ float As[16][72];
    __shared__ float Bs[16][72];
    const int tid = threadIdx.x;
    const int tx = tid & 15, ty = tid >> 4;
    const int rBase = blockIdx.y * 64, cBase = blockIdx.x * 64;

    float acc[4][4];
#pragma unroll
    for (int i = 0; i < 4; i++)
#pragma unroll
        for (int j = 0; j < 4; j++) acc[i][j] = 0.f;

    for (int kt = 0; kt < 512; kt += 16) {
        const int row = tid >> 2, q = (tid & 3) * 4;
        float4 va = *(const float4*)&A[(size_t)(rBase + row) * lda + kt + q];
        As[q + 0][row] = va.x; As[q + 1][row] = va.y;
        As[q + 2][row] = va.z; As[q + 3][row] = va.w;
        float4 vb = *(const float4*)&B[(size_t)(cBase + row) * ldb + kt + q];
        Bs[q + 0][row] = vb.x; Bs[q + 1][row] = vb.y;
        Bs[q + 2][row] = vb.z; Bs[q + 3][row] = vb.w;
        __syncthreads();
#pragma unroll
        for (int k = 0; k < 16; k++) {
            float a[4], bb[4];
            *(float4*)&a[0]  = *(const float4*)&As[k][ty * 4];
            *(float4*)&bb[0] = *(const float4*)&Bs[k][tx * 4];
#pragma unroll
            for (int i = 0; i < 4; i++)
#pragma unroll
                for (int j = 0; j < 4; j++) acc[i][j] += a[i] * bb[j];
        }
        __syncthreads();
    }
#pragma unroll
    for (int i = 0; i < 4; i++) {
        const int row = rBase + ty * 4 + i;
        const int col = cBase + tx * 4;
        split_store(Ch, Cm, (size_t)row * 512 + col, acc[i][0], acc[i][1]);
        split_store(Ch, Cm, (size_t)row * 512 + col + 2, acc[i][2], acc[i][3]);
    }
}

// ---------------- prep kernels ----------------------------------------------
__global__ void transpose_w(const float* __restrict__ W) {
    __shared__ float t[32][33];
    int o0 = blockIdx.x * 32, c0 = blockIdx.y * 32;
    int tx = threadIdx.x, ty = threadIdx.y;
#pragma unroll
    for (int j = 0; j < 32; j += 8)
        t[ty + j][tx] = W[(size_t)(o0 + ty + j) * 512 + c0 + tx];
    __syncthreads();
#pragma unroll
    for (int j = 0; j < 32; j += 8)
        g_WT[(size_t)(c0 + ty + j) * 1536 + o0 + tx] = t[tx][ty + j];
}

__global__ void prep_rhw(const float* __restrict__ rel_h, const float* __restrict__ rel_w) {
    int idx = blockIdx.x * blockDim.x + threadIdx.x;
    if (idx >= 64 * 512) return;
    int r = idx >> 9, c = idx & 511;
    g_rhw[idx] = (r < 32) ? rel_h[c * 32 + r] : rel_w[c * 32 + (r - 32)];
}

__global__ void prep_w16(const float* __restrict__ W) {
    int idx = blockIdx.x * blockDim.x + threadIdx.x;
    if (idx >= 512 * 512) return;
    int cv = idx >> 9, c = idx & 511;
    float v = W[(size_t)(1024 + cv) * 512 + c];
    __half h = __float2half_rn(v);
    g_W16h[idx] = h;
    g_W16l[idx] = __float2half_rn(v - __half2float(h));
}

__global__ void transpose_x(const float* __restrict__ x) {
    __shared__ float t[32][33];
    int b = blockIdx.z;
    int n0 = blockIdx.x * 32, c0 = blockIdx.y * 32;
    const float* src = x + (size_t)b * CDIM * NTOK;
    size_t dbase = (size_t)b * NTOK * CDIM;
    int tx = threadIdx.x, ty = threadIdx.y;
#pragma unroll
    for (int j = 0; j < 32; j += 8)
        t[ty + j][tx] = src[(size_t)(c0 + ty + j) * NTOK + n0 + tx];
    __syncthreads();
#pragma unroll
    for (int j = 0; j < 32; j += 8) {
        float v = t[tx][ty + j];
        size_t off = dbase + (size_t)(n0 + ty + j) * CDIM + c0 + tx;
        bf h = __float2bfloat16(v);
        g_xTh[off] = h;
        g_xTm[off] = __float2bfloat16(v - __bfloat162float(h));
        g_xT16[off] = __float2half_rn(v);
    }
}

// softmax over m with fused pos-bias; writes fp16 att
__global__ __launch_bounds__(256) void softmax_bias() {
    size_t row = blockIdx.x;
    int b = (int)(row >> 10);
    int n = (int)(row & 1023);
    int h = n >> 5, w = n & 31;
    const float* p  = g_logit + row * NTOK;
    const float* ph = g_P + ((size_t)b * 64 + h) * 1024;
    const float* pw = g_P + ((size_t)b * 64 + 32 + w) * 1024;
    int tid = threadIdx.x;

    float4 v = *(const float4*)&p[tid * 4];
    float4 bh = *(const float4*)&ph[tid * 4];
    float4 bw = *(const float4*)&pw[tid * 4];
    v.x += bh.x + bw.x; v.y += bh.y + bw.y;
    v.z += bh.z + bw.z; v.w += bh.w + bw.w;

    float m = fmaxf(fmaxf(v.x, v.y), fmaxf(v.z, v.w));
#pragma unroll
    for (int o = 16; o; o >>= 1) m = fmaxf(m, __shfl_xor_sync(~0u, m, o));
    __shared__ float red[8];
    if ((tid & 31) == 0) red[tid >> 5] = m;
    __syncthreads();
    float bm = red[0];
#pragma unroll
    for (int i = 1; i < 8; i++) bm = fmaxf(bm, red[i]);
    __syncthreads();

    v.x = __expf(v.x - bm); v.y = __expf(v.y - bm);
    v.z = __expf(v.z - bm); v.w = __expf(v.w - bm);
    float s = v.x + v.y + v.z + v.w;
#pragma unroll
    for (int o = 16; o; o >>= 1) s += __shfl_xor_sync(~0u, s, o);
    if ((tid & 31) == 0) red[tid >> 5] = s;
    __syncthreads();
    float bs = 0.f;
#pragma unroll
    for (int i = 0; i < 8; i++) bs += red[i];
    float inv = 1.0f / bs;

    __half2 a0; a0.x = __float2half_rn(v.x * inv); a0.y = __float2half_rn(v.y * inv);
    __half2 a1; a1.x = __float2half_rn(v.z * inv); a1.y = __float2half_rn(v.w * inv);
    size_t off = row * NTOK + tid * 4;
    *reinterpret_cast<__half2*>(g_att16 + off) = a0;
    *reinterpret_cast<__half2*>(g_att16 + off + 2) = a1;
}

// ---------------------------------------------------------------------------
extern "C" void kernel_launch(void* const* d_in, const int* in_sizes, int n_in,
                              void* d_out, int out_size) {
    const float* x     = (const float*)d_in[0];
    const float* Wmat  = (const float*)d_in[1];
    const float* rel_h = (const float*)d_in[2];
    const float* rel_w = (const float*)d_in[3];
    float* out = (float*)d_out;

    cudaFuncSetAttribute(gemm3<0>, cudaFuncAttributeMaxDynamicSharedMemorySize, SMEM_MAIN);
    cudaFuncSetAttribute(gemm3<1>, cudaFuncAttributeMaxDynamicSharedMemorySize, SMEM_MAIN);
    cudaFuncSetAttribute(p_gemm,   cudaFuncAttributeMaxDynamicSharedMemorySize, SMEM_P);
    cudaFuncSetAttribute(v_gemm,   cudaFuncAttributeMaxDynamicSharedMemorySize, SMEM_V);
    cudaFuncSetAttribute(out_gemm, cudaFuncAttributeMaxDynamicSharedMemorySize, SMEM_U);

    transpose_w<<<dim3(48, 16), dim3(32, 8)>>>(Wmat);
    prep_rhw<<<(64 * 512 + 255) / 256, 256>>>(rel_h, rel_w);
    prep_w16<<<(512 * 512 + 255) / 256, 256>>>(Wmat);
    transpose_x<<<dim3(32, 16, 64), dim3(32, 8)>>>(x);

    sgemm_split<0><<<dim3(8, 8), 256>>>();     // M = Wq^T Wk
    sgemm_split<1><<<dim3(8, 1), 256>>>();     // G = RHW * Wq

    gemm3<0><<<dim3(4, 8, 64), 256, SMEM_MAIN>>>();   // T^T = xT . M
    gemm3<1><<<dim3(8, 8, 64), 256, SMEM_MAIN>>>();   // logits = xT . T^T
    p_gemm<<<dim3(8, 1, 64), 256, SMEM_P>>>();        // P = G . xT
    v_gemm<<<dim3(8, 4, 64), 256, SMEM_V>>>();        // v fp16
    softmax_bias<<<BATCH * NTOK, 256>>>();            // att fp16
    out_gemm<<<dim3(8, 4, 64), 256, SMEM_U>>>(out);   // out = v . att
}

// round 8
// speedup vs baseline: 5.0053x; 1.0297x over previous
#include <cuda_runtime.h>
#include <cuda_bf16.h>
#include <cuda_fp16.h>
#include <cstdint>

#define BATCH 64
#define CDIM  512
#define NTOK  1024

typedef __nv_bfloat16 bf;

// ---------------- scratch (device globals) ----------------------------------
__device__ float g_WT [(size_t)512 * 1536];            // [c][o] = W[o][c]
__device__ float g_rhw[(size_t)64 * 512];              // [r][c] fp32
__device__ bf g_Mh[(size_t)512 * 512];                 // M = Wq^T Wk
__device__ bf g_Mm[(size_t)512 * 512];
__device__ bf g_Gh[(size_t)64 * 512];                  // G = RHW * Wq
__device__ bf g_Gm[(size_t)64 * 512];
__device__ bf g_xTh[(size_t)BATCH * NTOK * CDIM];      // [b][n][c]
__device__ bf g_xTm[(size_t)BATCH * NTOK * CDIM];
__device__ __half g_xT16[(size_t)BATCH * NTOK * CDIM];
__device__ __half g_W16h[(size_t)512 * 512];           // Wv fp16 hi  [cv][c]
__device__ __half g_W16l[(size_t)512 * 512];
__device__ bf g_Th[(size_t)BATCH * NTOK * 512];        // T^T [b][m][c1]
__device__ bf g_Tm[(size_t)BATCH * NTOK * 512];
__device__ float  g_logit[(size_t)BATCH * NTOK * NTOK];
__device__ float  g_P[(size_t)BATCH * 64 * NTOK];
__device__ __half g_v16[(size_t)BATCH * CDIM * NTOK];  // [b][c][n]
__device__ __half g_att16[(size_t)BATCH * NTOK * NTOK];

// ---------------- PTX helpers ----------------------------------------------
__device__ __forceinline__ uint32_t smem_u32(const void* p) {
    uint32_t a;
    asm("{ .reg .u64 t; cvta.to.shared.u64 t, %1; cvt.u32.u64 %0, t; }" : "=r"(a) : "l"(p));
    return a;
}
__device__ __forceinline__ void cpa16(uint32_t dst, const void* src) {
    asm volatile("cp.async.cg.shared.global [%0], [%1], 16;" :: "r"(dst), "l"(src));
}
__device__ __forceinline__ void ldsm4(uint32_t r[4], uint32_t addr) {
    asm volatile("ldmatrix.sync.aligned.m8n8.x4.shared.b16 {%0,%1,%2,%3}, [%4];"
                 : "=r"(r[0]), "=r"(r[1]), "=r"(r[2]), "=r"(r[3]) : "r"(addr));
}
__device__ __forceinline__ void mma16816(float c[4], const uint32_t a[4], const uint32_t b[2]) {
    asm volatile("mma.sync.aligned.m16n8k16.row.col.f32.bf16.bf16.f32 "
                 "{%0,%1,%2,%3}, {%4,%5,%6,%7}, {%8,%9}, {%0,%1,%2,%3};"
                 : "+f"(c[0]), "+f"(c[1]), "+f"(c[2]), "+f"(c[3])
                 : "r"(a[0]), "r"(a[1]), "r"(a[2]), "r"(a[3]), "r"(b[0]), "r"(b[1]));
}
__device__ __forceinline__ void mma16816h(float c[4], const uint32_t a[4], const uint32_t b[2]) {
    asm volatile("mma.sync.aligned.m16n8k16.row.col.f32.f16.f16.f32 "
                 "{%0,%1,%2,%3}, {%4,%5,%6,%7}, {%8,%9}, {%0,%1,%2,%3};"
                 : "+f"(c[0]), "+f"(c[1]), "+f"(c[2]), "+f"(c[3])
                 : "r"(a[0]), "r"(a[1]), "r"(a[2]), "r"(a[3]), "r"(b[0]), "r"(b[1]));
}
__device__ __forceinline__ uint32_t sw_off(int row, int chunk) {
    return (uint32_t)(row * 64 + ((chunk ^ ((row >> 1) & 3)) << 4));
}
__device__ __forceinline__ void split_store(bf* __restrict__ ph, bf* __restrict__ pm,
                                            size_t off, float v0, float v1) {
    bf h0 = __float2bfloat16(v0), h1 = __float2bfloat16(v1);
    bf m0 = __float2bfloat16(v0 - __bfloat162float(h0));
    bf m1 = __float2bfloat16(v1 - __bfloat162float(h1));
    __nv_bfloat162 hh; hh.x = h0; hh.y = h1;
    __nv_bfloat162 mm; mm.x = m0; mm.y = m1;
    *reinterpret_cast<__nv_bfloat162*>(ph + off) = hh;
    *reinterpret_cast<__nv_bfloat162*>(pm + off) = mm;
}

// ================= 3-term bf16 GEMM, 128x128 tile, 4 warps (64x64/warp) =====
// MODE 0: T^T[b][m][c1] = sum_c2 xT[m][c2] * M[c1][c2]     K=512
// MODE 1: logit[b][n][m] = sum_c1 xT[n][c1] * T^T[m][c1]   K=512
#define OFF_AH 0
#define OFF_AM 8192
#define OFF_BH 16384
#define OFF_BM 24576
#define STAGE_BYTES 32768
#define NSTAGE 3
#define SMEM_MAIN (NSTAGE * STAGE_BYTES)

template <int MODE>
__global__ __launch_bounds__(128, 2) void gemm3() {
    extern __shared__ __align__(128) char smem[];
    const uint32_t sbase = smem_u32(smem);
    const int tid = threadIdx.x;
    const int wid = tid >> 5, lane = tid & 31;
    const int b = blockIdx.z;
    const int nBase = blockIdx.x * 128;
    const int mBase = blockIdx.y * 128;
    const int wm = (wid >> 1) * 64, wn = (wid & 1) * 64;

    constexpr int NIT = 16;
    const size_t bXT = (size_t)b << 19;
    const size_t bQK = (size_t)b << 20;

    float acc[4][8][4];
#pragma unroll
    for (int i = 0; i < 4; i++)
#pragma unroll
        for (int j = 0; j < 8; j++)
#pragma unroll
            for (int k = 0; k < 4; k++) acc[i][j][k] = 0.f;

    auto issue_stage = [&](int stage, int kt) {
        const bf *pah, *pam, *pbh, *pbm;
        pah = g_xTh + bXT + (size_t)mBase * 512 + kt;
        pam = g_xTm + bXT + (size_t)mBase * 512 + kt;
        if (MODE == 0) {
            pbh = g_Mh + (size_t)nBase * 512 + kt;
            pbm = g_Mm + (size_t)nBase * 512 + kt;
        } else {
            pbh = g_Th + bXT + (size_t)nBase * 512 + kt;
            pbm = g_Tm + bXT + (size_t)nBase * 512 + kt;
        }
        const uint32_t sb = sbase + stage * STAGE_BYTES;
#pragma unroll
        for (int j = 0; j < 4; j++) {
            const int idx = tid + j * 128;          // 0..511
            const int row = idx >> 2, ch = idx & 3;
            const uint32_t d = sw_off(row, ch);
            const int s = row * 512 + ch * 8;
            cpa16(sb + OFF_AH + d, pah + s);
            cpa16(sb + OFF_AM + d, pam + s);
            cpa16(sb + OFF_BH + d, pbh + s);
            cpa16(sb + OFF_BM + d, pbm + s);
        }
        asm volatile("cp.async.commit_group;");
    };

    auto compute = [&](int stage) {
        const uint32_t base = sbase + stage * STAGE_BYTES;
        const int sel = lane >> 3;          // 0..3
#pragma unroll
        for (int k8 = 0; k8 < 2; k8++) {
            uint32_t bhf[8][2], bmf[8][2];
#pragma unroll
            for (int pr = 0; pr < 4; pr++) {
                const int nt = 2 * pr + (sel >> 1);
                const int kb = sel & 1;
                const uint32_t ra = base + OFF_BH + sw_off(wn + nt * 8 + (lane & 7), k8 * 2 + kb);
                uint32_t r[4];
                ldsm4(r, ra);
                bhf[2 * pr][0] = r[0]; bhf[2 * pr][1] = r[1];
                bhf[2 * pr + 1][0] = r[2]; bhf[2 * pr + 1][1] = r[3];
                ldsm4(r, ra + (OFF_BM - OFF_BH));
                bmf[2 * pr][0] = r[0]; bmf[2 * pr][1] = r[1];
                bmf[2 * pr + 1][0] = r[2]; bmf[2 * pr + 1][1] = r[3];
            }
#pragma unroll
            for (int mt = 0; mt < 4; mt++) {
                const uint32_t aa = base + OFF_AH +
                    sw_off(wm + mt * 16 + (sel & 1) * 8 + (lane & 7), k8 * 2 + (sel >> 1));
                uint32_t ah[4], am[4];
                ldsm4(ah, aa);
                ldsm4(am, aa + (OFF_AM - OFF_AH));
#pragma unroll
                for (int nt = 0; nt < 8; nt++) mma16816(acc[mt][nt], ah, bhf[nt]);
#pragma unroll
                for (int nt = 0; nt < 8; nt++) mma16816(acc[mt][nt], ah, bmf[nt]);
#pragma unroll
                for (int nt = 0; nt < 8; nt++) mma16816(acc[mt][nt], am, bhf[nt]);
            }
        }
    };

    issue_stage(0, 0);
    issue_stage(1, 32);
    for (int it = 0; it < NIT; it++) {
        if (it + 2 < NIT) asm volatile("cp.async.wait_group 1;");
        else              asm volatile("cp.async.wait_group 0;");
        __syncthreads();
        if (it + 2 < NIT) issue_stage((it + 2) % NSTAGE, (it + 2) * 32);
        compute(it % NSTAGE);
    }

    const int lr = lane >> 2, lc = 2 * (lane & 3);
#pragma unroll
    for (int mt = 0; mt < 4; mt++) {
#pragma unroll
        for (int nt = 0; nt < 8; nt++) {
            const int r0 = mBase + wm + mt * 16 + lr;
            const int c0 = nBase + wn + nt * 8 + lc;
            if (MODE == 0) {
                split_store(g_Th + bXT, g_Tm + bXT, (size_t)r0 * 512 + c0, acc[mt][nt][0], acc[mt][nt][1]);
                split_store(g_Th + bXT, g_Tm + bXT, (size_t)(r0 + 8) * 512 + c0, acc[mt][nt][2], acc[mt][nt][3]);
            } else {
                float2 v0; v0.x = acc[mt][nt][0]; v0.y = acc[mt][nt][1];
                float2 v1; v1.x = acc[mt][nt][2]; v1.y = acc[mt][nt][3];
                *reinterpret_cast<float2*>(g_logit + bQK + (size_t)r0 * 1024 + c0) = v0;
                *reinterpret_cast<float2*>(g_logit + bQK + (size_t)(r0 + 8) * 1024 + c0) = v1;
            }
        }
    }
}

// ================= P GEMM: P[b][r][m] = G[r][:] . xT[m][:]  (64x128 tile) ===
#define P_AH 0
#define P_AM 4096
#define P_BH 8192
#define P_BM 16384
#define P_STAGE 24576
#define SMEM_P (NSTAGE * P_STAGE)

__global__ __launch_bounds__(256, 2) void p_gemm() {
    extern __shared__ __align__(128) char smem[];
    const uint32_t sbase = smem_u32(smem);
    const int tid = threadIdx.x;
    const int wid = tid >> 5, lane = tid & 31;
    const int b = blockIdx.z;
    const int nBase = blockIdx.x * 128;
    const int wm = (wid >> 2) * 32, wn = (wid & 3) * 32;
    const size_t bXT = (size_t)b << 19;

    float acc[2][4][4];
#pragma unroll
    for (int i = 0; i < 2; i++)
#pragma unroll
        for (int j = 0; j < 4; j++)
#pragma unroll
            for (int k = 0; k < 4; k++) acc[i][j][k] = 0.f;

    auto issue_stage = [&](int stage, int kt) {
        const uint32_t sb = sbase + stage * P_STAGE;
        {
            const int row = tid >> 2, ch = tid & 3;
            const uint32_t d = sw_off(row, ch);
            const int s = row * 512 + kt + ch * 8;
            cpa16(sb + P_AH + d, g_Gh + s);
            cpa16(sb + P_AM + d, g_Gm + s);
        }
#pragma unroll
        for (int j = 0; j < 2; j++) {
            const int idx = tid + j * 256;
            const int row = idx >> 2, ch = idx & 3;
            const uint32_t d = sw_off(row, ch);
            const size_t s = bXT + (size_t)(nBase + row) * 512 + kt + ch * 8;
            cpa16(sb + P_BH + d, g_xTh + s);
            cpa16(sb + P_BM + d, g_xTm + s);
        }
        asm volatile("cp.async.commit_group;");
    };

    auto compute = [&](int stage) {
        const uint32_t base = sbase + stage * P_STAGE;
        const int sel = lane >> 3;
#pragma unroll
        for (int k8 = 0; k8 < 2; k8++) {
            uint32_t bhf[4][2], bmf[4][2];
#pragma unroll
            for (int pr = 0; pr < 2; pr++) {
                const int nt = 2 * pr + (sel >> 1);
                const int kb = sel & 1;
                const uint32_t ra = base + P_BH + sw_off(wn + nt * 8 + (lane & 7), k8 * 2 + kb);
                uint32_t r[4];
                ldsm4(r, ra);
                bhf[2 * pr][0] = r[0]; bhf[2 * pr][1] = r[1];
                bhf[2 * pr + 1][0] = r[2]; bhf[2 * pr + 1][1] = r[3];
                ldsm4(r, ra + (P_BM - P_BH));
                bmf[2 * pr][0] = r[0]; bmf[2 * pr][1] = r[1];
                bmf[2 * pr + 1][0] = r[2]; bmf[2 * pr + 1][1] = r[3];
            }
#pragma unroll
            for (int mt = 0; mt < 2; mt++) {
                const uint32_t aa = base + P_AH +
                    sw_off(wm + mt * 16 + (sel & 1) * 8 + (lane & 7), k8 * 2 + (sel >> 1));
                uint32_t ah[4], am[4];
                ldsm4(ah, aa);
                ldsm4(am, aa + (P_AM - P_AH));
#pragma unroll
                for (int nt = 0; nt < 4; nt++) mma16816(acc[mt][nt], ah, bhf[nt]);
#pragma unroll
                for (int nt = 0; nt < 4; nt++) mma16816(acc[mt][nt], ah, bmf[nt]);
#pragma unroll
                for (int nt = 0; nt < 4; nt++) mma16816(acc[mt][nt], am, bhf[nt]);
            }
        }
    };

    issue_stage(0, 0);
    issue_stage(1, 32);
    for (int it = 0; it < 16; it++) {
        if (it + 2 < 16) asm volatile("cp.async.wait_group 1;");
        else             asm volatile("cp.async.wait_group 0;");
        __syncthreads();
        if (it + 2 < 16) issue_stage((it + 2) % NSTAGE, (it + 2) * 32);
        compute(it % NSTAGE);
    }

    const int lr = lane >> 2, lc = 2 * (lane & 3);
    float* P = g_P + (size_t)b * 64 * 1024;
#pragma unroll
    for (int mt = 0; mt < 2; mt++) {
#pragma unroll
        for (int nt = 0; nt < 4; nt++) {
            const int r0 = wm + mt * 16 + lr;
            const int c0 = nBase + wn + nt * 8 + lc;
            float2 v0; v0.x = acc[mt][nt][0]; v0.y = acc[mt][nt][1];
            float2 v1; v1.x = acc[mt][nt][2]; v1.y = acc[mt][nt][3];
            *reinterpret_cast<float2*>(P + (size_t)r0 * 1024 + c0) = v0;
            *reinterpret_cast<float2*>(P + (size_t)(r0 + 8) * 1024 + c0) = v1;
        }
    }
}

// ======= v GEMM: fp16 2-term, 128x128 tile, 4 warps ========================
#define V_AH 0
#define V_AL 8192
#define V_B  16384
#define V_STAGE 24576
#define SMEM_V (NSTAGE * V_STAGE)

__global__ __launch_bounds__(128, 2) void v_gemm() {
    extern __shared__ __align__(128) char smem[];
    const uint32_t sbase = smem_u32(smem);
    const int tid = threadIdx.x;
    const int wid = tid >> 5, lane = tid & 31;
    const int b = blockIdx.z;
    const int nBase = blockIdx.x * 128;
    const int mBase = blockIdx.y * 128;
    const int wm = (wid >> 1) * 64, wn = (wid & 1) * 64;
    const size_t bXT = (size_t)b << 19;

    float acc[4][8][4];
#pragma unroll
    for (int i = 0; i < 4; i++)
#pragma unroll
        for (int j = 0; j < 8; j++)
#pragma unroll
            for (int k = 0; k < 4; k++) acc[i][j][k] = 0.f;

    auto issue_stage = [&](int stage, int kt) {
        const __half* pah = g_W16h + (size_t)mBase * 512 + kt;
        const __half* pal = g_W16l + (size_t)mBase * 512 + kt;
        const __half* pb  = g_xT16 + bXT + (size_t)nBase * 512 + kt;
        const uint32_t sb = sbase + stage * V_STAGE;
#pragma unroll
        for (int j = 0; j < 4; j++) {
            const int idx = tid + j * 128;
            const int row = idx >> 2, ch = idx & 3;
            const uint32_t d = sw_off(row, ch);
            const int s = row * 512 + ch * 8;
            cpa16(sb + V_AH + d, pah + s);
            cpa16(sb + V_AL + d, pal + s);
            cpa16(sb + V_B  + d, pb  + s);
        }
        asm volatile("cp.async.commit_group;");
    };

    auto compute = [&](int stage) {
        const uint32_t base = sbase + stage * V_STAGE;
        const int sel = lane >> 3;
#pragma unroll
        for (int k8 = 0; k8 < 2; k8++) {
            uint32_t bff[8][2];
#pragma unroll
            for (int pr = 0; pr < 4; pr++) {
                const int nt = 2 * pr + (sel >> 1);
                const int kb = sel & 1;
                uint32_t r[4];
                ldsm4(r, base + V_B + sw_off(wn + nt * 8 + (lane & 7), k8 * 2 + kb));
                bff[2 * pr][0] = r[0]; bff[2 * pr][1] = r[1];
                bff[2 * pr + 1][0] = r[2]; bff[2 * pr + 1][1] = r[3];
            }
#pragma unroll
            for (int mt = 0; mt < 4; mt++) {
                const uint32_t aa = base + V_AH +
                    sw_off(wm + mt * 16 + (sel & 1) * 8 + (lane & 7), k8 * 2 + (sel >> 1));
                uint32_t ah[4], al[4];
                ldsm4(ah, aa);
                ldsm4(al, aa + (V_AL - V_AH));
#pragma unroll
                for (int nt = 0; nt < 8; nt++) mma16816h(acc[mt][nt], ah, bff[nt]);
#pragma unroll
                for (int nt = 0; nt < 8; nt++) mma16816h(acc[mt][nt], al, bff[nt]);
            }
        }
    };

    issue_stage(0, 0);
    issue_stage(1, 32);
    for (int it = 0; it < 16; it++) {
        if (it + 2 < 16) asm volatile("cp.async.wait_group 1;");
        else             asm volatile("cp.async.wait_group 0;");
        __syncthreads();
        if (it + 2 < 16) issue_stage((it + 2) % NSTAGE, (it + 2) * 32);
        compute(it % NSTAGE);
    }

    const int lr = lane >> 2, lc = 2 * (lane & 3);
    __half* ov = g_v16 + bXT;
#pragma unroll
    for (int mt = 0; mt < 4; mt++) {
#pragma unroll
        for (int nt = 0; nt < 8; nt++) {
            const int r0 = mBase + wm + mt * 16 + lr;
            const int c0 = nBase + wn + nt * 8 + lc;
            __half2 h0; h0.x = __float2half_rn(acc[mt][nt][0]); h0.y = __float2half_rn(acc[mt][nt][1]);
            __half2 h1; h1.x = __float2half_rn(acc[mt][nt][2]); h1.y = __float2half_rn(acc[mt][nt][3]);
            *reinterpret_cast<__half2*>(ov + (size_t)r0 * 1024 + c0) = h0;
            *reinterpret_cast<__half2*>(ov + (size_t)(r0 + 8) * 1024 + c0) = h1;
        }
    }
}

// ======= out GEMM: fp16 single-term, 128x128 tile, 4 warps ==================
#define U_A  0
#define U_B  8192
#define U_STAGE 16384
#define SMEM_U (NSTAGE * U_STAGE)

__global__ __launch_bounds__(128, 2) void out_gemm(float* __restrict__ outp) {
    extern __shared__ __align__(128) char smem[];
    const uint32_t sbase = smem_u32(smem);
    const int tid = threadIdx.x;
    const int wid = tid >> 5, lane = tid & 31;
    const int b = blockIdx.z;
    const int nBase = blockIdx.x * 128;
    const int mBase = blockIdx.y * 128;
    const int wm = (wid >> 1) * 64, wn = (wid & 1) * 64;
    const size_t bQK = (size_t)b << 20;
    const size_t bXT = (size_t)b << 19;

    float acc[4][8][4];
#pragma unroll
    for (int i = 0; i < 4; i++)
#pragma unroll
        for (int j = 0; j < 8; j++)
#pragma unroll
            for (int k = 0; k < 4; k++) acc[i][j][k] = 0.f;

    auto issue_stage = [&](int stage, int kt) {
        const __half* pa = g_v16 + bXT + (size_t)mBase * 1024 + kt;
        const __half* pb = g_att16 + bQK + (size_t)nBase * 1024 + kt;
        const uint32_t sb = sbase + stage * U_STAGE;
#pragma unroll
        for (int j = 0; j < 4; j++) {
            const int idx = tid + j * 128;
            const int row = idx >> 2, ch = idx & 3;
            const uint32_t d = sw_off(row, ch);
            const int s = row * 1024 + ch * 8;
            cpa16(sb + U_A + d, pa + s);
            cpa16(sb + U_B + d, pb + s);
        }
        asm volatile("cp.async.commit_group;");
    };

    auto compute = [&](int stage) {
        const uint32_t base = sbase + stage * U_STAGE;
        const int sel = lane >> 3;
#pragma unroll
        for (int k8 = 0; k8 < 2; k8++) {
            uint32_t bff[8][2];
#pragma unroll
            for (int pr = 0; pr < 4; pr++) {
                const int nt = 2 * pr + (sel >> 1);
                const int kb = sel & 1;
                uint32_t r[4];
                ldsm4(r, base + U_B + sw_off(wn + nt * 8 + (lane & 7), k8 * 2 + kb));
                bff[2 * pr][0] = r[0]; bff[2 * pr][1] = r[1];
                bff[2 * pr + 1][0] = r[2]; bff[2 * pr + 1][1] = r[3];
            }
#pragma unroll
            for (int mt = 0; mt < 4; mt++) {
                const uint32_t aa = base + U_A +
                    sw_off(wm + mt * 16 + (sel & 1) * 8 + (lane & 7), k8 * 2 + (sel >> 1));
                uint32_t ah[4];
                ldsm4(ah, aa);
#pragma unroll
                for (int nt = 0; nt < 8; nt++) mma16816h(acc[mt][nt], ah, bff[nt]);
            }
        }
    };

    issue_stage(0, 0);
    issue_stage(1, 32);
    for (int it = 0; it < 32; it++) {
        if (it + 2 < 32) asm volatile("cp.async.wait_group 1;");
        else             asm volatile("cp.async.wait_group 0;");
        __syncthreads();
        if (it + 2 < 32) issue_stage((it + 2) % NSTAGE, (it + 2) * 32);
        compute(it % NSTAGE);
    }

    const int lr = lane >> 2, lc = 2 * (lane & 3);
    float* of = outp + bXT;
#pragma unroll
    for (int mt = 0; mt < 4; mt++) {
#pragma unroll
        for (int nt = 0; nt < 8; nt++) {
            const int r0 = mBase + wm + mt * 16 + lr;
            const int c0 = nBase + wn + nt * 8 + lc;
            float2 v0; v0.x = acc[mt][nt][0]; v0.y = acc[mt][nt][1];
            float2 v1; v1.x = acc[mt][nt][2]; v1.y = acc[mt][nt][3];
            *reinterpret_cast<float2*>(of + (size_t)r0 * 1024 + c0) = v0;
            *reinterpret_cast<float2*>(of + (size_t)(r0 + 8) * 1024 + c0) = v1;
        }
    }
}

// ---------------- small fp32 GEMM for M and G precompute --------------------
template <int IS_G>
__global__ __launch_bounds__(256) void sgemm_split() {
    const float* A = IS_G ? g_rhw : g_WT;
    const int lda = IS_G ? 512 : 1536;
    const float* B = IS_G ? g_WT : (g_WT + 512);
    const int ldb = 1536;
    bf* Ch = IS_G ? g_Gh : g_Mh;
    bf* Cm = IS_G ? g_Gm : g_Mm;

    __shared__ float As[16][72];
    __shared__ float Bs[16][72];
    const int tid = threadIdx.x;
    const int tx = tid & 15, ty = tid >> 4;
    const int rBase = blockIdx.y * 64, cBase = blockIdx.x * 64;

    float acc[4][4];
#pragma unroll
    for (int i = 0; i < 4; i++)
#pragma unroll
        for (int j = 0; j < 4; j++) acc[i][j] = 0.f;

    for (int kt = 0; kt < 512; kt += 16) {
        const int row = tid >> 2, q = (tid & 3) * 4;
        float4 va = *(const float4*)&A[(size_t)(rBase + row) * lda + kt + q];
        As[q + 0][row] = va.x; As[q + 1][row] = va.y;
        As[q + 2][row] = va.z; As[q + 3][row] = va.w;
        float4 vb = *(const float4*)&B[(size_t)(cBase + row) * ldb + kt + q];
        Bs[q + 0][row] = vb.x; Bs[q + 1][row] = vb.y;
        Bs[q + 2][row] = vb.z; Bs[q + 3][row] = vb.w;
        __syncthreads();
#pragma unroll
        for (int k = 0; k < 16; k++) {
            float a[4], bb[4];
            *(float4*)&a[0]  = *(const float4*)&As[k][ty * 4];
            *(float4*)&bb[0] = *(const float4*)&Bs[k][tx * 4];
#pragma unroll
            for (int i = 0; i < 4; i++)
#pragma unroll
                for (int j = 0; j < 4; j++) acc[i][j] += a[i] * bb[j];
        }
        __syncthreads();
    }
#pragma unroll
    for (int i = 0; i < 4; i++) {
        const int row = rBase + ty * 4 + i;
        const int col = cBase + tx * 4;
        split_store(Ch, Cm, (size_t)row * 512 + col, acc[i][0], acc[i][1]);
        split_store(Ch, Cm, (size_t)row * 512 + col + 2, acc[i][2], acc[i][3]);
    }
}

// ---------------- prep kernels ----------------------------------------------
__global__ void transpose_w(const float* __restrict__ W) {
    __shared__ float t[32][33];
    int o0 = blockIdx.x * 32, c0 = blockIdx.y * 32;
    int tx = threadIdx.x, ty = threadIdx.y;
#pragma unroll
    for (int j = 0; j < 32; j += 8)
        t[ty + j][tx] = W[(size_t)(o0 + ty + j) * 512 + c0 + tx];
    __syncthreads();
#pragma unroll
    for (int j = 0; j < 32; j += 8)
        g_WT[(size_t)(c0 + ty + j) * 1536 + o0 + tx] = t[tx][ty + j];
}

__global__ void prep_rhw(const float* __restrict__ rel_h, const float* __restrict__ rel_w) {
    int idx = blockIdx.x * blockDim.x + threadIdx.x;
    if (idx >= 64 * 512) return;
    int r = idx >> 9, c = idx & 511;
    g_rhw[idx] = (r < 32) ? rel_h[c * 32 + r] : rel_w[c * 32 + (r - 32)];
}

__global__ void prep_w16(const float* __restrict__ W) {
    int idx = blockIdx.x * blockDim.x + threadIdx.x;
    if (idx >= 512 * 512) return;
    int cv = idx >> 9, c = idx & 511;
    float v = W[(size_t)(1024 + cv) * 512 + c];
    __half h = __float2half_rn(v);
    g_W16h[idx] = h;
    g_W16l[idx] = __float2half_rn(v - __half2float(h));
}

__global__ void transpose_x(const float* __restrict__ x) {
    __shared__ float t[32][33];
    int b = blockIdx.z;
    int n0 = blockIdx.x * 32, c0 = blockIdx.y * 32;
    const float* src = x + (size_t)b * CDIM * NTOK;
    size_t dbase = (size_t)b * NTOK * CDIM;
    int tx = threadIdx.x, ty = threadIdx.y;
#pragma unroll
    for (int j = 0; j < 32; j += 8)
        t[ty + j][tx] = src[(size_t)(c0 + ty + j) * NTOK + n0 + tx];
    __syncthreads();
#pragma unroll
    for (int j = 0; j < 32; j += 8) {
        float v = t[tx][ty + j];
        size_t off = dbase + (size_t)(n0 + ty + j) * CDIM + c0 + tx;
        bf h = __float2bfloat16(v);
        g_xTh[off] = h;
        g_xTm[off] = __float2bfloat16(v - __bfloat162float(h));
        g_xT16[off] = __float2half_rn(v);
    }
}

// softmax over m with fused pos-bias; writes fp16 att
__global__ __launch_bounds__(256) void softmax_bias() {
    size_t row = blockIdx.x;
    int b = (int)(row >> 10);
    int n = (int)(row & 1023);
    int h = n >> 5, w = n & 31;
    const float* p  = g_logit + row * NTOK;
    const float* ph = g_P + ((size_t)b * 64 + h) * 1024;
    const float* pw = g_P + ((size_t)b * 64 + 32 + w) * 1024;
    int tid = threadIdx.x;

    float4 v = *(const float4*)&p[tid * 4];
    float4 bh = *(const float4*)&ph[tid * 4];
    float4 bw = *(const float4*)&pw[tid * 4];
    v.x += bh.x + bw.x; v.y += bh.y + bw.y;
    v.z += bh.z + bw.z; v.w += bh.w + bw.w;

    float m = fmaxf(fmaxf(v.x, v.y), fmaxf(v.z, v.w));
#pragma unroll
    for (int o = 16; o; o >>= 1) m = fmaxf(m, __shfl_xor_sync(~0u, m, o));
    __shared__ float red[8];
    if ((tid & 31) == 0) red[tid >> 5] = m;
    __syncthreads();
    float bm = red[0];
#pragma unroll
    for (int i = 1; i < 8; i++) bm = fmaxf(bm, red[i]);
    __syncthreads();

    v.x = __expf(v.x - bm); v.y = __expf(v.y - bm);
    v.z = __expf(v.z - bm); v.w = __expf(v.w - bm);
    float s = v.x + v.y + v.z + v.w;
#pragma unroll
    for (int o = 16; o; o >>= 1) s += __shfl_xor_sync(~0u, s, o);
    if ((tid & 31) == 0) red[tid >> 5] = s;
    __syncthreads();
    float bs = 0.f;
#pragma unroll
    for (int i = 0; i < 8; i++) bs += red[i];
    float inv = 1.0f / bs;

    __half2 a0; a0.x = __float2half_rn(v.x * inv); a0.y = __float2half_rn(v.y * inv);
    __half2 a1; a1.x = __float2half_rn(v.z * inv); a1.y = __float2half_rn(v.w * inv);
    size_t off = row * NTOK + tid * 4;
    *reinterpret_cast<__half2*>(g_att16 + off) = a0;
    *reinterpret_cast<__half2*>(g_att16 + off + 2) = a1;
}

// ---------------------------------------------------------------------------
extern "C" void kernel_launch(void* const* d_in, const int* in_sizes, int n_in,
                              void* d_out, int out_size) {
    const float* x     = (const float*)d_in[0];
    const float* Wmat  = (const float*)d_in[1];
    const float* rel_h = (const float*)d_in[2];
    const float* rel_w = (const float*)d_in[3];
    float* out = (float*)d_out;

    cudaFuncSetAttribute(gemm3<0>, cudaFuncAttributeMaxDynamicSharedMemorySize, SMEM_MAIN);
    cudaFuncSetAttribute(gemm3<1>, cudaFuncAttributeMaxDynamicSharedMemorySize, SMEM_MAIN);
    cudaFuncSetAttribute(p_gemm,   cudaFuncAttributeMaxDynamicSharedMemorySize, SMEM_P);
    cudaFuncSetAttribute(v_gemm,   cudaFuncAttributeMaxDynamicSharedMemorySize, SMEM_V);
    cudaFuncSetAttribute(out_gemm, cudaFuncAttributeMaxDynamicSharedMemorySize, SMEM_U);

    transpose_w<<<dim3(48, 16), dim3(32, 8)>>>(Wmat);
    prep_rhw<<<(64 * 512 + 255) / 256, 256>>>(rel_h, rel_w);
    prep_w16<<<(512 * 512 + 255) / 256, 256>>>(Wmat);
    transpose_x<<<dim3(32, 16, 64), dim3(32, 8)>>>(x);

    sgemm_split<0><<<dim3(8, 8), 256>>>();     // M = Wq^T Wk
    sgemm_split<1><<<dim3(8, 1), 256>>>();     // G = RHW * Wq

    gemm3<0><<<dim3(4, 8, 64), 128, SMEM_MAIN>>>();   // T^T = xT . M
    gemm3<1><<<dim3(8, 8, 64), 128, SMEM_MAIN>>>();   // logits = xT . T^T
    p_gemm<<<dim3(8, 1, 64), 256, SMEM_P>>>();        // P = G . xT
    v_gemm<<<dim3(8, 4, 64), 128, SMEM_V>>>();        // v fp16
    softmax_bias<<<BATCH * NTOK, 256>>>();            // att fp16
    out_gemm<<<dim3(8, 4, 64), 128, SMEM_U>>>(out);   // out = v . att
}

// round 9
// speedup vs baseline: 5.3352x; 1.0659x over previous
#include <cuda_runtime.h>
#include <cuda_bf16.h>
#include <cuda_fp16.h>
#include <cstdint>

#define BATCH 64
#define CDIM  512
#define NTOK  1024

typedef __nv_bfloat16 bf;

// ---------------- scratch (device globals) ----------------------------------
__device__ float g_WT [(size_t)512 * 1536];            // [c][o] = W[o][c]
__device__ float g_rhw[(size_t)64 * 512];              // [r][c] fp32
__device__ bf g_Mh[(size_t)512 * 512];                 // M = Wq^T Wk
__device__ bf g_Mm[(size_t)512 * 512];
__device__ bf g_Gh[(size_t)64 * 512];                  // G = RHW * Wq
__device__ bf g_Gm[(size_t)64 * 512];
__device__ bf g_xTh[(size_t)BATCH * NTOK * CDIM];      // [b][n][c]
__device__ bf g_xTm[(size_t)BATCH * NTOK * CDIM];
__device__ __half g_xT16[(size_t)BATCH * NTOK * CDIM];
__device__ __half g_W16h[(size_t)512 * 512];           // Wv fp16  [cv][c]
__device__ bf g_Th[(size_t)BATCH * NTOK * 512];        // T^T [b][m][c1]
__device__ bf g_Tm[(size_t)BATCH * NTOK * 512];
__device__ float  g_logit[(size_t)BATCH * NTOK * NTOK];
__device__ float  g_P[(size_t)BATCH * 64 * NTOK];
__device__ __half g_v16[(size_t)BATCH * CDIM * NTOK];  // [b][c][n]
__device__ __half g_att16[(size_t)BATCH * NTOK * NTOK];

// ---------------- PTX helpers ----------------------------------------------
__device__ __forceinline__ uint32_t smem_u32(const void* p) {
    uint32_t a;
    asm("{ .reg .u64 t; cvta.to.shared.u64 t, %1; cvt.u32.u64 %0, t; }" : "=r"(a) : "l"(p));
    return a;
}
__device__ __forceinline__ void cpa16(uint32_t dst, const void* src) {
    asm volatile("cp.async.cg.shared.global [%0], [%1], 16;" :: "r"(dst), "l"(src));
}
__device__ __forceinline__ void ldsm4(uint32_t r[4], uint32_t addr) {
    asm volatile("ldmatrix.sync.aligned.m8n8.x4.shared.b16 {%0,%1,%2,%3}, [%4];"
                 : "=r"(r[0]), "=r"(r[1]), "=r"(r[2]), "=r"(r[3]) : "r"(addr));
}
__device__ __forceinline__ void mma16816(float c[4], const uint32_t a[4], const uint32_t b[2]) {
    asm volatile("mma.sync.aligned.m16n8k16.row.col.f32.bf16.bf16.f32 "
                 "{%0,%1,%2,%3}, {%4,%5,%6,%7}, {%8,%9}, {%0,%1,%2,%3};"
                 : "+f"(c[0]), "+f"(c[1]), "+f"(c[2]), "+f"(c[3])
                 : "r"(a[0]), "r"(a[1]), "r"(a[2]), "r"(a[3]), "r"(b[0]), "r"(b[1]));
}
__device__ __forceinline__ void mma16816h(float c[4], const uint32_t a[4], const uint32_t b[2]) {
    asm volatile("mma.sync.aligned.m16n8k16.row.col.f32.f16.f16.f32 "
                 "{%0,%1,%2,%3}, {%4,%5,%6,%7}, {%8,%9}, {%0,%1,%2,%3};"
                 : "+f"(c[0]), "+f"(c[1]), "+f"(c[2]), "+f"(c[3])
                 : "r"(a[0]), "r"(a[1]), "r"(a[2]), "r"(a[3]), "r"(b[0]), "r"(b[1]));
}
__device__ __forceinline__ uint32_t sw_off(int row, int chunk) {
    return (uint32_t)(row * 64 + ((chunk ^ ((row >> 1) & 3)) << 4));
}
__device__ __forceinline__ void split_store(bf* __restrict__ ph, bf* __restrict__ pm,
                                            size_t off, float v0, float v1) {
    bf h0 = __float2bfloat16(v0), h1 = __float2bfloat16(v1);
    bf m0 = __float2bfloat16(v0 - __bfloat162float(h0));
    bf m1 = __float2bfloat16(v1 - __bfloat162float(h1));
    __nv_bfloat162 hh; hh.x = h0; hh.y = h1;
    __nv_bfloat162 mm; mm.x = m0; mm.y = m1;
    *reinterpret_cast<__nv_bfloat162*>(ph + off) = hh;
    *reinterpret_cast<__nv_bfloat162*>(pm + off) = mm;
}

// ================= 3-term bf16 GEMM, 128x128 tile, 4 warps (64x64/warp) =====
// MODE 0: T^T[b][m][c1] = sum_c2 xT[m][c2] * M[c1][c2]     K=512
// MODE 1: logit[b][n][m] = sum_c1 xT[n][c1] * T^T[m][c1]   K=512
#define OFF_AH 0
#define OFF_AM 8192
#define OFF_BH 16384
#define OFF_BM 24576
#define STAGE_BYTES 32768
#define NSTAGE 3
#define SMEM_MAIN (NSTAGE * STAGE_BYTES)

template <int MODE>
__global__ __launch_bounds__(128, 2) void gemm3() {
    extern __shared__ __align__(128) char smem[];
    const uint32_t sbase = smem_u32(smem);
    const int tid = threadIdx.x;
    const int wid = tid >> 5, lane = tid & 31;
    const int b = blockIdx.z;
    const int nBase = blockIdx.x * 128;
    const int mBase = blockIdx.y * 128;
    const int wm = (wid >> 1) * 64, wn = (wid & 1) * 64;

    constexpr int NIT = 16;
    const size_t bXT = (size_t)b << 19;
    const size_t bQK = (size_t)b << 20;

    float acc[4][8][4];
#pragma unroll
    for (int i = 0; i < 4; i++)
#pragma unroll
        for (int j = 0; j < 8; j++)
#pragma unroll
            for (int k = 0; k < 4; k++) acc[i][j][k] = 0.f;

    auto issue_stage = [&](int stage, int kt) {
        const bf *pah, *pam, *pbh, *pbm;
        pah = g_xTh + bXT + (size_t)mBase * 512 + kt;
        pam = g_xTm + bXT + (size_t)mBase * 512 + kt;
        if (MODE == 0) {
            pbh = g_Mh + (size_t)nBase * 512 + kt;
            pbm = g_Mm + (size_t)nBase * 512 + kt;
        } else {
            pbh = g_Th + bXT + (size_t)nBase * 512 + kt;
            pbm = g_Tm + bXT + (size_t)nBase * 512 + kt;
        }
        const uint32_t sb = sbase + stage * STAGE_BYTES;
#pragma unroll
        for (int j = 0; j < 4; j++) {
            const int idx = tid + j * 128;          // 0..511
            const int row = idx >> 2, ch = idx & 3;
            const uint32_t d = sw_off(row, ch);
            const int s = row * 512 + ch * 8;
            cpa16(sb + OFF_AH + d, pah + s);
            cpa16(sb + OFF_AM + d, pam + s);
            cpa16(sb + OFF_BH + d, pbh + s);
            cpa16(sb + OFF_BM + d, pbm + s);
        }
        asm volatile("cp.async.commit_group;");
    };

    auto compute = [&](int stage) {
        const uint32_t base = sbase + stage * STAGE_BYTES;
        const int sel = lane >> 3;          // 0..3
#pragma unroll
        for (int k8 = 0; k8 < 2; k8++) {
            uint32_t bhf[8][2], bmf[8][2];
#pragma unroll
            for (int pr = 0; pr < 4; pr++) {
                const int nt = 2 * pr + (sel >> 1);
                const int kb = sel & 1;
                const uint32_t ra = base + OFF_BH + sw_off(wn + nt * 8 + (lane & 7), k8 * 2 + kb);
                uint32_t r[4];
                ldsm4(r, ra);
                bhf[2 * pr][0] = r[0]; bhf[2 * pr][1] = r[1];
                bhf[2 * pr + 1][0] = r[2]; bhf[2 * pr + 1][1] = r[3];
                ldsm4(r, ra + (OFF_BM - OFF_BH));
                bmf[2 * pr][0] = r[0]; bmf[2 * pr][1] = r[1];
                bmf[2 * pr + 1][0] = r[2]; bmf[2 * pr + 1][1] = r[3];
            }
#pragma unroll
            for (int mt = 0; mt < 4; mt++) {
                const uint32_t aa = base + OFF_AH +
                    sw_off(wm + mt * 16 + (sel & 1) * 8 + (lane & 7), k8 * 2 + (sel >> 1));
                uint32_t ah[4], am[4];
                ldsm4(ah, aa);
                ldsm4(am, aa + (OFF_AM - OFF_AH));
#pragma unroll
                for (int nt = 0; nt < 8; nt++) mma16816(acc[mt][nt], ah, bhf[nt]);
#pragma unroll
                for (int nt = 0; nt < 8; nt++) mma16816(acc[mt][nt], ah, bmf[nt]);
#pragma unroll
                for (int nt = 0; nt < 8; nt++) mma16816(acc[mt][nt], am, bhf[nt]);
            }
        }
    };

    issue_stage(0, 0);
    issue_stage(1, 32);
    for (int it = 0; it < NIT; it++) {
        if (it + 2 < NIT) asm volatile("cp.async.wait_group 1;");
        else              asm volatile("cp.async.wait_group 0;");
        __syncthreads();
        if (it + 2 < NIT) issue_stage((it + 2) % NSTAGE, (it + 2) * 32);
        compute(it % NSTAGE);
    }

    const int lr = lane >> 2, lc = 2 * (lane & 3);
#pragma unroll
    for (int mt = 0; mt < 4; mt++) {
#pragma unroll
        for (int nt = 0; nt < 8; nt++) {
            const int r0 = mBase + wm + mt * 16 + lr;
            const int c0 = nBase + wn + nt * 8 + lc;
            if (MODE == 0) {
                split_store(g_Th + bXT, g_Tm + bXT, (size_t)r0 * 512 + c0, acc[mt][nt][0], acc[mt][nt][1]);
                split_store(g_Th + bXT, g_Tm + bXT, (size_t)(r0 + 8) * 512 + c0, acc[mt][nt][2], acc[mt][nt][3]);
            } else {
                float2 v0; v0.x = acc[mt][nt][0]; v0.y = acc[mt][nt][1];
                float2 v1; v1.x = acc[mt][nt][2]; v1.y = acc[mt][nt][3];
                *reinterpret_cast<float2*>(g_logit + bQK + (size_t)r0 * 1024 + c0) = v0;
                *reinterpret_cast<float2*>(g_logit + bQK + (size_t)(r0 + 8) * 1024 + c0) = v1;
            }
        }
    }
}

// ================= P GEMM: P[b][r][m] = G[r][:] . xT[m][:]  (64x128 tile) ===
#define P_AH 0
#define P_AM 4096
#define P_BH 8192
#define P_BM 16384
#define P_STAGE 24576
#define SMEM_P (NSTAGE * P_STAGE)

__global__ __launch_bounds__(256, 2) void p_gemm() {
    extern __shared__ __align__(128) char smem[];
    const uint32_t sbase = smem_u32(smem);
    const int tid = threadIdx.x;
    const int wid = tid >> 5, lane = tid & 31;
    const int b = blockIdx.z;
    const int nBase = blockIdx.x * 128;
    const int wm = (wid >> 2) * 32, wn = (wid & 3) * 32;
    const size_t bXT = (size_t)b << 19;

    float acc[2][4][4];
#pragma unroll
    for (int i = 0; i < 2; i++)
#pragma unroll
        for (int j = 0; j < 4; j++)
#pragma unroll
            for (int k = 0; k < 4; k++) acc[i][j][k] = 0.f;

    auto issue_stage = [&](int stage, int kt) {
        const uint32_t sb = sbase + stage * P_STAGE;
        {
            const int row = tid >> 2, ch = tid & 3;
            const uint32_t d = sw_off(row, ch);
            const int s = row * 512 + kt + ch * 8;
            cpa16(sb + P_AH + d, g_Gh + s);
            cpa16(sb + P_AM + d, g_Gm + s);
        }
#pragma unroll
        for (int j = 0; j < 2; j++) {
            const int idx = tid + j * 256;
            const int row = idx >> 2, ch = idx & 3;
            const uint32_t d = sw_off(row, ch);
            const size_t s = bXT + (size_t)(nBase + row) * 512 + kt + ch * 8;
            cpa16(sb + P_BH + d, g_xTh + s);
            cpa16(sb + P_BM + d, g_xTm + s);
        }
        asm volatile("cp.async.commit_group;");
    };

    auto compute = [&](int stage) {
        const uint32_t base = sbase + stage * P_STAGE;
        const int sel = lane >> 3;
#pragma unroll
        for (int k8 = 0; k8 < 2; k8++) {
            uint32_t bhf[4][2], bmf[4][2];
#pragma unroll
            for (int pr = 0; pr < 2; pr++) {
                const int nt = 2 * pr + (sel >> 1);
                const int kb = sel & 1;
                const uint32_t ra = base + P_BH + sw_off(wn + nt * 8 + (lane & 7), k8 * 2 + kb);
                uint32_t r[4];
                ldsm4(r, ra);
                bhf[2 * pr][0] = r[0]; bhf[2 * pr][1] = r[1];
                bhf[2 * pr + 1][0] = r[2]; bhf[2 * pr + 1][1] = r[3];
                ldsm4(r, ra + (P_BM - P_BH));
                bmf[2 * pr][0] = r[0]; bmf[2 * pr][1] = r[1];
                bmf[2 * pr + 1][0] = r[2]; bmf[2 * pr + 1][1] = r[3];
            }
#pragma unroll
            for (int mt = 0; mt < 2; mt++) {
                const uint32_t aa = base + P_AH +
                    sw_off(wm + mt * 16 + (sel & 1) * 8 + (lane & 7), k8 * 2 + (sel >> 1));
                uint32_t ah[4], am[4];
                ldsm4(ah, aa);
                ldsm4(am, aa + (P_AM - P_AH));
#pragma unroll
                for (int nt = 0; nt < 4; nt++) mma16816(acc[mt][nt], ah, bhf[nt]);
#pragma unroll
                for (int nt = 0; nt < 4; nt++) mma16816(acc[mt][nt], ah, bmf[nt]);
#pragma unroll
                for (int nt = 0; nt < 4; nt++) mma16816(acc[mt][nt], am, bhf[nt]);
            }
        }
    };

    issue_stage(0, 0);
    issue_stage(1, 32);
    for (int it = 0; it < 16; it++) {
        if (it + 2 < 16) asm volatile("cp.async.wait_group 1;");
        else             asm volatile("cp.async.wait_group 0;");
        __syncthreads();
        if (it + 2 < 16) issue_stage((it + 2) % NSTAGE, (it + 2) * 32);
        compute(it % NSTAGE);
    }

    const int lr = lane >> 2, lc = 2 * (lane & 3);
    float* P = g_P + (size_t)b * 64 * 1024;
#pragma unroll
    for (int mt = 0; mt < 2; mt++) {
#pragma unroll
        for (int nt = 0; nt < 4; nt++) {
            const int r0 = wm + mt * 16 + lr;
            const int c0 = nBase + wn + nt * 8 + lc;
            float2 v0; v0.x = acc[mt][nt][0]; v0.y = acc[mt][nt][1];
            float2 v1; v1.x = acc[mt][nt][2]; v1.y = acc[mt][nt][3];
            *reinterpret_cast<float2*>(P + (size_t)r0 * 1024 + c0) = v0;
            *reinterpret_cast<float2*>(P + (size_t)(r0 + 8) * 1024 + c0) = v1;
        }
    }
}

// ======= fp16 single-term GEMM: 128x128 tile, 4 warps =======================
// MODE 0: v[b][c][n]   = W16h[c][:] . xT16[n][:]    K=512,  out half
// MODE 1: out[b][c][n] = v16[c][:] . att16[n][:]    K=1024, out fp32
#define U_A  0
#define U_B  8192
#define U_STAGE 16384
#define SMEM_U (NSTAGE * U_STAGE)

template <int MODE>
__global__ __launch_bounds__(128, 2) void h1_gemm(float* __restrict__ outp) {
    extern __shared__ __align__(128) char smem[];
    const uint32_t sbase = smem_u32(smem);
    const int tid = threadIdx.x;
    const int wid = tid >> 5, lane = tid & 31;
    const int b = blockIdx.z;
    const int nBase = blockIdx.x * 128;
    const int mBase = blockIdx.y * 128;
    const int wm = (wid >> 1) * 64, wn = (wid & 1) * 64;
    const size_t bQK = (size_t)b << 20;
    const size_t bXT = (size_t)b << 19;

    constexpr int NIT = (MODE == 0) ? 16 : 32;
    constexpr int LD  = (MODE == 0) ? 512 : 1024;

    float acc[4][8][4];
#pragma unroll
    for (int i = 0; i < 4; i++)
#pragma unroll
        for (int j = 0; j < 8; j++)
#pragma unroll
            for (int k = 0; k < 4; k++) acc[i][j][k] = 0.f;

    auto issue_stage = [&](int stage, int kt) {
        const __half *pa, *pb;
        if (MODE == 0) {
            pa = g_W16h + (size_t)mBase * 512 + kt;
            pb = g_xT16 + bXT + (size_t)nBase * 512 + kt;
        } else {
            pa = g_v16 + bXT + (size_t)mBase * 1024 + kt;
            pb = g_att16 + bQK + (size_t)nBase * 1024 + kt;
        }
        const uint32_t sb = sbase + stage * U_STAGE;
#pragma unroll
        for (int j = 0; j < 4; j++) {
            const int idx = tid + j * 128;
            const int row = idx >> 2, ch = idx & 3;
            const uint32_t d = sw_off(row, ch);
            const int s = row * LD + ch * 8;
            cpa16(sb + U_A + d, pa + s);
            cpa16(sb + U_B + d, pb + s);
        }
        asm volatile("cp.async.commit_group;");
    };

    auto compute = [&](int stage) {
        const uint32_t base = sbase + stage * U_STAGE;
        const int sel = lane >> 3;
#pragma unroll
        for (int k8 = 0; k8 < 2; k8++) {
            uint32_t bff[8][2];
#pragma unroll
            for (int pr = 0; pr < 4; pr++) {
                const int nt = 2 * pr + (sel >> 1);
                const int kb = sel & 1;
                uint32_t r[4];
                ldsm4(r, base + U_B + sw_off(wn + nt * 8 + (lane & 7), k8 * 2 + kb));
                bff[2 * pr][0] = r[0]; bff[2 * pr][1] = r[1];
                bff[2 * pr + 1][0] = r[2]; bff[2 * pr + 1][1] = r[3];
            }
#pragma unroll
            for (int mt = 0; mt < 4; mt++) {
                const uint32_t aa = base + U_A +
                    sw_off(wm + mt * 16 + (sel & 1) * 8 + (lane & 7), k8 * 2 + (sel >> 1));
                uint32_t ah[4];
                ldsm4(ah, aa);
#pragma unroll
                for (int nt = 0; nt < 8; nt++) mma16816h(acc[mt][nt], ah, bff[nt]);
            }
        }
    };

    issue_stage(0, 0);
    issue_stage(1, 32);
    for (int it = 0; it < NIT; it++) {
        if (it + 2 < NIT) asm volatile("cp.async.wait_group 1;");
        else              asm volatile("cp.async.wait_group 0;");
        __syncthreads();
        if (it + 2 < NIT) issue_stage((it + 2) % NSTAGE, (it + 2) * 32);
        compute(it % NSTAGE);
    }

    const int lr = lane >> 2, lc = 2 * (lane & 3);
#pragma unroll
    for (int mt = 0; mt < 4; mt++) {
#pragma unroll
        for (int nt = 0; nt < 8; nt++) {
            const int r0 = mBase + wm + mt * 16 + lr;
            const int c0 = nBase + wn + nt * 8 + lc;
            if (MODE == 0) {
                __half* ov = g_v16 + bXT;
                __half2 h0; h0.x = __float2half_rn(acc[mt][nt][0]); h0.y = __float2half_rn(acc[mt][nt][1]);
                __half2 h1; h1.x = __float2half_rn(acc[mt][nt][2]); h1.y = __float2half_rn(acc[mt][nt][3]);
                *reinterpret_cast<__half2*>(ov + (size_t)r0 * 1024 + c0) = h0;
                *reinterpret_cast<__half2*>(ov + (size_t)(r0 + 8) * 1024 + c0) = h1;
            } else {
                float* of = outp + bXT;
                float2 v0; v0.x = acc[mt][nt][0]; v0.y = acc[mt][nt][1];
                float2 v1; v1.x = acc[mt][nt][2]; v1.y = acc[mt][nt][3];
                *reinterpret_cast<float2*>(of + (size_t)r0 * 1024 + c0) = v0;
                *reinterpret_cast<float2*>(of + (size_t)(r0 + 8) * 1024 + c0) = v1;
            }
        }
    }
}

// ---------------- small fp32 GEMM for M and G precompute --------------------
template <int IS_G>
__global__ __launch_bounds__(256) void sgemm_split() {
    const float* A = IS_G ? g_rhw : g_WT;
    const int lda = IS_G ? 512 : 1536;
    const float* B = IS_G ? g_WT : (g_WT + 512);
    const int ldb = 1536;
    bf* Ch = IS_G ? g_Gh : g_Mh;
    bf* Cm = IS_G ? g_Gm : g_Mm;

    __shared__ float As[16][72];
    __shared__ float Bs[16][72];
    const int tid = threadIdx.x;
    const int tx = tid & 15, ty = tid >> 4;
    const int rBase = blockIdx.y * 64, cBase = blockIdx.x * 64;

    float acc[4][4];
#pragma unroll
    for (int i = 0; i < 4; i++)
#pragma unroll
        for (int j = 0; j < 4; j++) acc[i][j] = 0.f;

    for (int kt = 0; kt < 512; kt += 16) {
        const int row = tid >> 2, q = (tid & 3) * 4;
        float4 va = *(const float4*)&A[(size_t)(rBase + row) * lda + kt + q];
        As[q + 0][row] = va.x; As[q + 1][row] = va.y;
        As[q + 2][row] = va.z; As[q + 3][row] = va.w;
        float4 vb = *(const float4*)&B[(size_t)(cBase + row) * ldb + kt + q];
        Bs[q + 0][row] = vb.x; Bs[q + 1][row] = vb.y;
        Bs[q + 2][row] = vb.z; Bs[q + 3][row] = vb.w;
        __syncthreads();
#pragma unroll
        for (int k = 0; k < 16; k++) {
            float a[4], bb[4];
            *(float4*)&a[0]  = *(const float4*)&As[k][ty * 4];
            *(float4*)&bb[0] = *(const float4*)&Bs[k][tx * 4];
#pragma unroll
            for (int i = 0; i < 4; i++)
#pragma unroll
                for (int j = 0; j < 4; j++) acc[i][j] += a[i] * bb[j];
        }
        __syncthreads();
    }
#pragma unroll
    for (int i = 0; i < 4; i++) {
        const int row = rBase + ty * 4 + i;
        const int col = cBase + tx * 4;
        split_store(Ch, Cm, (size_t)row * 512 + col, acc[i][0], acc[i][1]);
        split_store(Ch, Cm, (size_t)row * 512 + col + 2, acc[i][2], acc[i][3]);
    }
}

// ---------------- prep kernels ----------------------------------------------
__global__ void transpose_w(const float* __restrict__ W) {
    __shared__ float t[32][33];
    int o0 = blockIdx.x * 32, c0 = blockIdx.y * 32;
    int tx = threadIdx.x, ty = threadIdx.y;
#pragma unroll
    for (int j = 0; j < 32; j += 8)
        t[ty + j][tx] = W[(size_t)(o0 + ty + j) * 512 + c0 + tx];
    __syncthreads();
#pragma unroll
    for (int j = 0; j < 32; j += 8)
        g_WT[(size_t)(c0 + ty + j) * 1536 + o0 + tx] = t[tx][ty + j];
}

__global__ void prep_rhw(const float* __restrict__ rel_h, const float* __restrict__ rel_w) {
    int idx = blockIdx.x * blockDim.x + threadIdx.x;
    if (idx >= 64 * 512) return;
    int r = idx >> 9, c = idx & 511;
    g_rhw[idx] = (r < 32) ? rel_h[c * 32 + r] : rel_w[c * 32 + (r - 32)];
}

__global__ void prep_w16(const float* __restrict__ W) {
    int idx = blockIdx.x * blockDim.x + threadIdx.x;
    if (idx >= 512 * 512) return;
    int cv = idx >> 9, c = idx & 511;
    g_W16h[idx] = __float2half_rn(W[(size_t)(1024 + cv) * 512 + c]);
}

// transpose + split: tile 32n x 64c, vectorized paired stores
__global__ void transpose_x(const float* __restrict__ x) {
    __shared__ float t[64][33];
    int b = blockIdx.z;
    int n0 = blockIdx.x * 32, c0 = blockIdx.y * 64;
    const float* src = x + (size_t)b * CDIM * NTOK;
    size_t dbase = (size_t)b * NTOK * CDIM;
    int tx = threadIdx.x, ty = threadIdx.y;
#pragma unroll
    for (int j = 0; j < 8; j++)
        t[ty + j * 8][tx] = src[(size_t)(c0 + ty + j * 8) * NTOK + n0 + tx];
    __syncthreads();
#pragma unroll
    for (int j = 0; j < 4; j++) {
        int n = ty + j * 8;
        float v0 = t[2 * tx][n], v1 = t[2 * tx + 1][n];
        size_t off = dbase + (size_t)(n0 + n) * CDIM + c0 + 2 * tx;
        bf h0 = __float2bfloat16(v0), h1 = __float2bfloat16(v1);
        __nv_bfloat162 hh; hh.x = h0; hh.y = h1;
        __nv_bfloat162 mm;
        mm.x = __float2bfloat16(v0 - __bfloat162float(h0));
        mm.y = __float2bfloat16(v1 - __bfloat162float(h1));
        __half2 xx; xx.x = __float2half_rn(v0); xx.y = __float2half_rn(v1);
        *reinterpret_cast<__nv_bfloat162*>(g_xTh + off) = hh;
        *reinterpret_cast<__nv_bfloat162*>(g_xTm + off) = mm;
        *reinterpret_cast<__half2*>(g_xT16 + off) = xx;
    }
}

// softmax over m with fused pos-bias; writes fp16 att
__global__ __launch_bounds__(256) void softmax_bias() {
    size_t row = blockIdx.x;
    int b = (int)(row >> 10);
    int n = (int)(row & 1023);
    int h = n >> 5, w = n & 31;
    const float* p  = g_logit + row * NTOK;
    const float* ph = g_P + ((size_t)b * 64 + h) * 1024;
    const float* pw = g_P + ((size_t)b * 64 + 32 + w) * 1024;
    int tid = threadIdx.x;

    float4 v = *(const float4*)&p[tid * 4];
    float4 bh = *(const float4*)&ph[tid * 4];
    float4 bw = *(const float4*)&pw[tid * 4];
    v.x += bh.x + bw.x; v.y += bh.y + bw.y;
    v.z += bh.z + bw.z; v.w += bh.w + bw.w;

    float m = fmaxf(fmaxf(v.x, v.y), fmaxf(v.z, v.w));
#pragma unroll
    for (int o = 16; o; o >>= 1) m = fmaxf(m, __shfl_xor_sync(~0u, m, o));
    __shared__ float red[8];
    if ((tid & 31) == 0) red[tid >> 5] = m;
    __syncthreads();
    float bm = red[0];
#pragma unroll
    for (int i = 1; i < 8; i++) bm = fmaxf(bm, red[i]);
    __syncthreads();

    v.x = __expf(v.x - bm); v.y = __expf(v.y - bm);
    v.z = __expf(v.z - bm); v.w = __expf(v.w - bm);
    float s = v.x + v.y + v.z + v.w;
#pragma unroll
    for (int o = 16; o; o >>= 1) s += __shfl_xor_sync(~0u, s, o);
    if ((tid & 31) == 0) red[tid >> 5] = s;
    __syncthreads();
    float bs = 0.f;
#pragma unroll
    for (int i = 0; i < 8; i++) bs += red[i];
    float inv = 1.0f / bs;

    __half2 a0; a0.x = __float2half_rn(v.x * inv); a0.y = __float2half_rn(v.y * inv);
    __half2 a1; a1.x = __float2half_rn(v.z * inv); a1.y = __float2half_rn(v.w * inv);
    size_t off = row * NTOK + tid * 4;
    *reinterpret_cast<__half2*>(g_att16 + off) = a0;
    *reinterpret_cast<__half2*>(g_att16 + off + 2) = a1;
}

// ---------------------------------------------------------------------------
extern "C" void kernel_launch(void* const* d_in, const int* in_sizes, int n_in,
                              void* d_out, int out_size) {
    const float* x     = (const float*)d_in[0];
    const float* Wmat  = (const float*)d_in[1];
    const float* rel_h = (const float*)d_in[2];
    const float* rel_w = (const float*)d_in[3];
    float* out = (float*)d_out;

    cudaFuncSetAttribute(gemm3<0>,  cudaFuncAttributeMaxDynamicSharedMemorySize, SMEM_MAIN);
    cudaFuncSetAttribute(gemm3<1>,  cudaFuncAttributeMaxDynamicSharedMemorySize, SMEM_MAIN);
    cudaFuncSetAttribute(p_gemm,    cudaFuncAttributeMaxDynamicSharedMemorySize, SMEM_P);
    cudaFuncSetAttribute(h1_gemm<0>, cudaFuncAttributeMaxDynamicSharedMemorySize, SMEM_U);
    cudaFuncSetAttribute(h1_gemm<1>, cudaFuncAttributeMaxDynamicSharedMemorySize, SMEM_U);

    // launch order chosen so launch #4 (profiled) is gemm3<0>
    transpose_w<<<dim3(48, 16), dim3(32, 8)>>>(Wmat);                 // 1
    transpose_x<<<dim3(32, 8, 64), dim3(32, 8)>>>(x);                 // 2
    sgemm_split<0><<<dim3(8, 8), 256>>>();                            // 3: M = Wq^T Wk
    gemm3<0><<<dim3(4, 8, 64), 128, SMEM_MAIN>>>();                   // 4: T^T = xT . M
    prep_rhw<<<(64 * 512 + 255) / 256, 256>>>(rel_h, rel_w);          // 5
    sgemm_split<1><<<dim3(8, 1), 256>>>();                            // 6: G = RHW * Wq
    prep_w16<<<(512 * 512 + 255) / 256, 256>>>(Wmat);                 // 7
    h1_gemm<0><<<dim3(8, 4, 64), 128, SMEM_U>>>(nullptr);             // 8: v fp16
    gemm3<1><<<dim3(8, 8, 64), 128, SMEM_MAIN>>>();                   // 9: logits
    p_gemm<<<dim3(8, 1, 64), 256, SMEM_P>>>();                        // 10: P = G . xT
    softmax_bias<<<BATCH * NTOK, 256>>>();                            // 11: att fp16
    h1_gemm<1><<<dim3(8, 4, 64), 128, SMEM_U>>>(out);                 // 12: out
}

// round 10
// speedup vs baseline: 5.7449x; 1.0768x over previous
#include <cuda_runtime.h>
#include <cuda_bf16.h>
#include <cuda_fp16.h>
#include <cstdint>

#define BATCH 64
#define CDIM  512
#define NTOK  1024

typedef __nv_bfloat16 bf;

// ---------------- scratch (device globals) ----------------------------------
__device__ float g_WT [(size_t)512 * 1536];            // [c][o] = W[o][c]
__device__ float g_rhw[(size_t)64 * 512];              // [r][c] fp32
__device__ bf g_Mh[(size_t)512 * 512];                 // M = Wq^T Wk
__device__ bf g_Mm[(size_t)512 * 512];
__device__ bf g_Gh[(size_t)64 * 512];                  // G = RHW * Wq
__device__ bf g_Gm[(size_t)64 * 512];
__device__ bf g_xTh[(size_t)BATCH * NTOK * CDIM];      // [b][n][c]
__device__ bf g_xTm[(size_t)BATCH * NTOK * CDIM];
__device__ __half g_xT16[(size_t)BATCH * NTOK * CDIM];
__device__ __half g_W16h[(size_t)512 * 512];           // Wv fp16  [cv][c]
__device__ bf g_Th[(size_t)BATCH * NTOK * 512];        // T^T [b][m][c1]
__device__ bf g_Tm[(size_t)BATCH * NTOK * 512];
__device__ float  g_logit[(size_t)BATCH * NTOK * NTOK];
__device__ float  g_P[(size_t)BATCH * 64 * NTOK];
__device__ __half g_v16[(size_t)BATCH * CDIM * NTOK];  // [b][c][n]
__device__ __half g_att16[(size_t)BATCH * NTOK * NTOK];

// ---------------- PTX helpers ----------------------------------------------
__device__ __forceinline__ uint32_t smem_u32(const void* p) {
    uint32_t a;
    asm("{ .reg .u64 t; cvta.to.shared.u64 t, %1; cvt.u32.u64 %0, t; }" : "=r"(a) : "l"(p));
    return a;
}
__device__ __forceinline__ void cpa16(uint32_t dst, const void* src) {
    asm volatile("cp.async.cg.shared.global [%0], [%1], 16;" :: "r"(dst), "l"(src));
}
__device__ __forceinline__ void ldsm4(uint32_t r[4], uint32_t addr) {
    asm volatile("ldmatrix.sync.aligned.m8n8.x4.shared.b16 {%0,%1,%2,%3}, [%4];"
                 : "=r"(r[0]), "=r"(r[1]), "=r"(r[2]), "=r"(r[3]) : "r"(addr));
}
__device__ __forceinline__ void mma16816(float c[4], const uint32_t a[4], const uint32_t b[2]) {
    asm volatile("mma.sync.aligned.m16n8k16.row.col.f32.bf16.bf16.f32 "
                 "{%0,%1,%2,%3}, {%4,%5,%6,%7}, {%8,%9}, {%0,%1,%2,%3};"
                 : "+f"(c[0]), "+f"(c[1]), "+f"(c[2]), "+f"(c[3])
                 : "r"(a[0]), "r"(a[1]), "r"(a[2]), "r"(a[3]), "r"(b[0]), "r"(b[1]));
}
__device__ __forceinline__ void mma16816h(float c[4], const uint32_t a[4], const uint32_t b[2]) {
    asm volatile("mma.sync.aligned.m16n8k16.row.col.f32.f16.f16.f32 "
                 "{%0,%1,%2,%3}, {%4,%5,%6,%7}, {%8,%9}, {%0,%1,%2,%3};"
                 : "+f"(c[0]), "+f"(c[1]), "+f"(c[2]), "+f"(c[3])
                 : "r"(a[0]), "r"(a[1]), "r"(a[2]), "r"(a[3]), "r"(b[0]), "r"(b[1]));
}
__device__ __forceinline__ uint32_t sw_off(int row, int chunk) {
    return (uint32_t)(row * 64 + ((chunk ^ ((row >> 1) & 3)) << 4));
}
__device__ __forceinline__ void split_store(bf* __restrict__ ph, bf* __restrict__ pm,
                                            size_t off, float v0, float v1) {
    bf h0 = __float2bfloat16(v0), h1 = __float2bfloat16(v1);
    bf m0 = __float2bfloat16(v0 - __bfloat162float(h0));
    bf m1 = __float2bfloat16(v1 - __bfloat162float(h1));
    __nv_bfloat162 hh; hh.x = h0; hh.y = h1;
    __nv_bfloat162 mm; mm.x = m0; mm.y = m1;
    *reinterpret_cast<__nv_bfloat162*>(ph + off) = hh;
    *reinterpret_cast<__nv_bfloat162*>(pm + off) = mm;
}

// ================= 3-term bf16 GEMM, 128x128 tile, 4 warps (64x64/warp) =====
#define OFF_AH 0
#define OFF_AM 8192
#define OFF_BH 16384
#define OFF_BM 24576
#define STAGE_BYTES 32768
#define NSTAGE 3
#define SMEM_MAIN (NSTAGE * STAGE_BYTES)

template <int MODE>
__global__ __launch_bounds__(128, 2) void gemm3() {
    extern __shared__ __align__(128) char smem[];
    const uint32_t sbase = smem_u32(smem);
    const int tid = threadIdx.x;
    const int wid = tid >> 5, lane = tid & 31;
    const int b = blockIdx.z;
    const int nBase = blockIdx.x * 128;
    const int mBase = blockIdx.y * 128;
    const int wm = (wid >> 1) * 64, wn = (wid & 1) * 64;

    constexpr int NIT = 16;
    const size_t bXT = (size_t)b << 19;
    const size_t bQK = (size_t)b << 20;

    float acc[4][8][4];
#pragma unroll
    for (int i = 0; i < 4; i++)
#pragma unroll
        for (int j = 0; j < 8; j++)
#pragma unroll
            for (int k = 0; k < 4; k++) acc[i][j][k] = 0.f;

    auto issue_stage = [&](int stage, int kt) {
        const bf *pah, *pam, *pbh, *pbm;
        pah = g_xTh + bXT + (size_t)mBase * 512 + kt;
        pam = g_xTm + bXT + (size_t)mBase * 512 + kt;
        if (MODE == 0) {
            pbh = g_Mh + (size_t)nBase * 512 + kt;
            pbm = g_Mm + (size_t)nBase * 512 + kt;
        } else {
            pbh = g_Th + bXT + (size_t)nBase * 512 + kt;
            pbm = g_Tm + bXT + (size_t)nBase * 512 + kt;
        }
        const uint32_t sb = sbase + stage * STAGE_BYTES;
#pragma unroll
        for (int j = 0; j < 4; j++) {
            const int idx = tid + j * 128;
            const int row = idx >> 2, ch = idx & 3;
            const uint32_t d = sw_off(row, ch);
            const int s = row * 512 + ch * 8;
            cpa16(sb + OFF_AH + d, pah + s);
            cpa16(sb + OFF_AM + d, pam + s);
            cpa16(sb + OFF_BH + d, pbh + s);
            cpa16(sb + OFF_BM + d, pbm + s);
        }
        asm volatile("cp.async.commit_group;");
    };

    auto compute = [&](int stage) {
        const uint32_t base = sbase + stage * STAGE_BYTES;
        const int sel = lane >> 3;
#pragma unroll
        for (int k8 = 0; k8 < 2; k8++) {
            uint32_t bhf[8][2], bmf[8][2];
#pragma unroll
            for (int pr = 0; pr < 4; pr++) {
                const int nt = 2 * pr + (sel >> 1);
                const int kb = sel & 1;
                const uint32_t ra = base + OFF_BH + sw_off(wn + nt * 8 + (lane & 7), k8 * 2 + kb);
                uint32_t r[4];
                ldsm4(r, ra);
                bhf[2 * pr][0] = r[0]; bhf[2 * pr][1] = r[1];
                bhf[2 * pr + 1][0] = r[2]; bhf[2 * pr + 1][1] = r[3];
                ldsm4(r, ra + (OFF_BM - OFF_BH));
                bmf[2 * pr][0] = r[0]; bmf[2 * pr][1] = r[1];
                bmf[2 * pr + 1][0] = r[2]; bmf[2 * pr + 1][1] = r[3];
            }
#pragma unroll
            for (int mt = 0; mt < 4; mt++) {
                const uint32_t aa = base + OFF_AH +
                    sw_off(wm + mt * 16 + (sel & 1) * 8 + (lane & 7), k8 * 2 + (sel >> 1));
                uint32_t ah[4], am[4];
                ldsm4(ah, aa);
                ldsm4(am, aa + (OFF_AM - OFF_AH));
#pragma unroll
                for (int nt = 0; nt < 8; nt++) mma16816(acc[mt][nt], ah, bhf[nt]);
#pragma unroll
                for (int nt = 0; nt < 8; nt++) mma16816(acc[mt][nt], ah, bmf[nt]);
#pragma unroll
                for (int nt = 0; nt < 8; nt++) mma16816(acc[mt][nt], am, bhf[nt]);
            }
        }
    };

    issue_stage(0, 0);
    issue_stage(1, 32);
    for (int it = 0; it < NIT; it++) {
        if (it + 2 < NIT) asm volatile("cp.async.wait_group 1;");
        else              asm volatile("cp.async.wait_group 0;");
        __syncthreads();
        if (it + 2 < NIT) issue_stage((it + 2) % NSTAGE, (it + 2) * 32);
        compute(it % NSTAGE);
    }

    const int lr = lane >> 2, lc = 2 * (lane & 3);
#pragma unroll
    for (int mt = 0; mt < 4; mt++) {
#pragma unroll
        for (int nt = 0; nt < 8; nt++) {
            const int r0 = mBase + wm + mt * 16 + lr;
            const int c0 = nBase + wn + nt * 8 + lc;
            if (MODE == 0) {
                split_store(g_Th + bXT, g_Tm + bXT, (size_t)r0 * 512 + c0, acc[mt][nt][0], acc[mt][nt][1]);
                split_store(g_Th + bXT, g_Tm + bXT, (size_t)(r0 + 8) * 512 + c0, acc[mt][nt][2], acc[mt][nt][3]);
            } else {
                float2 v0; v0.x = acc[mt][nt][0]; v0.y = acc[mt][nt][1];
                float2 v1; v1.x = acc[mt][nt][2]; v1.y = acc[mt][nt][3];
                *reinterpret_cast<float2*>(g_logit + bQK + (size_t)r0 * 1024 + c0) = v0;
                *reinterpret_cast<float2*>(g_logit + bQK + (size_t)(r0 + 8) * 1024 + c0) = v1;
            }
        }
    }
}

// ================= P GEMM: P[b][r][m] = G[r][:] . xT[m][:]  (64x128 tile) ===
#define P_AH 0
#define P_AM 4096
#define P_BH 8192
#define P_BM 16384
#define P_STAGE 24576
#define SMEM_P (NSTAGE * P_STAGE)

__global__ __launch_bounds__(256, 2) void p_gemm() {
    extern __shared__ __align__(128) char smem[];
    const uint32_t sbase = smem_u32(smem);
    const int tid = threadIdx.x;
    const int wid = tid >> 5, lane = tid & 31;
    const int b = blockIdx.z;
    const int nBase = blockIdx.x * 128;
    const int wm = (wid >> 2) * 32, wn = (wid & 3) * 32;
    const size_t bXT = (size_t)b << 19;

    float acc[2][4][4];
#pragma unroll
    for (int i = 0; i < 2; i++)
#pragma unroll
        for (int j = 0; j < 4; j++)
#pragma unroll
            for (int k = 0; k < 4; k++) acc[i][j][k] = 0.f;

    auto issue_stage = [&](int stage, int kt) {
        const uint32_t sb = sbase + stage * P_STAGE;
        {
            const int row = tid >> 2, ch = tid & 3;
            const uint32_t d = sw_off(row, ch);
            const int s = row * 512 + kt + ch * 8;
            cpa16(sb + P_AH + d, g_Gh + s);
            cpa16(sb + P_AM + d, g_Gm + s);
        }
#pragma unroll
        for (int j = 0; j < 2; j++) {
            const int idx = tid + j * 256;
            const int row = idx >> 2, ch = idx & 3;
            const uint32_t d = sw_off(row, ch);
            const size_t s = bXT + (size_t)(nBase + row) * 512 + kt + ch * 8;
            cpa16(sb + P_BH + d, g_xTh + s);
            cpa16(sb + P_BM + d, g_xTm + s);
        }
        asm volatile("cp.async.commit_group;");
    };

    auto compute = [&](int stage) {
        const uint32_t base = sbase + stage * P_STAGE;
        const int sel = lane >> 3;
#pragma unroll
        for (int k8 = 0; k8 < 2; k8++) {
            uint32_t bhf[4][2], bmf[4][2];
#pragma unroll
            for (int pr = 0; pr < 2; pr++) {
                const int nt = 2 * pr + (sel >> 1);
                const int kb = sel & 1;
                const uint32_t ra = base + P_BH + sw_off(wn + nt * 8 + (lane & 7), k8 * 2 + kb);
                uint32_t r[4];
                ldsm4(r, ra);
                bhf[2 * pr][0] = r[0]; bhf[2 * pr][1] = r[1];
                bhf[2 * pr + 1][0] = r[2]; bhf[2 * pr + 1][1] = r[3];
                ldsm4(r, ra + (P_BM - P_BH));
                bmf[2 * pr][0] = r[0]; bmf[2 * pr][1] = r[1];
                bmf[2 * pr + 1][0] = r[2]; bmf[2 * pr + 1][1] = r[3];
            }
#pragma unroll
            for (int mt = 0; mt < 2; mt++) {
                const uint32_t aa = base + P_AH +
                    sw_off(wm + mt * 16 + (sel & 1) * 8 + (lane & 7), k8 * 2 + (sel >> 1));
                uint32_t ah[4], am[4];
                ldsm4(ah, aa);
                ldsm4(am, aa + (P_AM - P_AH));
#pragma unroll
                for (int nt = 0; nt < 4; nt++) mma16816(acc[mt][nt], ah, bhf[nt]);
#pragma unroll
                for (int nt = 0; nt < 4; nt++) mma16816(acc[mt][nt], ah, bmf[nt]);
#pragma unroll
                for (int nt = 0; nt < 4; nt++) mma16816(acc[mt][nt], am, bhf[nt]);
            }
        }
    };

    issue_stage(0, 0);
    issue_stage(1, 32);
    for (int it = 0; it < 16; it++) {
        if (it + 2 < 16) asm volatile("cp.async.wait_group 1;");
        else             asm volatile("cp.async.wait_group 0;");
        __syncthreads();
        if (it + 2 < 16) issue_stage((it + 2) % NSTAGE, (it + 2) * 32);
        compute(it % NSTAGE);
    }

    const int lr = lane >> 2, lc = 2 * (lane & 3);
    float* P = g_P + (size_t)b * 64 * 1024;
#pragma unroll
    for (int mt = 0; mt < 2; mt++) {
#pragma unroll
        for (int nt = 0; nt < 4; nt++) {
            const int r0 = wm + mt * 16 + lr;
            const int c0 = nBase + wn + nt * 8 + lc;
            float2 v0; v0.x = acc[mt][nt][0]; v0.y = acc[mt][nt][1];
            float2 v1; v1.x = acc[mt][nt][2]; v1.y = acc[mt][nt][3];
            *reinterpret_cast<float2*>(P + (size_t)r0 * 1024 + c0) = v0;
            *reinterpret_cast<float2*>(P + (size_t)(r0 + 8) * 1024 + c0) = v1;
        }
    }
}

// ======= fp16 single-term GEMM: 128x128 tile, 4 warps =======================
#define U_A  0
#define U_B  8192
#define U_STAGE 16384
#define SMEM_U (NSTAGE * U_STAGE)

template <int MODE>
__global__ __launch_bounds__(128, 2) void h1_gemm(float* __restrict__ outp) {
    extern __shared__ __align__(128) char smem[];
    const uint32_t sbase = smem_u32(smem);
    const int tid = threadIdx.x;
    const int wid = tid >> 5, lane = tid & 31;
    const int b = blockIdx.z;
    const int nBase = blockIdx.x * 128;
    const int mBase = blockIdx.y * 128;
    const int wm = (wid >> 1) * 64, wn = (wid & 1) * 64;
    const size_t bQK = (size_t)b << 20;
    const size_t bXT = (size_t)b << 19;

    constexpr int NIT = (MODE == 0) ? 16 : 32;
    constexpr int LD  = (MODE == 0) ? 512 : 1024;

    float acc[4][8][4];
#pragma unroll
    for (int i = 0; i < 4; i++)
#pragma unroll
        for (int j = 0; j < 8; j++)
#pragma unroll
            for (int k = 0; k < 4; k++) acc[i][j][k] = 0.f;

    auto issue_stage = [&](int stage, int kt) {
        const __half *pa, *pb;
        if (MODE == 0) {
            pa = g_W16h + (size_t)mBase * 512 + kt;
            pb = g_xT16 + bXT + (size_t)nBase * 512 + kt;
        } else {
            pa = g_v16 + bXT + (size_t)mBase * 1024 + kt;
            pb = g_att16 + bQK + (size_t)nBase * 1024 + kt;
        }
        const uint32_t sb = sbase + stage * U_STAGE;
#pragma unroll
        for (int j = 0; j < 4; j++) {
            const int idx = tid + j * 128;
            const int row = idx >> 2, ch = idx & 3;
            const uint32_t d = sw_off(row, ch);
            const int s = row * LD + ch * 8;
            cpa16(sb + U_A + d, pa + s);
            cpa16(sb + U_B + d, pb + s);
        }
        asm volatile("cp.async.commit_group;");
    };

    auto compute = [&](int stage) {
        const uint32_t base = sbase + stage * U_STAGE;
        const int sel = lane >> 3;
#pragma unroll
        for (int k8 = 0; k8 < 2; k8++) {
            uint32_t bff[8][2];
#pragma unroll
            for (int pr = 0; pr < 4; pr++) {
                const int nt = 2 * pr + (sel >> 1);
                const int kb = sel & 1;
                uint32_t r[4];
                ldsm4(r, base + U_B + sw_off(wn + nt * 8 + (lane & 7), k8 * 2 + kb));
                bff[2 * pr][0] = r[0]; bff[2 * pr][1] = r[1];
                bff[2 * pr + 1][0] = r[2]; bff[2 * pr + 1][1] = r[3];
            }
#pragma unroll
            for (int mt = 0; mt < 4; mt++) {
                const uint32_t aa = base + U_A +
                    sw_off(wm + mt * 16 + (sel & 1) * 8 + (lane & 7), k8 * 2 + (sel >> 1));
                uint32_t ah[4];
                ldsm4(ah, aa);
#pragma unroll
                for (int nt = 0; nt < 8; nt++) mma16816h(acc[mt][nt], ah, bff[nt]);
            }
        }
    };

    issue_stage(0, 0);
    issue_stage(1, 32);
    for (int it = 0; it < NIT; it++) {
        if (it + 2 < NIT) asm volatile("cp.async.wait_group 1;");
        else              asm volatile("cp.async.wait_group 0;");
        __syncthreads();
        if (it + 2 < NIT) issue_stage((it + 2) % NSTAGE, (it + 2) * 32);
        compute(it % NSTAGE);
    }

    const int lr = lane >> 2, lc = 2 * (lane & 3);
#pragma unroll
    for (int mt = 0; mt < 4; mt++) {
#pragma unroll
        for (int nt = 0; nt < 8; nt++) {
            const int r0 = mBase + wm + mt * 16 + lr;
            const int c0 = nBase + wn + nt * 8 + lc;
            if (MODE == 0) {
                __half* ov = g_v16 + bXT;
                __half2 h0; h0.x = __float2half_rn(acc[mt][nt][0]); h0.y = __float2half_rn(acc[mt][nt][1]);
                __half2 h1; h1.x = __float2half_rn(acc[mt][nt][2]); h1.y = __float2half_rn(acc[mt][nt][3]);
                *reinterpret_cast<__half2*>(ov + (size_t)r0 * 1024 + c0) = h0;
                *reinterpret_cast<__half2*>(ov + (size_t)(r0 + 8) * 1024 + c0) = h1;
            } else {
                float* of = outp + bXT;
                float2 v0; v0.x = acc[mt][nt][0]; v0.y = acc[mt][nt][1];
                float2 v1; v1.x = acc[mt][nt][2]; v1.y = acc[mt][nt][3];
                *reinterpret_cast<float2*>(of + (size_t)r0 * 1024 + c0) = v0;
                *reinterpret_cast<float2*>(of + (size_t)(r0 + 8) * 1024 + c0) = v1;
            }
        }
    }
}

// ---------------- small fp32 GEMM for M and G precompute --------------------
template <int IS_G>
__global__ __launch_bounds__(256) void sgemm_split() {
    const float* A = IS_G ? g_rhw : g_WT;
    const int lda = IS_G ? 512 : 1536;
    const float* B = IS_G ? g_WT : (g_WT + 512);
    const int ldb = 1536;
    bf* Ch = IS_G ? g_Gh : g_Mh;
    bf* Cm = IS_G ? g_Gm : g_Mm;

    __shared__ float As[16][72];
    __shared__ float Bs[16][72];
    const int tid = threadIdx.x;
    const int tx = tid & 15, ty = tid >> 4;
    const int rBase = blockIdx.y * 64, cBase = blockIdx.x * 64;

    float acc[4][4];
#pragma unroll
    for (int i = 0; i < 4; i++)
#pragma unroll
        for (int j = 0; j < 4; j++) acc[i][j] = 0.f;

    for (int kt = 0; kt < 512; kt += 16) {
        const int row = tid >> 2, q = (tid & 3) * 4;
        float4 va = *(const float4*)&A[(size_t)(rBase + row) * lda + kt + q];
        As[q + 0][row] = va.x; As[q + 1][row] = va.y;
        As[q + 2][row] = va.z; As[q + 3][row] = va.w;
        float4 vb = *(const float4*)&B[(size_t)(cBase + row) * ldb + kt + q];
        Bs[q + 0][row] = vb.x; Bs[q + 1][row] = vb.y;
        Bs[q + 2][row] = vb.z; Bs[q + 3][row] = vb.w;
        __syncthreads();
#pragma unroll
        for (int k = 0; k < 16; k++) {
            float a[4], bb[4];
            *(float4*)&a[0]  = *(const float4*)&As[k][ty * 4];
            *(float4*)&bb[0] = *(const float4*)&Bs[k][tx * 4];
#pragma unroll
            for (int i = 0; i < 4; i++)
#pragma unroll
                for (int j = 0; j < 4; j++) acc[i][j] += a[i] * bb[j];
        }
        __syncthreads();
    }
#pragma unroll
    for (int i = 0; i < 4; i++) {
        const int row = rBase + ty * 4 + i;
        const int col = cBase + tx * 4;
        split_store(Ch, Cm, (size_t)row * 512 + col, acc[i][0], acc[i][1]);
        split_store(Ch, Cm, (size_t)row * 512 + col + 2, acc[i][2], acc[i][3]);
    }
}

// ---------------- prep kernels ----------------------------------------------
__global__ void transpose_w(const float* __restrict__ W) {
    __shared__ float t[32][33];
    int o0 = blockIdx.x * 32, c0 = blockIdx.y * 32;
    int tx = threadIdx.x, ty = threadIdx.y;
#pragma unroll
    for (int j = 0; j < 32; j += 8)
        t[ty + j][tx] = W[(size_t)(o0 + ty + j) * 512 + c0 + tx];
    __syncthreads();
#pragma unroll
    for (int j = 0; j < 32; j += 8)
        g_WT[(size_t)(c0 + ty + j) * 1536 + o0 + tx] = t[tx][ty + j];
}

__global__ void prep_rhw(const float* __restrict__ rel_h, const float* __restrict__ rel_w) {
    int idx = blockIdx.x * blockDim.x + threadIdx.x;
    if (idx >= 64 * 512) return;
    int r = idx >> 9, c = idx & 511;
    g_rhw[idx] = (r < 32) ? rel_h[c * 32 + r] : rel_w[c * 32 + (r - 32)];
}

__global__ void prep_w16(const float* __restrict__ W) {
    int idx = blockIdx.x * blockDim.x + threadIdx.x;
    if (idx >= 512 * 512) return;
    int cv = idx >> 9, c = idx & 511;
    g_W16h[idx] = __float2half_rn(W[(size_t)(1024 + cv) * 512 + c]);
}

// transpose + split: tile 32n x 64c, vectorized paired stores
__global__ void transpose_x(const float* __restrict__ x) {
    __shared__ float t[64][33];
    int b = blockIdx.z;
    int n0 = blockIdx.x * 32, c0 = blockIdx.y * 64;
    const float* src = x + (size_t)b * CDIM * NTOK;
    size_t dbase = (size_t)b * NTOK * CDIM;
    int tx = threadIdx.x, ty = threadIdx.y;
#pragma unroll
    for (int j = 0; j < 8; j++)
        t[ty + j * 8][tx] = src[(size_t)(c0 + ty + j * 8) * NTOK + n0 + tx];
    __syncthreads();
#pragma unroll
    for (int j = 0; j < 4; j++) {
        int n = ty + j * 8;
        float v0 = t[2 * tx][n], v1 = t[2 * tx + 1][n];
        size_t off = dbase + (size_t)(n0 + n) * CDIM + c0 + 2 * tx;
        bf h0 = __float2bfloat16(v0), h1 = __float2bfloat16(v1);
        __nv_bfloat162 hh; hh.x = h0; hh.y = h1;
        __nv_bfloat162 mm;
        mm.x = __float2bfloat16(v0 - __bfloat162float(h0));
        mm.y = __float2bfloat16(v1 - __bfloat162float(h1));
        __half2 xx; xx.x = __float2half_rn(v0); xx.y = __float2half_rn(v1);
        *reinterpret_cast<__nv_bfloat162*>(g_xTh + off) = hh;
        *reinterpret_cast<__nv_bfloat162*>(g_xTm + off) = mm;
        *reinterpret_cast<__half2*>(g_xT16 + off) = xx;
    }
}

// softmax over m with fused pos-bias; writes fp16 att
__global__ __launch_bounds__(256) void softmax_bias() {
    size_t row = blockIdx.x;
    int b = (int)(row >> 10);
    int n = (int)(row & 1023);
    int h = n >> 5, w = n & 31;
    const float* p  = g_logit + row * NTOK;
    const float* ph = g_P + ((size_t)b * 64 + h) * 1024;
    const float* pw = g_P + ((size_t)b * 64 + 32 + w) * 1024;
    int tid = threadIdx.x;

    float4 v = *(const float4*)&p[tid * 4];
    float4 bh = *(const float4*)&ph[tid * 4];
    float4 bw = *(const float4*)&pw[tid * 4];
    v.x += bh.x + bw.x; v.y += bh.y + bw.y;
    v.z += bh.z + bw.z; v.w += bh.w + bw.w;

    float m = fmaxf(fmaxf(v.x, v.y), fmaxf(v.z, v.w));
#pragma unroll
    for (int o = 16; o; o >>= 1) m = fmaxf(m, __shfl_xor_sync(~0u, m, o));
    __shared__ float red[8];
    if ((tid & 31) == 0) red[tid >> 5] = m;
    __syncthreads();
    float bm = red[0];
#pragma unroll
    for (int i = 1; i < 8; i++) bm = fmaxf(bm, red[i]);
    __syncthreads();

    v.x = __expf(v.x - bm); v.y = __expf(v.y - bm);
    v.z = __expf(v.z - bm); v.w = __expf(v.w - bm);
    float s = v.x + v.y + v.z + v.w;
#pragma unroll
    for (int o = 16; o; o >>= 1) s += __shfl_xor_sync(~0u, s, o);
    if ((tid & 31) == 0) red[tid >> 5] = s;
    __syncthreads();
    float bs = 0.f;
#pragma unroll
    for (int i = 0; i < 8; i++) bs += red[i];
    float inv = 1.0f / bs;

    __half2 a0; a0.x = __float2half_rn(v.x * inv); a0.y = __float2half_rn(v.y * inv);
    __half2 a1; a1.x = __float2half_rn(v.z * inv); a1.y = __float2half_rn(v.w * inv);
    size_t off = row * NTOK + tid * 4;
    *reinterpret_cast<__half2*>(g_att16 + off) = a0;
    *reinterpret_cast<__half2*>(g_att16 + off + 2) = a1;
}

// ---------------------------------------------------------------------------
extern "C" void kernel_launch(void* const* d_in, const int* in_sizes, int n_in,
                              void* d_out, int out_size) {
    const float* x     = (const float*)d_in[0];
    const float* Wmat  = (const float*)d_in[1];
    const float* rel_h = (const float*)d_in[2];
    const float* rel_w = (const float*)d_in[3];
    float* out = (float*)d_out;

    static cudaStream_t s1 = nullptr, s2 = nullptr;
    static cudaEvent_t eF1, eF2, eX, eM, eP, eV;
    if (s1 == nullptr) {
        cudaStreamCreateWithFlags(&s1, cudaStreamNonBlocking);
        cudaStreamCreateWithFlags(&s2, cudaStreamNonBlocking);
        cudaEventCreateWithFlags(&eF1, cudaEventDisableTiming);
        cudaEventCreateWithFlags(&eF2, cudaEventDisableTiming);
        cudaEventCreateWithFlags(&eX,  cudaEventDisableTiming);
        cudaEventCreateWithFlags(&eM,  cudaEventDisableTiming);
        cudaEventCreateWithFlags(&eP,  cudaEventDisableTiming);
        cudaEventCreateWithFlags(&eV,  cudaEventDisableTiming);
        cudaFuncSetAttribute(gemm3<0>,   cudaFuncAttributeMaxDynamicSharedMemorySize, SMEM_MAIN);
        cudaFuncSetAttribute(gemm3<1>,   cudaFuncAttributeMaxDynamicSharedMemorySize, SMEM_MAIN);
        cudaFuncSetAttribute(p_gemm,     cudaFuncAttributeMaxDynamicSharedMemorySize, SMEM_P);
        cudaFuncSetAttribute(h1_gemm<0>, cudaFuncAttributeMaxDynamicSharedMemorySize, SMEM_U);
        cudaFuncSetAttribute(h1_gemm<1>, cudaFuncAttributeMaxDynamicSharedMemorySize, SMEM_U);
    }

    // fork side streams from the capturing (default) stream
    cudaEventRecord(eF1, 0);
    cudaStreamWaitEvent(s1, eF1, 0);
    cudaEventRecord(eF2, 0);
    cudaStreamWaitEvent(s2, eF2, 0);

    // main: x transpose/split
    transpose_x<<<dim3(32, 8, 64), dim3(32, 8)>>>(x);
    cudaEventRecord(eX, 0);

    // s1: W-side preps -> M, then G, then P (needs xT)
    transpose_w<<<dim3(48, 16), dim3(32, 8), 0, s1>>>(Wmat);
    sgemm_split<0><<<dim3(8, 8), 256, 0, s1>>>();                 // M = Wq^T Wk
    cudaEventRecord(eM, s1);
    prep_rhw<<<(64 * 512 + 255) / 256, 256, 0, s1>>>(rel_h, rel_w);
    sgemm_split<1><<<dim3(8, 1), 256, 0, s1>>>();                 // G = RHW * Wq
    cudaStreamWaitEvent(s1, eX, 0);
    p_gemm<<<dim3(8, 1, 64), 256, SMEM_P, s1>>>();                // P = G . xT
    cudaEventRecord(eP, s1);

    // s2: Wv prep -> v (needs xT16)
    prep_w16<<<(512 * 512 + 255) / 256, 256, 0, s2>>>(Wmat);
    cudaStreamWaitEvent(s2, eX, 0);
    h1_gemm<0><<<dim3(8, 4, 64), 128, SMEM_U, s2>>>(nullptr);     // v fp16
    cudaEventRecord(eV, s2);

    // main: T -> logits (overlapped with s1/s2 work)
    cudaStreamWaitEvent(0, eM, 0);
    gemm3<0><<<dim3(4, 8, 64), 128, SMEM_MAIN>>>();               // T^T = xT . M
    gemm3<1><<<dim3(8, 8, 64), 128, SMEM_MAIN>>>();               // logits = xT . T^T

    // join P, softmax, join v, out
    cudaStreamWaitEvent(0, eP, 0);
    softmax_bias<<<BATCH * NTOK, 256>>>();                        // att fp16
    cudaStreamWaitEvent(0, eV, 0);
    h1_gemm<1><<<dim3(8, 4, 64), 128, SMEM_U>>>(out);             // out = v . att
}